// round 1
// baseline (speedup 1.0000x reference)
#include <cuda_runtime.h>
#include <math.h>

// Problem constants (fixed by setup_inputs)
#define NTOK 8192      // B*S = 4*2048
#define HDIM 1024
#define IDIM 2048
#define EEXP 8
#define TOPK 2

// GEMM tiling
#define TM 128
#define TN 64
#define TK 16
#define TMP 132        // padded A-tile row length (bank-conflict relief)

// ---------------- device scratch (static; no allocations) ----------------
__device__ int   g_cnt[EEXP];                    // tokens assigned per expert
__device__ int   g_pairs[EEXP * NTOK];           // per-expert list of pair ids (t*2+k)
__device__ float g_tokw[NTOK * 2];               // renormalized combine weight per (t,k)
__device__ int   g_toke[NTOK * 2];               // expert id per (t,k)
__device__ float g_selw[NTOK * 2];               // raw softmax weight per (t,k) (pre-renorm)
__device__ float g_hbuf[NTOK * 2 * IDIM];        // silu(gate)*up   [pair, I]  (134 MB)
__device__ float g_ybuf[NTOK * 2 * HDIM];        // expert outputs  [pair, H]  (67 MB)

// ---------------- reset ----------------
__global__ void reset_kernel() {
    if (threadIdx.x < EEXP) g_cnt[threadIdx.x] = 0;
}

// ---------------- router: one warp per token ----------------
__global__ void router_kernel(const float* __restrict__ x,
                              const float* __restrict__ gw) {
    int t = blockIdx.x * (blockDim.x >> 5) + (threadIdx.x >> 5);
    int lane = threadIdx.x & 31;
    if (t >= NTOK) return;
    const float* xr = x + (size_t)t * HDIM;
    float acc[EEXP];
#pragma unroll
    for (int e = 0; e < EEXP; e++) acc[e] = 0.f;
    for (int h = lane; h < HDIM; h += 32) {
        float xv = xr[h];
        const float* g = gw + h * EEXP;
#pragma unroll
        for (int e = 0; e < EEXP; e++) acc[e] = fmaf(xv, g[e], acc[e]);
    }
#pragma unroll
    for (int off = 16; off > 0; off >>= 1) {
#pragma unroll
        for (int e = 0; e < EEXP; e++)
            acc[e] += __shfl_down_sync(0xffffffffu, acc[e], off);
    }
    if (lane == 0) {
        float mx = acc[0];
#pragma unroll
        for (int e = 1; e < EEXP; e++) mx = fmaxf(mx, acc[e]);
        float p[EEXP];
        float s = 0.f;
#pragma unroll
        for (int e = 0; e < EEXP; e++) { p[e] = expf(acc[e] - mx); s += p[e]; }
        float inv = 1.f / s;
#pragma unroll
        for (int e = 0; e < EEXP; e++) p[e] *= inv;
        // top-1 (ties -> lowest index via strict >)
        int e0 = 0;
#pragma unroll
        for (int e = 1; e < EEXP; e++) if (p[e] > p[e0]) e0 = e;
        // top-2
        int e1 = (e0 == 0) ? 1 : 0;
#pragma unroll
        for (int e = 0; e < EEXP; e++) if (e != e0 && p[e] > p[e1]) e1 = e;
        float w0 = p[e0], w1 = p[e1];
        float rs = 1.f / (w0 + w1);
        g_toke[2 * t] = e0;      g_toke[2 * t + 1] = e1;
        g_selw[2 * t] = w0;      g_selw[2 * t + 1] = w1;
        g_tokw[2 * t] = w0 * rs; g_tokw[2 * t + 1] = w1 * rs;
        int p0 = atomicAdd(&g_cnt[e0], 1);
        g_pairs[e0 * NTOK + p0] = 2 * t;
        int p1 = atomicAdd(&g_cnt[e1], 1);
        g_pairs[e1 * NTOK + p1] = 2 * t + 1;
    }
}

// ---------------- aux loss: single block, deterministic reduction ----------------
__global__ void aux_kernel(float* __restrict__ out_aux) {
    __shared__ float sload[256][EEXP];
    int tid = threadIdx.x;
    float l[EEXP];
#pragma unroll
    for (int e = 0; e < EEXP; e++) l[e] = 0.f;
    for (int a = tid; a < NTOK * 2; a += 256)
        l[g_toke[a]] += g_selw[a];
#pragma unroll
    for (int e = 0; e < EEXP; e++) sload[tid][e] = l[e];
    __syncthreads();
    for (int s = 128; s > 0; s >>= 1) {
        if (tid < s) {
#pragma unroll
            for (int e = 0; e < EEXP; e++) sload[tid][e] += sload[tid + s][e];
        }
        __syncthreads();
    }
    if (tid == 0) {
        float aux = 0.f;
#pragma unroll
        for (int e = 0; e < EEXP; e++) {
            float pe = sload[0][e] / (float)NTOK;
            float pt = (float)g_cnt[e] / (float)(NTOK * TOPK);
            aux += pe * pt;
        }
        aux *= (float)EEXP * 1e-3f;
        *out_aux = aux;
    }
}

// ---------------- gate+up GEMM, gathered rows, fused SwiGLU epilogue ----------------
__global__ __launch_bounds__(256, 2) void gateup_kernel(
    const float* __restrict__ x,
    const float* __restrict__ w_gate,
    const float* __restrict__ w_up) {
    int e = blockIdx.z;
    int M = g_cnt[e];
    int m0 = blockIdx.y * TM;
    if (m0 >= M) return;
    int n0 = blockIdx.x * TN;

    __shared__ float As[TK][TMP];
    __shared__ float Bg[TK][TN];
    __shared__ float Bu[TK][TN];
    __shared__ int   prow[TM];
    __shared__ int   toks[TM];

    int tid = threadIdx.x;
    if (tid < TM) {
        int r = m0 + tid;
        int pr = (r < M) ? g_pairs[e * NTOK + r] : g_pairs[e * NTOK];
        prow[tid] = pr;
        toks[tid] = pr >> 1;
    }
    __syncthreads();

    const float* wg = w_gate + (size_t)e * HDIM * IDIM;
    const float* wu = w_up   + (size_t)e * HDIM * IDIM;

    float accG[8][4], accU[8][4];
#pragma unroll
    for (int i = 0; i < 8; i++)
#pragma unroll
        for (int j = 0; j < 4; j++) { accG[i][j] = 0.f; accU[i][j] = 0.f; }

    int ty = tid >> 4;          // 0..15 -> 8 m-rows each
    int tx = tid & 15;          // 0..15 -> 4 n-cols each
    int ar0 = tid >> 2;         // A-load row (0..63), second row +64
    int akq = (tid & 3) * 4;    // A-load k offset
    int bk = tid >> 4;          // B-load k row (0..15)
    int bn = (tid & 15) * 4;    // B-load n offset

    for (int k0 = 0; k0 < HDIM; k0 += TK) {
        // A tile (gathered), stored transposed As[k][m]
        {
            float4 v = *(const float4*)(x + (size_t)toks[ar0] * HDIM + k0 + akq);
            As[akq + 0][ar0] = v.x; As[akq + 1][ar0] = v.y;
            As[akq + 2][ar0] = v.z; As[akq + 3][ar0] = v.w;
            int r2 = ar0 + 64;
            float4 w = *(const float4*)(x + (size_t)toks[r2] * HDIM + k0 + akq);
            As[akq + 0][r2] = w.x; As[akq + 1][r2] = w.y;
            As[akq + 2][r2] = w.z; As[akq + 3][r2] = w.w;
        }
        // B tiles
        *(float4*)&Bg[bk][bn] = *(const float4*)(wg + (size_t)(k0 + bk) * IDIM + n0 + bn);
        *(float4*)&Bu[bk][bn] = *(const float4*)(wu + (size_t)(k0 + bk) * IDIM + n0 + bn);
        __syncthreads();

#pragma unroll
        for (int k = 0; k < TK; k++) {
            float a[8], bg[4], bu[4];
            *(float4*)&a[0] = *(const float4*)&As[k][ty * 8];
            *(float4*)&a[4] = *(const float4*)&As[k][ty * 8 + 4];
            *(float4*)&bg[0] = *(const float4*)&Bg[k][tx * 4];
            *(float4*)&bu[0] = *(const float4*)&Bu[k][tx * 4];
#pragma unroll
            for (int i = 0; i < 8; i++)
#pragma unroll
                for (int j = 0; j < 4; j++) {
                    accG[i][j] = fmaf(a[i], bg[j], accG[i][j]);
                    accU[i][j] = fmaf(a[i], bu[j], accU[i][j]);
                }
        }
        __syncthreads();
    }

    // epilogue: h = silu(g) * u
#pragma unroll
    for (int i = 0; i < 8; i++) {
        int r = m0 + ty * 8 + i;
        if (r < M) {
            int p = prow[ty * 8 + i];
            float* hb = g_hbuf + (size_t)p * IDIM + n0 + tx * 4;
#pragma unroll
            for (int j = 0; j < 4; j++) {
                float g = accG[i][j];
                float s = g / (1.f + expf(-g));
                hb[j] = s * accU[i][j];
            }
        }
    }
}

// ---------------- down GEMM, gathered rows ----------------
__global__ __launch_bounds__(256, 2) void down_kernel(const float* __restrict__ w_down) {
    int e = blockIdx.z;
    int M = g_cnt[e];
    int m0 = blockIdx.y * TM;
    if (m0 >= M) return;
    int n0 = blockIdx.x * TN;

    __shared__ float As[TK][TMP];
    __shared__ float Bs[TK][TN];
    __shared__ int   prow[TM];

    int tid = threadIdx.x;
    if (tid < TM) {
        int r = m0 + tid;
        prow[tid] = (r < M) ? g_pairs[e * NTOK + r] : g_pairs[e * NTOK];
    }
    __syncthreads();

    const float* wd = w_down + (size_t)e * IDIM * HDIM;

    float acc[8][4];
#pragma unroll
    for (int i = 0; i < 8; i++)
#pragma unroll
        for (int j = 0; j < 4; j++) acc[i][j] = 0.f;

    int ty = tid >> 4;
    int tx = tid & 15;
    int ar0 = tid >> 2;
    int akq = (tid & 3) * 4;
    int bk = tid >> 4;
    int bn = (tid & 15) * 4;

    for (int k0 = 0; k0 < IDIM; k0 += TK) {
        {
            float4 v = *(const float4*)(g_hbuf + (size_t)prow[ar0] * IDIM + k0 + akq);
            As[akq + 0][ar0] = v.x; As[akq + 1][ar0] = v.y;
            As[akq + 2][ar0] = v.z; As[akq + 3][ar0] = v.w;
            int r2 = ar0 + 64;
            float4 w = *(const float4*)(g_hbuf + (size_t)prow[r2] * IDIM + k0 + akq);
            As[akq + 0][r2] = w.x; As[akq + 1][r2] = w.y;
            As[akq + 2][r2] = w.z; As[akq + 3][r2] = w.w;
        }
        *(float4*)&Bs[bk][bn] = *(const float4*)(wd + (size_t)(k0 + bk) * HDIM + n0 + bn);
        __syncthreads();

#pragma unroll
        for (int k = 0; k < TK; k++) {
            float a[8], b[4];
            *(float4*)&a[0] = *(const float4*)&As[k][ty * 8];
            *(float4*)&a[4] = *(const float4*)&As[k][ty * 8 + 4];
            *(float4*)&b[0] = *(const float4*)&Bs[k][tx * 4];
#pragma unroll
            for (int i = 0; i < 8; i++)
#pragma unroll
                for (int j = 0; j < 4; j++)
                    acc[i][j] = fmaf(a[i], b[j], acc[i][j]);
        }
        __syncthreads();
    }

#pragma unroll
    for (int i = 0; i < 8; i++) {
        int r = m0 + ty * 8 + i;
        if (r < M) {
            int p = prow[ty * 8 + i];
            float* yb = g_ybuf + (size_t)p * HDIM + n0 + tx * 4;
#pragma unroll
            for (int j = 0; j < 4; j++) yb[j] = acc[i][j];
        }
    }
}

// ---------------- combine: y[t] = w0*yb[2t] + w1*yb[2t+1] ----------------
__global__ void combine_kernel(float* __restrict__ y) {
    int idx = blockIdx.x * blockDim.x + threadIdx.x;   // over NTOK*HDIM/4
    int t = idx / (HDIM / 4);
    int h4 = (idx - t * (HDIM / 4)) * 4;
    float w0 = g_tokw[2 * t], w1 = g_tokw[2 * t + 1];
    float4 a = *(const float4*)&g_ybuf[(size_t)(2 * t) * HDIM + h4];
    float4 b = *(const float4*)&g_ybuf[(size_t)(2 * t + 1) * HDIM + h4];
    float4 r;
    r.x = w0 * a.x + w1 * b.x;
    r.y = w0 * a.y + w1 * b.y;
    r.z = w0 * a.z + w1 * b.z;
    r.w = w0 * a.w + w1 * b.w;
    *(float4*)&y[(size_t)t * HDIM + h4] = r;
}

// ---------------- launch ----------------
extern "C" void kernel_launch(void* const* d_in, const int* in_sizes, int n_in,
                              void* d_out, int out_size) {
    const float* x  = (const float*)d_in[0];
    const float* gw = (const float*)d_in[1];
    const float* wg = (const float*)d_in[2];
    const float* wu = (const float*)d_in[3];
    const float* wd = (const float*)d_in[4];
    float* y = (float*)d_out;

    reset_kernel<<<1, 32>>>();
    router_kernel<<<NTOK / 8, 256>>>(x, gw);
    aux_kernel<<<1, 256>>>(y + (out_size - 1));
    gateup_kernel<<<dim3(IDIM / TN, NTOK / TM, EEXP), 256>>>(x, wg, wu);
    down_kernel<<<dim3(HDIM / TN, NTOK / TM, EEXP), 256>>>(wd);
    combine_kernel<<<(NTOK * HDIM / 4) / 256, 256>>>(y);
}

// round 2
// speedup vs baseline: 1.3206x; 1.3206x over previous
#include <cuda_runtime.h>
#include <cuda_bf16.h>
#include <math.h>

// Problem constants (fixed by setup_inputs)
#define NTOK 8192      // B*S
#define HDIM 1024
#define IDIM 2048
#define EEXP 8
#define TOPK 2

// GEMM tiling
#define TM 128
#define TN 64
#define TK 32
#define AP 36          // padded k-length for A/B smem rows

// ---------------- device scratch ----------------
__device__ int   g_cnt[EEXP];
__device__ int   g_pairs[EEXP * NTOK];
__device__ float g_tokw[NTOK * 2];
__device__ int   g_toke[NTOK * 2];
__device__ float g_selw[NTOK * 2];
__device__ float g_hbuf[NTOK * 2 * IDIM];   // silu(gate)*up [pair, I]
__device__ float g_ybuf[NTOK * 2 * HDIM];   // expert outputs [pair, H]

// ---------------- helpers ----------------
__device__ __forceinline__ void bsplit2(float2 v, unsigned &hi, unsigned &lo) {
    __nv_bfloat162 h = __floats2bfloat162_rn(v.x, v.y);
    float lx = v.x - __bfloat162float(__low2bfloat16(h));
    float ly = v.y - __bfloat162float(__high2bfloat16(h));
    __nv_bfloat162 l = __floats2bfloat162_rn(lx, ly);
    hi = *reinterpret_cast<unsigned*>(&h);
    lo = *reinterpret_cast<unsigned*>(&l);
}

__device__ __forceinline__ void mma_bf16(float *d, const unsigned *a, const unsigned *b) {
    asm volatile("mma.sync.aligned.m16n8k16.row.col.f32.bf16.bf16.f32 "
        "{%0,%1,%2,%3}, {%4,%5,%6,%7}, {%8,%9}, {%0,%1,%2,%3};\n"
        : "+f"(d[0]), "+f"(d[1]), "+f"(d[2]), "+f"(d[3])
        : "r"(a[0]), "r"(a[1]), "r"(a[2]), "r"(a[3]), "r"(b[0]), "r"(b[1]));
}

// ---------------- reset ----------------
__global__ void reset_kernel() {
    if (threadIdx.x < EEXP) g_cnt[threadIdx.x] = 0;
}

// ---------------- router: one warp per token ----------------
__global__ void router_kernel(const float* __restrict__ x,
                              const float* __restrict__ gw) {
    int t = blockIdx.x * (blockDim.x >> 5) + (threadIdx.x >> 5);
    int lane = threadIdx.x & 31;
    if (t >= NTOK) return;
    const float* xr = x + (size_t)t * HDIM;
    float acc[EEXP];
#pragma unroll
    for (int e = 0; e < EEXP; e++) acc[e] = 0.f;
    for (int h = lane; h < HDIM; h += 32) {
        float xv = xr[h];
        const float* g = gw + h * EEXP;
#pragma unroll
        for (int e = 0; e < EEXP; e++) acc[e] = fmaf(xv, g[e], acc[e]);
    }
#pragma unroll
    for (int off = 16; off > 0; off >>= 1) {
#pragma unroll
        for (int e = 0; e < EEXP; e++)
            acc[e] += __shfl_down_sync(0xffffffffu, acc[e], off);
    }
    if (lane == 0) {
        float mx = acc[0];
#pragma unroll
        for (int e = 1; e < EEXP; e++) mx = fmaxf(mx, acc[e]);
        float p[EEXP];
        float s = 0.f;
#pragma unroll
        for (int e = 0; e < EEXP; e++) { p[e] = expf(acc[e] - mx); s += p[e]; }
        float inv = 1.f / s;
#pragma unroll
        for (int e = 0; e < EEXP; e++) p[e] *= inv;
        int e0 = 0;
#pragma unroll
        for (int e = 1; e < EEXP; e++) if (p[e] > p[e0]) e0 = e;
        int e1 = (e0 == 0) ? 1 : 0;
#pragma unroll
        for (int e = 0; e < EEXP; e++) if (e != e0 && p[e] > p[e1]) e1 = e;
        float w0 = p[e0], w1 = p[e1];
        float rs = 1.f / (w0 + w1);
        g_toke[2 * t] = e0;      g_toke[2 * t + 1] = e1;
        g_selw[2 * t] = w0;      g_selw[2 * t + 1] = w1;
        g_tokw[2 * t] = w0 * rs; g_tokw[2 * t + 1] = w1 * rs;
        int p0 = atomicAdd(&g_cnt[e0], 1);
        g_pairs[e0 * NTOK + p0] = 2 * t;
        int p1 = atomicAdd(&g_cnt[e1], 1);
        g_pairs[e1 * NTOK + p1] = 2 * t + 1;
    }
}

// ---------------- aux loss ----------------
__global__ void aux_kernel(float* __restrict__ out_aux) {
    __shared__ float sload[256][EEXP];
    int tid = threadIdx.x;
    float l[EEXP];
#pragma unroll
    for (int e = 0; e < EEXP; e++) l[e] = 0.f;
    for (int a = tid; a < NTOK * 2; a += 256)
        l[g_toke[a]] += g_selw[a];
#pragma unroll
    for (int e = 0; e < EEXP; e++) sload[tid][e] = l[e];
    __syncthreads();
    for (int s = 128; s > 0; s >>= 1) {
        if (tid < s) {
#pragma unroll
            for (int e = 0; e < EEXP; e++) sload[tid][e] += sload[tid + s][e];
        }
        __syncthreads();
    }
    if (tid == 0) {
        float aux = 0.f;
#pragma unroll
        for (int e = 0; e < EEXP; e++) {
            float pe = sload[0][e] / (float)NTOK;
            float pt = (float)g_cnt[e] / (float)(NTOK * TOPK);
            aux += pe * pt;
        }
        aux *= (float)EEXP * 1e-3f;
        *out_aux = aux;
    }
}

// ---------------- gate+up GEMM (bf16-split tensor core) ----------------
__global__ __launch_bounds__(256) void gateup_kernel(
    const float* __restrict__ x,
    const float* __restrict__ w_gate,
    const float* __restrict__ w_up) {
    int e = blockIdx.z;
    int M = g_cnt[e];
    int m0 = blockIdx.y * TM;
    if (m0 >= M) return;
    int n0 = blockIdx.x * TN;

    __shared__ float As[TM][AP];     // [m][k]
    __shared__ float Bg[TN][AP];     // [n][k] (transposed)
    __shared__ float Bu[TN][AP];
    __shared__ int   prow[TM];
    __shared__ int   toks[TM];

    int tid = threadIdx.x;
    if (tid < TM) {
        int r = m0 + tid;
        int pr = (r < M) ? g_pairs[e * NTOK + r] : g_pairs[e * NTOK];
        prow[tid] = pr;
        toks[tid] = pr >> 1;
    }
    __syncthreads();

    const float* wg = w_gate + (size_t)e * HDIM * IDIM;
    const float* wu = w_up   + (size_t)e * HDIM * IDIM;

    int wid = tid >> 5;
    int lane = tid & 31;
    int wm = wid >> 1;         // 0..3
    int wn = wid & 1;          // 0..1
    int g = lane >> 2;         // 0..7
    int q = lane & 3;          // 0..3

    float accG[2][4][4], accU[2][4][4];
#pragma unroll
    for (int i = 0; i < 2; i++)
#pragma unroll
        for (int j = 0; j < 4; j++)
#pragma unroll
            for (int c = 0; c < 4; c++) { accG[i][j][c] = 0.f; accU[i][j][c] = 0.f; }

    for (int k0 = 0; k0 < HDIM; k0 += TK) {
        // A tile: 128 rows x 32 k = 1024 float4 chunks / 256 thr = 4 each
#pragma unroll
        for (int i = 0; i < 4; i++) {
            int c = tid + i * 256;
            int row = c >> 3;
            int kq = (c & 7) * 4;
            float4 v = *(const float4*)(x + (size_t)toks[row] * HDIM + k0 + kq);
            *(float4*)&As[row][kq] = v;
        }
        // B tiles: transpose [k][n] -> [n][k]; 64x32 = 512 chunks / 256 = 2 each
#pragma unroll
        for (int i = 0; i < 2; i++) {
            int c = tid + i * 256;
            int kk = c >> 4;
            int nn = (c & 15) * 4;
            float4 vg = *(const float4*)(wg + (size_t)(k0 + kk) * IDIM + n0 + nn);
            Bg[nn + 0][kk] = vg.x; Bg[nn + 1][kk] = vg.y;
            Bg[nn + 2][kk] = vg.z; Bg[nn + 3][kk] = vg.w;
            float4 vu = *(const float4*)(wu + (size_t)(k0 + kk) * IDIM + n0 + nn);
            Bu[nn + 0][kk] = vu.x; Bu[nn + 1][kk] = vu.y;
            Bu[nn + 2][kk] = vu.z; Bu[nn + 3][kk] = vu.w;
        }
        __syncthreads();

#pragma unroll
        for (int kk = 0; kk < TK; kk += 16) {
            // A fragments (hi/lo)
            unsigned aH[2][4], aL[2][4];
#pragma unroll
            for (int mf = 0; mf < 2; mf++) {
                int rm = wm * 32 + mf * 16 + g;
                float2 v0 = *(const float2*)&As[rm][kk + 2 * q];
                float2 v1 = *(const float2*)&As[rm + 8][kk + 2 * q];
                float2 v2 = *(const float2*)&As[rm][kk + 2 * q + 8];
                float2 v3 = *(const float2*)&As[rm + 8][kk + 2 * q + 8];
                bsplit2(v0, aH[mf][0], aL[mf][0]);
                bsplit2(v1, aH[mf][1], aL[mf][1]);
                bsplit2(v2, aH[mf][2], aL[mf][2]);
                bsplit2(v3, aH[mf][3], aL[mf][3]);
            }
            // gate
#pragma unroll
            for (int nf = 0; nf < 4; nf++) {
                int cn = wn * 32 + nf * 8 + g;
                float2 u0 = *(const float2*)&Bg[cn][kk + 2 * q];
                float2 u1 = *(const float2*)&Bg[cn][kk + 2 * q + 8];
                unsigned bH[2], bL[2];
                bsplit2(u0, bH[0], bL[0]);
                bsplit2(u1, bH[1], bL[1]);
#pragma unroll
                for (int mf = 0; mf < 2; mf++) {
                    mma_bf16(accG[mf][nf], aH[mf], bH);
                    mma_bf16(accG[mf][nf], aL[mf], bH);
                    mma_bf16(accG[mf][nf], aH[mf], bL);
                }
            }
            // up
#pragma unroll
            for (int nf = 0; nf < 4; nf++) {
                int cn = wn * 32 + nf * 8 + g;
                float2 u0 = *(const float2*)&Bu[cn][kk + 2 * q];
                float2 u1 = *(const float2*)&Bu[cn][kk + 2 * q + 8];
                unsigned bH[2], bL[2];
                bsplit2(u0, bH[0], bL[0]);
                bsplit2(u1, bH[1], bL[1]);
#pragma unroll
                for (int mf = 0; mf < 2; mf++) {
                    mma_bf16(accU[mf][nf], aH[mf], bH);
                    mma_bf16(accU[mf][nf], aL[mf], bH);
                    mma_bf16(accU[mf][nf], aH[mf], bL);
                }
            }
        }
        __syncthreads();
    }

    // epilogue: h = silu(g) * u, write float2 pairs
#pragma unroll
    for (int mf = 0; mf < 2; mf++) {
#pragma unroll
        for (int half = 0; half < 2; half++) {
            int lr = wm * 32 + mf * 16 + g + half * 8;
            int r = m0 + lr;
            if (r < M) {
                int p = prow[lr];
#pragma unroll
                for (int nf = 0; nf < 4; nf++) {
                    int col = n0 + wn * 32 + nf * 8 + 2 * q;
                    float gv0 = accG[mf][nf][half * 2 + 0];
                    float gv1 = accG[mf][nf][half * 2 + 1];
                    float uv0 = accU[mf][nf][half * 2 + 0];
                    float uv1 = accU[mf][nf][half * 2 + 1];
                    float2 h;
                    h.x = (gv0 / (1.f + expf(-gv0))) * uv0;
                    h.y = (gv1 / (1.f + expf(-gv1))) * uv1;
                    *(float2*)&g_hbuf[(size_t)p * IDIM + col] = h;
                }
            }
        }
    }
}

// ---------------- down GEMM ----------------
__global__ __launch_bounds__(256) void down_kernel(const float* __restrict__ w_down) {
    int e = blockIdx.z;
    int M = g_cnt[e];
    int m0 = blockIdx.y * TM;
    if (m0 >= M) return;
    int n0 = blockIdx.x * TN;

    __shared__ float As[TM][AP];
    __shared__ float Bs[TN][AP];
    __shared__ int   prow[TM];

    int tid = threadIdx.x;
    if (tid < TM) {
        int r = m0 + tid;
        prow[tid] = (r < M) ? g_pairs[e * NTOK + r] : g_pairs[e * NTOK];
    }
    __syncthreads();

    const float* wd = w_down + (size_t)e * IDIM * HDIM;

    int wid = tid >> 5;
    int lane = tid & 31;
    int wm = wid >> 1;
    int wn = wid & 1;
    int g = lane >> 2;
    int q = lane & 3;

    float acc[2][4][4];
#pragma unroll
    for (int i = 0; i < 2; i++)
#pragma unroll
        for (int j = 0; j < 4; j++)
#pragma unroll
            for (int c = 0; c < 4; c++) acc[i][j][c] = 0.f;

    for (int k0 = 0; k0 < IDIM; k0 += TK) {
#pragma unroll
        for (int i = 0; i < 4; i++) {
            int c = tid + i * 256;
            int row = c >> 3;
            int kq = (c & 7) * 4;
            float4 v = *(const float4*)(g_hbuf + (size_t)prow[row] * IDIM + k0 + kq);
            *(float4*)&As[row][kq] = v;
        }
#pragma unroll
        for (int i = 0; i < 2; i++) {
            int c = tid + i * 256;
            int kk = c >> 4;
            int nn = (c & 15) * 4;
            float4 v = *(const float4*)(wd + (size_t)(k0 + kk) * HDIM + n0 + nn);
            Bs[nn + 0][kk] = v.x; Bs[nn + 1][kk] = v.y;
            Bs[nn + 2][kk] = v.z; Bs[nn + 3][kk] = v.w;
        }
        __syncthreads();

#pragma unroll
        for (int kk = 0; kk < TK; kk += 16) {
            unsigned aH[2][4], aL[2][4];
#pragma unroll
            for (int mf = 0; mf < 2; mf++) {
                int rm = wm * 32 + mf * 16 + g;
                float2 v0 = *(const float2*)&As[rm][kk + 2 * q];
                float2 v1 = *(const float2*)&As[rm + 8][kk + 2 * q];
                float2 v2 = *(const float2*)&As[rm][kk + 2 * q + 8];
                float2 v3 = *(const float2*)&As[rm + 8][kk + 2 * q + 8];
                bsplit2(v0, aH[mf][0], aL[mf][0]);
                bsplit2(v1, aH[mf][1], aL[mf][1]);
                bsplit2(v2, aH[mf][2], aL[mf][2]);
                bsplit2(v3, aH[mf][3], aL[mf][3]);
            }
#pragma unroll
            for (int nf = 0; nf < 4; nf++) {
                int cn = wn * 32 + nf * 8 + g;
                float2 u0 = *(const float2*)&Bs[cn][kk + 2 * q];
                float2 u1 = *(const float2*)&Bs[cn][kk + 2 * q + 8];
                unsigned bH[2], bL[2];
                bsplit2(u0, bH[0], bL[0]);
                bsplit2(u1, bH[1], bL[1]);
#pragma unroll
                for (int mf = 0; mf < 2; mf++) {
                    mma_bf16(acc[mf][nf], aH[mf], bH);
                    mma_bf16(acc[mf][nf], aL[mf], bH);
                    mma_bf16(acc[mf][nf], aH[mf], bL);
                }
            }
        }
        __syncthreads();
    }

#pragma unroll
    for (int mf = 0; mf < 2; mf++) {
#pragma unroll
        for (int half = 0; half < 2; half++) {
            int lr = wm * 32 + mf * 16 + g + half * 8;
            int r = m0 + lr;
            if (r < M) {
                int p = prow[lr];
#pragma unroll
                for (int nf = 0; nf < 4; nf++) {
                    int col = n0 + wn * 32 + nf * 8 + 2 * q;
                    float2 o;
                    o.x = acc[mf][nf][half * 2 + 0];
                    o.y = acc[mf][nf][half * 2 + 1];
                    *(float2*)&g_ybuf[(size_t)p * HDIM + col] = o;
                }
            }
        }
    }
}

// ---------------- combine ----------------
__global__ void combine_kernel(float* __restrict__ y) {
    int idx = blockIdx.x * blockDim.x + threadIdx.x;
    int t = idx / (HDIM / 4);
    int h4 = (idx - t * (HDIM / 4)) * 4;
    float w0 = g_tokw[2 * t], w1 = g_tokw[2 * t + 1];
    float4 a = *(const float4*)&g_ybuf[(size_t)(2 * t) * HDIM + h4];
    float4 b = *(const float4*)&g_ybuf[(size_t)(2 * t + 1) * HDIM + h4];
    float4 r;
    r.x = w0 * a.x + w1 * b.x;
    r.y = w0 * a.y + w1 * b.y;
    r.z = w0 * a.z + w1 * b.z;
    r.w = w0 * a.w + w1 * b.w;
    *(float4*)&y[(size_t)t * HDIM + h4] = r;
}

// ---------------- launch ----------------
extern "C" void kernel_launch(void* const* d_in, const int* in_sizes, int n_in,
                              void* d_out, int out_size) {
    const float* x  = (const float*)d_in[0];
    const float* gw = (const float*)d_in[1];
    const float* wg = (const float*)d_in[2];
    const float* wu = (const float*)d_in[3];
    const float* wd = (const float*)d_in[4];
    float* y = (float*)d_out;

    reset_kernel<<<1, 32>>>();
    router_kernel<<<NTOK / 8, 256>>>(x, gw);
    aux_kernel<<<1, 256>>>(y + (out_size - 1));
    gateup_kernel<<<dim3(IDIM / TN, (NTOK * 2) / TM, EEXP), 256>>>(x, wg, wu);
    down_kernel<<<dim3(HDIM / TN, (NTOK * 2) / TM, EEXP), 256>>>(wd);
    combine_kernel<<<(NTOK * HDIM / 4) / 256, 256>>>(y);
}

// round 4
// speedup vs baseline: 1.8957x; 1.4355x over previous
#include <cuda_runtime.h>
#include <cuda_bf16.h>
#include <math.h>

// Problem constants (fixed by setup_inputs)
#define NTOK 8192      // B*S
#define HDIM 1024
#define IDIM 2048
#define EEXP 8
#define TOPK 2

// GEMM tiling
#define TM 128
#define TN 64
#define TK 32
#define AP 40          // padded k-row length (bf16 elems): 80B stride -> conflict-free

// ---------------- device scratch ----------------
__device__ int   g_cnt[EEXP];
__device__ int   g_pairs[EEXP * NTOK];
__device__ float g_tokw[NTOK * 2];
__device__ int   g_toke[NTOK * 2];
__device__ float g_selw[NTOK * 2];

// pre-split operands (bf16 hi/lo)
__device__ __nv_bfloat16 g_xh[NTOK * HDIM];
__device__ __nv_bfloat16 g_xl[NTOK * HDIM];
__device__ __nv_bfloat16 g_wgh[EEXP * IDIM * HDIM];  // gate, transposed [e][i][h]
__device__ __nv_bfloat16 g_wgl[EEXP * IDIM * HDIM];
__device__ __nv_bfloat16 g_wuh[EEXP * IDIM * HDIM];  // up, transposed [e][i][h]
__device__ __nv_bfloat16 g_wul[EEXP * IDIM * HDIM];
__device__ __nv_bfloat16 g_wdh[EEXP * HDIM * IDIM];  // down, transposed [e][h][i]
__device__ __nv_bfloat16 g_wdl[EEXP * HDIM * IDIM];
__device__ __nv_bfloat16 g_hbh[NTOK * 2 * IDIM];     // silu(g)*u hi  [pair][I]
__device__ __nv_bfloat16 g_hbl[NTOK * 2 * IDIM];     // silu(g)*u lo
__device__ float g_ybuf[NTOK * 2 * HDIM];            // expert outputs [pair][H]

// ---------------- helpers ----------------
__device__ __forceinline__ void bsplit2(float a, float b, unsigned &hi, unsigned &lo) {
    __nv_bfloat162 h = __floats2bfloat162_rn(a, b);
    float lx = a - __bfloat162float(__low2bfloat16(h));
    float ly = b - __bfloat162float(__high2bfloat16(h));
    __nv_bfloat162 l = __floats2bfloat162_rn(lx, ly);
    hi = *reinterpret_cast<unsigned*>(&h);
    lo = *reinterpret_cast<unsigned*>(&l);
}

__device__ __forceinline__ void mma_bf16(float *d, const unsigned *a, const unsigned *b) {
    asm volatile("mma.sync.aligned.m16n8k16.row.col.f32.bf16.bf16.f32 "
        "{%0,%1,%2,%3}, {%4,%5,%6,%7}, {%8,%9}, {%0,%1,%2,%3};\n"
        : "+f"(d[0]), "+f"(d[1]), "+f"(d[2]), "+f"(d[3])
        : "r"(a[0]), "r"(a[1]), "r"(a[2]), "r"(a[3]), "r"(b[0]), "r"(b[1]));
}

// ---------------- reset ----------------
__global__ void reset_kernel() {
    if (threadIdx.x < EEXP) g_cnt[threadIdx.x] = 0;
}

// ---------------- split x into bf16 hi/lo ----------------
__global__ void split_x_kernel(const float* __restrict__ x) {
    int idx = blockIdx.x * blockDim.x + threadIdx.x;   // over NTOK*HDIM/4
    float4 v = ((const float4*)x)[idx];
    unsigned h0, l0, h1, l1;
    bsplit2(v.x, v.y, h0, l0);
    bsplit2(v.z, v.w, h1, l1);
    uint2 hh; hh.x = h0; hh.y = h1;
    uint2 ll; ll.x = l0; ll.y = l1;
    ((uint2*)g_xh)[idx] = hh;
    ((uint2*)g_xl)[idx] = ll;
}

// ---------------- transpose+split weights: src [E][R][C] -> dst [E][C][R] ----------------
// W selects the destination __device__ arrays IN DEVICE CODE (host code must
// never pass a __device__ global's address as a kernel argument — that passes
// the host shadow symbol, which ATS silently dereferences into host memory).
template<int W>
__global__ void transpose_split_kernel(const float* __restrict__ src, int R, int C) {
    __nv_bfloat16* dh = (W == 0) ? g_wgh : (W == 1) ? g_wuh : g_wdh;
    __nv_bfloat16* dl = (W == 0) ? g_wgl : (W == 1) ? g_wul : g_wdl;
    __shared__ float s[32][33];
    int e = blockIdx.z;
    int r0 = blockIdx.y * 32, c0 = blockIdx.x * 32;
    int tx = threadIdx.x & 31, ty = threadIdx.x >> 5;  // 256 thr: ty 0..7
    const float* sp = src + ((size_t)e * R + r0) * C + c0;
#pragma unroll
    for (int j = 0; j < 4; j++)
        s[ty + j * 8][tx] = sp[(size_t)(ty + j * 8) * C + tx];
    __syncthreads();
    size_t dbase = ((size_t)e * C + c0) * R + r0;
#pragma unroll
    for (int j = 0; j < 4; j++) {
        float v = s[tx][ty + j * 8];
        __nv_bfloat16 h = __float2bfloat16(v);
        __nv_bfloat16 l = __float2bfloat16(v - __bfloat162float(h));
        dh[dbase + (size_t)(ty + j * 8) * R + tx] = h;
        dl[dbase + (size_t)(ty + j * 8) * R + tx] = l;
    }
}

// ---------------- router: one warp per token ----------------
__global__ void router_kernel(const float* __restrict__ x,
                              const float* __restrict__ gw) {
    int t = blockIdx.x * (blockDim.x >> 5) + (threadIdx.x >> 5);
    int lane = threadIdx.x & 31;
    if (t >= NTOK) return;
    const float* xr = x + (size_t)t * HDIM;
    float acc[EEXP];
#pragma unroll
    for (int e = 0; e < EEXP; e++) acc[e] = 0.f;
    for (int h = lane; h < HDIM; h += 32) {
        float xv = xr[h];
        const float* g = gw + h * EEXP;
#pragma unroll
        for (int e = 0; e < EEXP; e++) acc[e] = fmaf(xv, g[e], acc[e]);
    }
#pragma unroll
    for (int off = 16; off > 0; off >>= 1) {
#pragma unroll
        for (int e = 0; e < EEXP; e++)
            acc[e] += __shfl_down_sync(0xffffffffu, acc[e], off);
    }
    if (lane == 0) {
        float mx = acc[0];
#pragma unroll
        for (int e = 1; e < EEXP; e++) mx = fmaxf(mx, acc[e]);
        float p[EEXP];
        float s = 0.f;
#pragma unroll
        for (int e = 0; e < EEXP; e++) { p[e] = expf(acc[e] - mx); s += p[e]; }
        float inv = 1.f / s;
#pragma unroll
        for (int e = 0; e < EEXP; e++) p[e] *= inv;
        int e0 = 0;
#pragma unroll
        for (int e = 1; e < EEXP; e++) if (p[e] > p[e0]) e0 = e;
        int e1 = (e0 == 0) ? 1 : 0;
#pragma unroll
        for (int e = 0; e < EEXP; e++) if (e != e0 && p[e] > p[e1]) e1 = e;
        float w0 = p[e0], w1 = p[e1];
        float rs = 1.f / (w0 + w1);
        g_toke[2 * t] = e0;      g_toke[2 * t + 1] = e1;
        g_selw[2 * t] = w0;      g_selw[2 * t + 1] = w1;
        g_tokw[2 * t] = w0 * rs; g_tokw[2 * t + 1] = w1 * rs;
        int p0 = atomicAdd(&g_cnt[e0], 1);
        g_pairs[e0 * NTOK + p0] = 2 * t;
        int p1 = atomicAdd(&g_cnt[e1], 1);
        g_pairs[e1 * NTOK + p1] = 2 * t + 1;
    }
}

// ---------------- aux loss ----------------
__global__ void aux_kernel(float* __restrict__ out_aux) {
    __shared__ float sload[256][EEXP];
    int tid = threadIdx.x;
    float l[EEXP];
#pragma unroll
    for (int e = 0; e < EEXP; e++) l[e] = 0.f;
    for (int a = tid; a < NTOK * 2; a += 256)
        l[g_toke[a]] += g_selw[a];
#pragma unroll
    for (int e = 0; e < EEXP; e++) sload[tid][e] = l[e];
    __syncthreads();
    for (int s = 128; s > 0; s >>= 1) {
        if (tid < s) {
#pragma unroll
            for (int e = 0; e < EEXP; e++) sload[tid][e] += sload[tid + s][e];
        }
        __syncthreads();
    }
    if (tid == 0) {
        float aux = 0.f;
#pragma unroll
        for (int e = 0; e < EEXP; e++) {
            float pe = sload[0][e] / (float)NTOK;
            float pt = (float)g_cnt[e] / (float)(NTOK * TOPK);
            aux += pe * pt;
        }
        aux *= (float)EEXP * 1e-3f;
        *out_aux = aux;
    }
}

// ---------------- gate+up GEMM (pre-split bf16 tensor core) ----------------
__global__ __launch_bounds__(256) void gateup_kernel() {
    int e = blockIdx.z;
    int M = g_cnt[e];
    int m0 = blockIdx.y * TM;
    if (m0 >= M) return;
    int n0 = blockIdx.x * TN;

    __shared__ __nv_bfloat16 Ah[TM][AP], Al[TM][AP];
    __shared__ __nv_bfloat16 Bgh[TN][AP], Bgl[TN][AP], Buh[TN][AP], Bul[TN][AP];
    __shared__ int prow[TM];
    __shared__ int toks[TM];

    int tid = threadIdx.x;
    if (tid < TM) {
        int r = m0 + tid;
        int pr = (r < M) ? g_pairs[e * NTOK + r] : g_pairs[e * NTOK];
        prow[tid] = pr;
        toks[tid] = pr >> 1;
    }
    __syncthreads();

    const __nv_bfloat16* wgh = g_wgh + (size_t)e * IDIM * HDIM;
    const __nv_bfloat16* wgl = g_wgl + (size_t)e * IDIM * HDIM;
    const __nv_bfloat16* wuh = g_wuh + (size_t)e * IDIM * HDIM;
    const __nv_bfloat16* wul = g_wul + (size_t)e * IDIM * HDIM;

    int wid = tid >> 5;
    int lane = tid & 31;
    int wm = wid >> 1;         // 0..3
    int wn = wid & 1;          // 0..1
    int g = lane >> 2;         // 0..7
    int q = lane & 3;          // 0..3

    float accG[2][4][4], accU[2][4][4];
#pragma unroll
    for (int i = 0; i < 2; i++)
#pragma unroll
        for (int j = 0; j < 4; j++)
#pragma unroll
            for (int c = 0; c < 4; c++) { accG[i][j][c] = 0.f; accU[i][j][c] = 0.f; }

    int arow = tid >> 2;            // 0..63
    int achk = (tid & 3) * 8;       // elem offset within row

    for (int k0 = 0; k0 < HDIM; k0 += TK) {
        // A tiles: rows gathered by token
#pragma unroll
        for (int i = 0; i < 2; i++) {
            int row = arow + i * 64;
            size_t goff = (size_t)toks[row] * HDIM + k0 + achk;
            *(int4*)&Ah[row][achk] = *(const int4*)&g_xh[goff];
            *(int4*)&Al[row][achk] = *(const int4*)&g_xl[goff];
        }
        // B tiles: straight copies from transposed weights
        {
            size_t goff = (size_t)(n0 + arow) * HDIM + k0 + achk;
            *(int4*)&Bgh[arow][achk] = *(const int4*)&wgh[goff];
            *(int4*)&Bgl[arow][achk] = *(const int4*)&wgl[goff];
            *(int4*)&Buh[arow][achk] = *(const int4*)&wuh[goff];
            *(int4*)&Bul[arow][achk] = *(const int4*)&wul[goff];
        }
        __syncthreads();

#pragma unroll
        for (int kk = 0; kk < TK; kk += 16) {
            unsigned aH[2][4], aL[2][4];
#pragma unroll
            for (int mf = 0; mf < 2; mf++) {
                int rm = wm * 32 + mf * 16 + g;
                aH[mf][0] = *(const unsigned*)&Ah[rm][kk + 2 * q];
                aH[mf][1] = *(const unsigned*)&Ah[rm + 8][kk + 2 * q];
                aH[mf][2] = *(const unsigned*)&Ah[rm][kk + 2 * q + 8];
                aH[mf][3] = *(const unsigned*)&Ah[rm + 8][kk + 2 * q + 8];
                aL[mf][0] = *(const unsigned*)&Al[rm][kk + 2 * q];
                aL[mf][1] = *(const unsigned*)&Al[rm + 8][kk + 2 * q];
                aL[mf][2] = *(const unsigned*)&Al[rm][kk + 2 * q + 8];
                aL[mf][3] = *(const unsigned*)&Al[rm + 8][kk + 2 * q + 8];
            }
#pragma unroll
            for (int nf = 0; nf < 4; nf++) {
                int cn = wn * 32 + nf * 8 + g;
                unsigned bH[2], bL[2];
                bH[0] = *(const unsigned*)&Bgh[cn][kk + 2 * q];
                bH[1] = *(const unsigned*)&Bgh[cn][kk + 2 * q + 8];
                bL[0] = *(const unsigned*)&Bgl[cn][kk + 2 * q];
                bL[1] = *(const unsigned*)&Bgl[cn][kk + 2 * q + 8];
#pragma unroll
                for (int mf = 0; mf < 2; mf++) {
                    mma_bf16(accG[mf][nf], aH[mf], bH);
                    mma_bf16(accG[mf][nf], aL[mf], bH);
                    mma_bf16(accG[mf][nf], aH[mf], bL);
                }
            }
#pragma unroll
            for (int nf = 0; nf < 4; nf++) {
                int cn = wn * 32 + nf * 8 + g;
                unsigned bH[2], bL[2];
                bH[0] = *(const unsigned*)&Buh[cn][kk + 2 * q];
                bH[1] = *(const unsigned*)&Buh[cn][kk + 2 * q + 8];
                bL[0] = *(const unsigned*)&Bul[cn][kk + 2 * q];
                bL[1] = *(const unsigned*)&Bul[cn][kk + 2 * q + 8];
#pragma unroll
                for (int mf = 0; mf < 2; mf++) {
                    mma_bf16(accU[mf][nf], aH[mf], bH);
                    mma_bf16(accU[mf][nf], aL[mf], bH);
                    mma_bf16(accU[mf][nf], aH[mf], bL);
                }
            }
        }
        __syncthreads();
    }

    // epilogue: h = silu(g) * u, pre-split to bf16 hi/lo
#pragma unroll
    for (int mf = 0; mf < 2; mf++) {
#pragma unroll
        for (int half = 0; half < 2; half++) {
            int lr = wm * 32 + mf * 16 + g + half * 8;
            int r = m0 + lr;
            if (r < M) {
                int p = prow[lr];
#pragma unroll
                for (int nf = 0; nf < 4; nf++) {
                    int col = n0 + wn * 32 + nf * 8 + 2 * q;
                    float gv0 = accG[mf][nf][half * 2 + 0];
                    float gv1 = accG[mf][nf][half * 2 + 1];
                    float uv0 = accU[mf][nf][half * 2 + 0];
                    float uv1 = accU[mf][nf][half * 2 + 1];
                    float hx = (gv0 / (1.f + expf(-gv0))) * uv0;
                    float hy = (gv1 / (1.f + expf(-gv1))) * uv1;
                    unsigned hb, lb;
                    bsplit2(hx, hy, hb, lb);
                    *(unsigned*)&g_hbh[(size_t)p * IDIM + col] = hb;
                    *(unsigned*)&g_hbl[(size_t)p * IDIM + col] = lb;
                }
            }
        }
    }
}

// ---------------- down GEMM ----------------
__global__ __launch_bounds__(256) void down_kernel() {
    int e = blockIdx.z;
    int M = g_cnt[e];
    int m0 = blockIdx.y * TM;
    if (m0 >= M) return;
    int n0 = blockIdx.x * TN;

    __shared__ __nv_bfloat16 Ah[TM][AP], Al[TM][AP];
    __shared__ __nv_bfloat16 Bh[TN][AP], Bl[TN][AP];
    __shared__ int prow[TM];

    int tid = threadIdx.x;
    if (tid < TM) {
        int r = m0 + tid;
        prow[tid] = (r < M) ? g_pairs[e * NTOK + r] : g_pairs[e * NTOK];
    }
    __syncthreads();

    const __nv_bfloat16* wdh = g_wdh + (size_t)e * HDIM * IDIM;
    const __nv_bfloat16* wdl = g_wdl + (size_t)e * HDIM * IDIM;

    int wid = tid >> 5;
    int lane = tid & 31;
    int wm = wid >> 1;
    int wn = wid & 1;
    int g = lane >> 2;
    int q = lane & 3;

    float acc[2][4][4];
#pragma unroll
    for (int i = 0; i < 2; i++)
#pragma unroll
        for (int j = 0; j < 4; j++)
#pragma unroll
            for (int c = 0; c < 4; c++) acc[i][j][c] = 0.f;

    int arow = tid >> 2;
    int achk = (tid & 3) * 8;

    for (int k0 = 0; k0 < IDIM; k0 += TK) {
#pragma unroll
        for (int i = 0; i < 2; i++) {
            int row = arow + i * 64;
            size_t goff = (size_t)prow[row] * IDIM + k0 + achk;
            *(int4*)&Ah[row][achk] = *(const int4*)&g_hbh[goff];
            *(int4*)&Al[row][achk] = *(const int4*)&g_hbl[goff];
        }
        {
            size_t goff = (size_t)(n0 + arow) * IDIM + k0 + achk;
            *(int4*)&Bh[arow][achk] = *(const int4*)&wdh[goff];
            *(int4*)&Bl[arow][achk] = *(const int4*)&wdl[goff];
        }
        __syncthreads();

#pragma unroll
        for (int kk = 0; kk < TK; kk += 16) {
            unsigned aH[2][4], aL[2][4];
#pragma unroll
            for (int mf = 0; mf < 2; mf++) {
                int rm = wm * 32 + mf * 16 + g;
                aH[mf][0] = *(const unsigned*)&Ah[rm][kk + 2 * q];
                aH[mf][1] = *(const unsigned*)&Ah[rm + 8][kk + 2 * q];
                aH[mf][2] = *(const unsigned*)&Ah[rm][kk + 2 * q + 8];
                aH[mf][3] = *(const unsigned*)&Ah[rm + 8][kk + 2 * q + 8];
                aL[mf][0] = *(const unsigned*)&Al[rm][kk + 2 * q];
                aL[mf][1] = *(const unsigned*)&Al[rm + 8][kk + 2 * q];
                aL[mf][2] = *(const unsigned*)&Al[rm][kk + 2 * q + 8];
                aL[mf][3] = *(const unsigned*)&Al[rm + 8][kk + 2 * q + 8];
            }
#pragma unroll
            for (int nf = 0; nf < 4; nf++) {
                int cn = wn * 32 + nf * 8 + g;
                unsigned bH[2], bL[2];
                bH[0] = *(const unsigned*)&Bh[cn][kk + 2 * q];
                bH[1] = *(const unsigned*)&Bh[cn][kk + 2 * q + 8];
                bL[0] = *(const unsigned*)&Bl[cn][kk + 2 * q];
                bL[1] = *(const unsigned*)&Bl[cn][kk + 2 * q + 8];
#pragma unroll
                for (int mf = 0; mf < 2; mf++) {
                    mma_bf16(acc[mf][nf], aH[mf], bH);
                    mma_bf16(acc[mf][nf], aL[mf], bH);
                    mma_bf16(acc[mf][nf], aH[mf], bL);
                }
            }
        }
        __syncthreads();
    }

#pragma unroll
    for (int mf = 0; mf < 2; mf++) {
#pragma unroll
        for (int half = 0; half < 2; half++) {
            int lr = wm * 32 + mf * 16 + g + half * 8;
            int r = m0 + lr;
            if (r < M) {
                int p = prow[lr];
#pragma unroll
                for (int nf = 0; nf < 4; nf++) {
                    int col = n0 + wn * 32 + nf * 8 + 2 * q;
                    float2 o;
                    o.x = acc[mf][nf][half * 2 + 0];
                    o.y = acc[mf][nf][half * 2 + 1];
                    *(float2*)&g_ybuf[(size_t)p * HDIM + col] = o;
                }
            }
        }
    }
}

// ---------------- combine ----------------
__global__ void combine_kernel(float* __restrict__ y) {
    int idx = blockIdx.x * blockDim.x + threadIdx.x;
    int t = idx / (HDIM / 4);
    int h4 = (idx - t * (HDIM / 4)) * 4;
    float w0 = g_tokw[2 * t], w1 = g_tokw[2 * t + 1];
    float4 a = *(const float4*)&g_ybuf[(size_t)(2 * t) * HDIM + h4];
    float4 b = *(const float4*)&g_ybuf[(size_t)(2 * t + 1) * HDIM + h4];
    float4 r;
    r.x = w0 * a.x + w1 * b.x;
    r.y = w0 * a.y + w1 * b.y;
    r.z = w0 * a.z + w1 * b.z;
    r.w = w0 * a.w + w1 * b.w;
    *(float4*)&y[(size_t)t * HDIM + h4] = r;
}

// ---------------- launch ----------------
extern "C" void kernel_launch(void* const* d_in, const int* in_sizes, int n_in,
                              void* d_out, int out_size) {
    const float* x  = (const float*)d_in[0];
    const float* gw = (const float*)d_in[1];
    const float* wg = (const float*)d_in[2];
    const float* wu = (const float*)d_in[3];
    const float* wd = (const float*)d_in[4];
    float* y = (float*)d_out;

    reset_kernel<<<1, 32>>>();
    router_kernel<<<NTOK / 8, 256>>>(x, gw);
    aux_kernel<<<1, 256>>>(y + (out_size - 1));

    split_x_kernel<<<(NTOK * HDIM / 4) / 256, 256>>>(x);
    // w_gate [E][H][I] -> [E][I][H]
    transpose_split_kernel<0><<<dim3(IDIM / 32, HDIM / 32, EEXP), 256>>>(wg, HDIM, IDIM);
    transpose_split_kernel<1><<<dim3(IDIM / 32, HDIM / 32, EEXP), 256>>>(wu, HDIM, IDIM);
    // w_down [E][I][H] -> [E][H][I]
    transpose_split_kernel<2><<<dim3(HDIM / 32, IDIM / 32, EEXP), 256>>>(wd, IDIM, HDIM);

    gateup_kernel<<<dim3(IDIM / TN, (NTOK * 2) / TM, EEXP), 256>>>();
    down_kernel<<<dim3(HDIM / TN, (NTOK * 2) / TM, EEXP), 256>>>();
    combine_kernel<<<(NTOK * HDIM / 4) / 256, 256>>>(y);
}

// round 5
// speedup vs baseline: 1.8969x; 1.0007x over previous
#include <cuda_runtime.h>
#include <cuda_bf16.h>
#include <math.h>

// Problem constants (fixed by setup_inputs)
#define NTOK 8192      // B*S
#define HDIM 1024
#define IDIM 2048
#define EEXP 8
#define TOPK 2

// GEMM tiling
#define TM 128
#define TN 64
#define TK 32
#define AP 40          // padded k-row length (bf16): 80B stride, 16B-aligned chunks

// ---------------- device scratch ----------------
__device__ int   g_cnt[EEXP];
__device__ int   g_pairs[EEXP * NTOK];
__device__ float g_tokw[NTOK * 2];
__device__ int   g_toke[NTOK * 2];
__device__ float g_selw[NTOK * 2];

// pre-split operands (bf16 hi/lo)
__device__ __nv_bfloat16 g_xh[NTOK * HDIM];
__device__ __nv_bfloat16 g_xl[NTOK * HDIM];
__device__ __nv_bfloat16 g_wgh[EEXP * IDIM * HDIM];  // gate, transposed [e][i][h]
__device__ __nv_bfloat16 g_wgl[EEXP * IDIM * HDIM];
__device__ __nv_bfloat16 g_wuh[EEXP * IDIM * HDIM];  // up, transposed [e][i][h]
__device__ __nv_bfloat16 g_wul[EEXP * IDIM * HDIM];
__device__ __nv_bfloat16 g_wdh[EEXP * HDIM * IDIM];  // down, transposed [e][h][i]
__device__ __nv_bfloat16 g_wdl[EEXP * HDIM * IDIM];
__device__ __nv_bfloat16 g_hbh[NTOK * 2 * IDIM];     // silu(g)*u hi  [pair][I]
__device__ __nv_bfloat16 g_hbl[NTOK * 2 * IDIM];     // silu(g)*u lo
__device__ float g_ybuf[NTOK * 2 * HDIM];            // expert outputs [pair][H]

// ---------------- helpers ----------------
__device__ __forceinline__ void bsplit2(float a, float b, unsigned &hi, unsigned &lo) {
    __nv_bfloat162 h = __floats2bfloat162_rn(a, b);
    float lx = a - __bfloat162float(__low2bfloat16(h));
    float ly = b - __bfloat162float(__high2bfloat16(h));
    __nv_bfloat162 l = __floats2bfloat162_rn(lx, ly);
    hi = *reinterpret_cast<unsigned*>(&h);
    lo = *reinterpret_cast<unsigned*>(&l);
}

__device__ __forceinline__ void mma_bf16(float *d, const unsigned *a, const unsigned *b) {
    asm volatile("mma.sync.aligned.m16n8k16.row.col.f32.bf16.bf16.f32 "
        "{%0,%1,%2,%3}, {%4,%5,%6,%7}, {%8,%9}, {%0,%1,%2,%3};\n"
        : "+f"(d[0]), "+f"(d[1]), "+f"(d[2]), "+f"(d[3])
        : "r"(a[0]), "r"(a[1]), "r"(a[2]), "r"(a[3]), "r"(b[0]), "r"(b[1]));
}

__device__ __forceinline__ void cpa16(void* smem, const void* g) {
    unsigned s = (unsigned)__cvta_generic_to_shared(smem);
    asm volatile("cp.async.cg.shared.global [%0], [%1], 16;\n" :: "r"(s), "l"(g));
}
__device__ __forceinline__ void cpa_commit() {
    asm volatile("cp.async.commit_group;\n");
}
__device__ __forceinline__ void cpa_wait0() {
    asm volatile("cp.async.wait_group 0;\n");
}

// ---------------- reset ----------------
__global__ void reset_kernel() {
    if (threadIdx.x < EEXP) g_cnt[threadIdx.x] = 0;
}

// ---------------- split x into bf16 hi/lo ----------------
__global__ void split_x_kernel(const float* __restrict__ x) {
    int idx = blockIdx.x * blockDim.x + threadIdx.x;
    float4 v = ((const float4*)x)[idx];
    unsigned h0, l0, h1, l1;
    bsplit2(v.x, v.y, h0, l0);
    bsplit2(v.z, v.w, h1, l1);
    uint2 hh; hh.x = h0; hh.y = h1;
    uint2 ll; ll.x = l0; ll.y = l1;
    ((uint2*)g_xh)[idx] = hh;
    ((uint2*)g_xl)[idx] = ll;
}

// ---------------- transpose+split weights: src [E][R][C] -> dst [E][C][R] ----------------
// W selects destinations IN DEVICE CODE (never pass __device__ globals as host-side
// kernel args: that passes the host shadow symbol; ATS dereferences host memory).
template<int W>
__global__ void transpose_split_kernel(const float* __restrict__ src, int R, int C) {
    __nv_bfloat16* dh = (W == 0) ? g_wgh : (W == 1) ? g_wuh : g_wdh;
    __nv_bfloat16* dl = (W == 0) ? g_wgl : (W == 1) ? g_wul : g_wdl;
    __shared__ float s[32][33];
    int e = blockIdx.z;
    int r0 = blockIdx.y * 32, c0 = blockIdx.x * 32;
    int tx = threadIdx.x & 31, ty = threadIdx.x >> 5;
    const float* sp = src + ((size_t)e * R + r0) * C + c0;
#pragma unroll
    for (int j = 0; j < 4; j++)
        s[ty + j * 8][tx] = sp[(size_t)(ty + j * 8) * C + tx];
    __syncthreads();
    size_t dbase = ((size_t)e * C + c0) * R + r0;
#pragma unroll
    for (int j = 0; j < 4; j++) {
        float v = s[tx][ty + j * 8];
        __nv_bfloat16 h = __float2bfloat16(v);
        __nv_bfloat16 l = __float2bfloat16(v - __bfloat162float(h));
        dh[dbase + (size_t)(ty + j * 8) * R + tx] = h;
        dl[dbase + (size_t)(ty + j * 8) * R + tx] = l;
    }
}

// ---------------- router: one warp per token ----------------
__global__ void router_kernel(const float* __restrict__ x,
                              const float* __restrict__ gw) {
    int t = blockIdx.x * (blockDim.x >> 5) + (threadIdx.x >> 5);
    int lane = threadIdx.x & 31;
    if (t >= NTOK) return;
    const float* xr = x + (size_t)t * HDIM;
    float acc[EEXP];
#pragma unroll
    for (int e = 0; e < EEXP; e++) acc[e] = 0.f;
    for (int h = lane; h < HDIM; h += 32) {
        float xv = xr[h];
        const float* g = gw + h * EEXP;
#pragma unroll
        for (int e = 0; e < EEXP; e++) acc[e] = fmaf(xv, g[e], acc[e]);
    }
#pragma unroll
    for (int off = 16; off > 0; off >>= 1) {
#pragma unroll
        for (int e = 0; e < EEXP; e++)
            acc[e] += __shfl_down_sync(0xffffffffu, acc[e], off);
    }
    if (lane == 0) {
        float mx = acc[0];
#pragma unroll
        for (int e = 1; e < EEXP; e++) mx = fmaxf(mx, acc[e]);
        float p[EEXP];
        float s = 0.f;
#pragma unroll
        for (int e = 0; e < EEXP; e++) { p[e] = expf(acc[e] - mx); s += p[e]; }
        float inv = 1.f / s;
#pragma unroll
        for (int e = 0; e < EEXP; e++) p[e] *= inv;
        int e0 = 0;
#pragma unroll
        for (int e = 1; e < EEXP; e++) if (p[e] > p[e0]) e0 = e;
        int e1 = (e0 == 0) ? 1 : 0;
#pragma unroll
        for (int e = 0; e < EEXP; e++) if (e != e0 && p[e] > p[e1]) e1 = e;
        float w0 = p[e0], w1 = p[e1];
        float rs = 1.f / (w0 + w1);
        g_toke[2 * t] = e0;      g_toke[2 * t + 1] = e1;
        g_selw[2 * t] = w0;      g_selw[2 * t + 1] = w1;
        g_tokw[2 * t] = w0 * rs; g_tokw[2 * t + 1] = w1 * rs;
        int p0 = atomicAdd(&g_cnt[e0], 1);
        g_pairs[e0 * NTOK + p0] = 2 * t;
        int p1 = atomicAdd(&g_cnt[e1], 1);
        g_pairs[e1 * NTOK + p1] = 2 * t + 1;
    }
}

// ---------------- aux loss ----------------
__global__ void aux_kernel(float* __restrict__ out_aux) {
    __shared__ float sload[256][EEXP];
    int tid = threadIdx.x;
    float l[EEXP];
#pragma unroll
    for (int e = 0; e < EEXP; e++) l[e] = 0.f;
    for (int a = tid; a < NTOK * 2; a += 256)
        l[g_toke[a]] += g_selw[a];
#pragma unroll
    for (int e = 0; e < EEXP; e++) sload[tid][e] = l[e];
    __syncthreads();
    for (int s = 128; s > 0; s >>= 1) {
        if (tid < s) {
#pragma unroll
            for (int e = 0; e < EEXP; e++) sload[tid][e] += sload[tid + s][e];
        }
        __syncthreads();
    }
    if (tid == 0) {
        float aux = 0.f;
#pragma unroll
        for (int e = 0; e < EEXP; e++) {
            float pe = sload[0][e] / (float)NTOK;
            float pt = (float)g_cnt[e] / (float)(NTOK * TOPK);
            aux += pe * pt;
        }
        aux *= (float)EEXP * 1e-3f;
        *out_aux = aux;
    }
}

// ---------------- gate+up GEMM (bf16-split, cp.async double-buffered) ----------------
__global__ __launch_bounds__(256) void gateup_kernel() {
    int e = blockIdx.z;
    int M = g_cnt[e];
    int m0 = blockIdx.y * TM;
    if (m0 >= M) return;
    int n0 = blockIdx.x * TN;

    __shared__ __nv_bfloat16 Ah[2][TM][AP], Al[2][TM][AP];
    __shared__ __nv_bfloat16 Bgh[2][TN][AP], Bgl[2][TN][AP], Buh[2][TN][AP], Bul[2][TN][AP];
    __shared__ int prow[TM];
    __shared__ int toks[TM];

    int tid = threadIdx.x;
    if (tid < TM) {
        int r = m0 + tid;
        int pr = (r < M) ? g_pairs[e * NTOK + r] : g_pairs[e * NTOK];
        prow[tid] = pr;
        toks[tid] = pr >> 1;
    }
    __syncthreads();

    const __nv_bfloat16* wgh = g_wgh + (size_t)e * IDIM * HDIM;
    const __nv_bfloat16* wgl = g_wgl + (size_t)e * IDIM * HDIM;
    const __nv_bfloat16* wuh = g_wuh + (size_t)e * IDIM * HDIM;
    const __nv_bfloat16* wul = g_wul + (size_t)e * IDIM * HDIM;

    int wid = tid >> 5;
    int lane = tid & 31;
    int wm = wid >> 1;
    int wn = wid & 1;
    int g = lane >> 2;
    int q = lane & 3;

    int arow = tid >> 2;            // 0..63
    int achk = (tid & 3) * 8;       // 0/8/16/24 elems

    unsigned offA0 = (unsigned)toks[arow] * HDIM + achk;
    unsigned offA1 = (unsigned)toks[arow + 64] * HDIM + achk;
    unsigned offB  = (unsigned)(n0 + arow) * HDIM + achk;

    float accG[2][4][4], accU[2][4][4];
#pragma unroll
    for (int i = 0; i < 2; i++)
#pragma unroll
        for (int j = 0; j < 4; j++)
#pragma unroll
            for (int c = 0; c < 4; c++) { accG[i][j][c] = 0.f; accU[i][j][c] = 0.f; }

#define GU_LOAD(st, k0)                                            \
    do {                                                           \
        cpa16(&Ah[st][arow][achk],      g_xh + offA0 + (k0));      \
        cpa16(&Ah[st][arow + 64][achk], g_xh + offA1 + (k0));      \
        cpa16(&Al[st][arow][achk],      g_xl + offA0 + (k0));      \
        cpa16(&Al[st][arow + 64][achk], g_xl + offA1 + (k0));      \
        cpa16(&Bgh[st][arow][achk],     wgh + offB + (k0));        \
        cpa16(&Bgl[st][arow][achk],     wgl + offB + (k0));        \
        cpa16(&Buh[st][arow][achk],     wuh + offB + (k0));        \
        cpa16(&Bul[st][arow][achk],     wul + offB + (k0));        \
        cpa_commit();                                              \
    } while (0)

    GU_LOAD(0, 0);

    const int NIT = HDIM / TK;
    for (int it = 0; it < NIT; it++) {
        cpa_wait0();
        __syncthreads();
        if (it + 1 < NIT) GU_LOAD((it + 1) & 1, (it + 1) * TK);
        int st = it & 1;

#pragma unroll
        for (int kk = 0; kk < TK; kk += 16) {
            unsigned aH[2][4], aL[2][4];
#pragma unroll
            for (int mf = 0; mf < 2; mf++) {
                int rm = wm * 32 + mf * 16 + g;
                aH[mf][0] = *(const unsigned*)&Ah[st][rm][kk + 2 * q];
                aH[mf][1] = *(const unsigned*)&Ah[st][rm + 8][kk + 2 * q];
                aH[mf][2] = *(const unsigned*)&Ah[st][rm][kk + 2 * q + 8];
                aH[mf][3] = *(const unsigned*)&Ah[st][rm + 8][kk + 2 * q + 8];
                aL[mf][0] = *(const unsigned*)&Al[st][rm][kk + 2 * q];
                aL[mf][1] = *(const unsigned*)&Al[st][rm + 8][kk + 2 * q];
                aL[mf][2] = *(const unsigned*)&Al[st][rm][kk + 2 * q + 8];
                aL[mf][3] = *(const unsigned*)&Al[st][rm + 8][kk + 2 * q + 8];
            }
#pragma unroll
            for (int nf = 0; nf < 4; nf++) {
                int cn = wn * 32 + nf * 8 + g;
                unsigned bH[2], bL[2];
                bH[0] = *(const unsigned*)&Bgh[st][cn][kk + 2 * q];
                bH[1] = *(const unsigned*)&Bgh[st][cn][kk + 2 * q + 8];
                bL[0] = *(const unsigned*)&Bgl[st][cn][kk + 2 * q];
                bL[1] = *(const unsigned*)&Bgl[st][cn][kk + 2 * q + 8];
#pragma unroll
                for (int mf = 0; mf < 2; mf++) {
                    mma_bf16(accG[mf][nf], aH[mf], bH);
                    mma_bf16(accG[mf][nf], aL[mf], bH);
                    mma_bf16(accG[mf][nf], aH[mf], bL);
                }
            }
#pragma unroll
            for (int nf = 0; nf < 4; nf++) {
                int cn = wn * 32 + nf * 8 + g;
                unsigned bH[2], bL[2];
                bH[0] = *(const unsigned*)&Buh[st][cn][kk + 2 * q];
                bH[1] = *(const unsigned*)&Buh[st][cn][kk + 2 * q + 8];
                bL[0] = *(const unsigned*)&Bul[st][cn][kk + 2 * q];
                bL[1] = *(const unsigned*)&Bul[st][cn][kk + 2 * q + 8];
#pragma unroll
                for (int mf = 0; mf < 2; mf++) {
                    mma_bf16(accU[mf][nf], aH[mf], bH);
                    mma_bf16(accU[mf][nf], aL[mf], bH);
                    mma_bf16(accU[mf][nf], aH[mf], bL);
                }
            }
        }
    }
#undef GU_LOAD

    // epilogue: h = silu(g) * u, pre-split to bf16 hi/lo
#pragma unroll
    for (int mf = 0; mf < 2; mf++) {
#pragma unroll
        for (int half = 0; half < 2; half++) {
            int lr = wm * 32 + mf * 16 + g + half * 8;
            int r = m0 + lr;
            if (r < M) {
                int p = prow[lr];
#pragma unroll
                for (int nf = 0; nf < 4; nf++) {
                    int col = n0 + wn * 32 + nf * 8 + 2 * q;
                    float gv0 = accG[mf][nf][half * 2 + 0];
                    float gv1 = accG[mf][nf][half * 2 + 1];
                    float uv0 = accU[mf][nf][half * 2 + 0];
                    float uv1 = accU[mf][nf][half * 2 + 1];
                    float hx = (gv0 / (1.f + expf(-gv0))) * uv0;
                    float hy = (gv1 / (1.f + expf(-gv1))) * uv1;
                    unsigned hb, lb;
                    bsplit2(hx, hy, hb, lb);
                    *(unsigned*)&g_hbh[(size_t)p * IDIM + col] = hb;
                    *(unsigned*)&g_hbl[(size_t)p * IDIM + col] = lb;
                }
            }
        }
    }
}

// ---------------- down GEMM (cp.async double-buffered) ----------------
__global__ __launch_bounds__(256) void down_kernel() {
    int e = blockIdx.z;
    int M = g_cnt[e];
    int m0 = blockIdx.y * TM;
    if (m0 >= M) return;
    int n0 = blockIdx.x * TN;

    __shared__ __nv_bfloat16 Ah[2][TM][AP], Al[2][TM][AP];
    __shared__ __nv_bfloat16 Bh[2][TN][AP], Bl[2][TN][AP];
    __shared__ int prow[TM];

    int tid = threadIdx.x;
    if (tid < TM) {
        int r = m0 + tid;
        prow[tid] = (r < M) ? g_pairs[e * NTOK + r] : g_pairs[e * NTOK];
    }
    __syncthreads();

    const __nv_bfloat16* wdh = g_wdh + (size_t)e * HDIM * IDIM;
    const __nv_bfloat16* wdl = g_wdl + (size_t)e * HDIM * IDIM;

    int wid = tid >> 5;
    int lane = tid & 31;
    int wm = wid >> 1;
    int wn = wid & 1;
    int g = lane >> 2;
    int q = lane & 3;

    int arow = tid >> 2;
    int achk = (tid & 3) * 8;

    unsigned offA0 = (unsigned)prow[arow] * IDIM + achk;
    unsigned offA1 = (unsigned)prow[arow + 64] * IDIM + achk;
    unsigned offB  = (unsigned)(n0 + arow) * IDIM + achk;

    float acc[2][4][4];
#pragma unroll
    for (int i = 0; i < 2; i++)
#pragma unroll
        for (int j = 0; j < 4; j++)
#pragma unroll
            for (int c = 0; c < 4; c++) acc[i][j][c] = 0.f;

#define DN_LOAD(st, k0)                                            \
    do {                                                           \
        cpa16(&Ah[st][arow][achk],      g_hbh + offA0 + (k0));     \
        cpa16(&Ah[st][arow + 64][achk], g_hbh + offA1 + (k0));     \
        cpa16(&Al[st][arow][achk],      g_hbl + offA0 + (k0));     \
        cpa16(&Al[st][arow + 64][achk], g_hbl + offA1 + (k0));     \
        cpa16(&Bh[st][arow][achk],      wdh + offB + (k0));        \
        cpa16(&Bl[st][arow][achk],      wdl + offB + (k0));        \
        cpa_commit();                                              \
    } while (0)

    DN_LOAD(0, 0);

    const int NIT = IDIM / TK;
    for (int it = 0; it < NIT; it++) {
        cpa_wait0();
        __syncthreads();
        if (it + 1 < NIT) DN_LOAD((it + 1) & 1, (it + 1) * TK);
        int st = it & 1;

#pragma unroll
        for (int kk = 0; kk < TK; kk += 16) {
            unsigned aH[2][4], aL[2][4];
#pragma unroll
            for (int mf = 0; mf < 2; mf++) {
                int rm = wm * 32 + mf * 16 + g;
                aH[mf][0] = *(const unsigned*)&Ah[st][rm][kk + 2 * q];
                aH[mf][1] = *(const unsigned*)&Ah[st][rm + 8][kk + 2 * q];
                aH[mf][2] = *(const unsigned*)&Ah[st][rm][kk + 2 * q + 8];
                aH[mf][3] = *(const unsigned*)&Ah[st][rm + 8][kk + 2 * q + 8];
                aL[mf][0] = *(const unsigned*)&Al[st][rm][kk + 2 * q];
                aL[mf][1] = *(const unsigned*)&Al[st][rm + 8][kk + 2 * q];
                aL[mf][2] = *(const unsigned*)&Al[st][rm][kk + 2 * q + 8];
                aL[mf][3] = *(const unsigned*)&Al[st][rm + 8][kk + 2 * q + 8];
            }
#pragma unroll
            for (int nf = 0; nf < 4; nf++) {
                int cn = wn * 32 + nf * 8 + g;
                unsigned bH[2], bL[2];
                bH[0] = *(const unsigned*)&Bh[st][cn][kk + 2 * q];
                bH[1] = *(const unsigned*)&Bh[st][cn][kk + 2 * q + 8];
                bL[0] = *(const unsigned*)&Bl[st][cn][kk + 2 * q];
                bL[1] = *(const unsigned*)&Bl[st][cn][kk + 2 * q + 8];
#pragma unroll
                for (int mf = 0; mf < 2; mf++) {
                    mma_bf16(acc[mf][nf], aH[mf], bH);
                    mma_bf16(acc[mf][nf], aL[mf], bH);
                    mma_bf16(acc[mf][nf], aH[mf], bL);
                }
            }
        }
    }
#undef DN_LOAD

#pragma unroll
    for (int mf = 0; mf < 2; mf++) {
#pragma unroll
        for (int half = 0; half < 2; half++) {
            int lr = wm * 32 + mf * 16 + g + half * 8;
            int r = m0 + lr;
            if (r < M) {
                int p = prow[lr];
#pragma unroll
                for (int nf = 0; nf < 4; nf++) {
                    int col = n0 + wn * 32 + nf * 8 + 2 * q;
                    float2 o;
                    o.x = acc[mf][nf][half * 2 + 0];
                    o.y = acc[mf][nf][half * 2 + 1];
                    *(float2*)&g_ybuf[(size_t)p * HDIM + col] = o;
                }
            }
        }
    }
}

// ---------------- combine ----------------
__global__ void combine_kernel(float* __restrict__ y) {
    int idx = blockIdx.x * blockDim.x + threadIdx.x;
    int t = idx / (HDIM / 4);
    int h4 = (idx - t * (HDIM / 4)) * 4;
    float w0 = g_tokw[2 * t], w1 = g_tokw[2 * t + 1];
    float4 a = *(const float4*)&g_ybuf[(size_t)(2 * t) * HDIM + h4];
    float4 b = *(const float4*)&g_ybuf[(size_t)(2 * t + 1) * HDIM + h4];
    float4 r;
    r.x = w0 * a.x + w1 * b.x;
    r.y = w0 * a.y + w1 * b.y;
    r.z = w0 * a.z + w1 * b.z;
    r.w = w0 * a.w + w1 * b.w;
    *(float4*)&y[(size_t)t * HDIM + h4] = r;
}

// ---------------- launch ----------------
extern "C" void kernel_launch(void* const* d_in, const int* in_sizes, int n_in,
                              void* d_out, int out_size) {
    const float* x  = (const float*)d_in[0];
    const float* gw = (const float*)d_in[1];
    const float* wg = (const float*)d_in[2];
    const float* wu = (const float*)d_in[3];
    const float* wd = (const float*)d_in[4];
    float* y = (float*)d_out;

    reset_kernel<<<1, 32>>>();
    router_kernel<<<NTOK / 8, 256>>>(x, gw);
    aux_kernel<<<1, 256>>>(y + (out_size - 1));

    split_x_kernel<<<(NTOK * HDIM / 4) / 256, 256>>>(x);
    transpose_split_kernel<0><<<dim3(IDIM / 32, HDIM / 32, EEXP), 256>>>(wg, HDIM, IDIM);
    transpose_split_kernel<1><<<dim3(IDIM / 32, HDIM / 32, EEXP), 256>>>(wu, HDIM, IDIM);
    transpose_split_kernel<2><<<dim3(HDIM / 32, IDIM / 32, EEXP), 256>>>(wd, IDIM, HDIM);

    gateup_kernel<<<dim3(IDIM / TN, (NTOK * 2) / TM, EEXP), 256>>>();
    down_kernel<<<dim3(HDIM / TN, (NTOK * 2) / TM, EEXP), 256>>>();
    combine_kernel<<<(NTOK * HDIM / 4) / 256, 256>>>(y);
}

// round 6
// speedup vs baseline: 2.2303x; 1.1758x over previous
#include <cuda_runtime.h>
#include <cuda_bf16.h>
#include <math.h>

// Problem constants (fixed by setup_inputs)
#define NTOK 8192      // B*S
#define HDIM 1024
#define IDIM 2048
#define EEXP 8
#define TOPK 2

// GEMM tiling
#define TM 128
#define TN 64
#define TK 32
#define AP 40          // padded k-row length (bf16): 80B stride, conflict-free LDSM

// ---------------- device scratch ----------------
__device__ int   g_cnt[EEXP];
__device__ int   g_pairs[EEXP * NTOK];
__device__ float g_tokw[NTOK * 2];
__device__ int   g_toke[NTOK * 2];
__device__ float g_selw[NTOK * 2];

// pre-split operands (bf16 hi/lo)
__device__ __nv_bfloat16 g_xh[NTOK * HDIM];
__device__ __nv_bfloat16 g_xl[NTOK * HDIM];
__device__ __nv_bfloat16 g_wgh[EEXP * IDIM * HDIM];  // gate, transposed [e][i][h]
__device__ __nv_bfloat16 g_wgl[EEXP * IDIM * HDIM];
__device__ __nv_bfloat16 g_wuh[EEXP * IDIM * HDIM];  // up, transposed [e][i][h]
__device__ __nv_bfloat16 g_wul[EEXP * IDIM * HDIM];
__device__ __nv_bfloat16 g_wdh[EEXP * HDIM * IDIM];  // down, transposed [e][h][i]
__device__ __nv_bfloat16 g_wdl[EEXP * HDIM * IDIM];
__device__ __nv_bfloat16 g_hbh[NTOK * 2 * IDIM];     // silu(g)*u hi  [pair][I]
__device__ __nv_bfloat16 g_hbl[NTOK * 2 * IDIM];     // silu(g)*u lo
__device__ float g_ybuf[NTOK * 2 * HDIM];            // expert outputs [pair][H]

// ---------------- helpers ----------------
__device__ __forceinline__ void bsplit2(float a, float b, unsigned &hi, unsigned &lo) {
    __nv_bfloat162 h = __floats2bfloat162_rn(a, b);
    float lx = a - __bfloat162float(__low2bfloat16(h));
    float ly = b - __bfloat162float(__high2bfloat16(h));
    __nv_bfloat162 l = __floats2bfloat162_rn(lx, ly);
    hi = *reinterpret_cast<unsigned*>(&h);
    lo = *reinterpret_cast<unsigned*>(&l);
}

__device__ __forceinline__ void mma_bf16(float *d, const unsigned *a, const unsigned *b) {
    asm volatile("mma.sync.aligned.m16n8k16.row.col.f32.bf16.bf16.f32 "
        "{%0,%1,%2,%3}, {%4,%5,%6,%7}, {%8,%9}, {%0,%1,%2,%3};\n"
        : "+f"(d[0]), "+f"(d[1]), "+f"(d[2]), "+f"(d[3])
        : "r"(a[0]), "r"(a[1]), "r"(a[2]), "r"(a[3]), "r"(b[0]), "r"(b[1]));
}

__device__ __forceinline__ void ldsm4(unsigned &r0, unsigned &r1, unsigned &r2, unsigned &r3,
                                      unsigned a) {
    asm volatile("ldmatrix.sync.aligned.m8n8.x4.shared.b16 {%0,%1,%2,%3}, [%4];\n"
        : "=r"(r0), "=r"(r1), "=r"(r2), "=r"(r3) : "r"(a));
}

__device__ __forceinline__ void cpa16(void* smem, const void* g) {
    unsigned s = (unsigned)__cvta_generic_to_shared(smem);
    asm volatile("cp.async.cg.shared.global [%0], [%1], 16;\n" :: "r"(s), "l"(g));
}
__device__ __forceinline__ void cpa_commit() {
    asm volatile("cp.async.commit_group;\n");
}
__device__ __forceinline__ void cpa_wait0() {
    asm volatile("cp.async.wait_group 0;\n");
}

// ---------------- reset ----------------
__global__ void reset_kernel() {
    if (threadIdx.x < EEXP) g_cnt[threadIdx.x] = 0;
}

// ---------------- split x into bf16 hi/lo ----------------
__global__ void split_x_kernel(const float* __restrict__ x) {
    int idx = blockIdx.x * blockDim.x + threadIdx.x;
    float4 v = ((const float4*)x)[idx];
    unsigned h0, l0, h1, l1;
    bsplit2(v.x, v.y, h0, l0);
    bsplit2(v.z, v.w, h1, l1);
    uint2 hh; hh.x = h0; hh.y = h1;
    uint2 ll; ll.x = l0; ll.y = l1;
    ((uint2*)g_xh)[idx] = hh;
    ((uint2*)g_xl)[idx] = ll;
}

// ---------------- transpose+split weights: src [E][R][C] -> dst [E][C][R] ----------------
// W selects destinations IN DEVICE CODE (never pass __device__ globals as host-side
// kernel args: that passes the host shadow symbol; ATS dereferences host memory).
template<int W>
__global__ void transpose_split_kernel(const float* __restrict__ src, int R, int C) {
    __nv_bfloat16* dh = (W == 0) ? g_wgh : (W == 1) ? g_wuh : g_wdh;
    __nv_bfloat16* dl = (W == 0) ? g_wgl : (W == 1) ? g_wul : g_wdl;
    __shared__ float s[32][33];
    int e = blockIdx.z;
    int r0 = blockIdx.y * 32, c0 = blockIdx.x * 32;
    int tx = threadIdx.x & 31, ty = threadIdx.x >> 5;
    const float* sp = src + ((size_t)e * R + r0) * C + c0;
#pragma unroll
    for (int j = 0; j < 4; j++)
        s[ty + j * 8][tx] = sp[(size_t)(ty + j * 8) * C + tx];
    __syncthreads();
    size_t dbase = ((size_t)e * C + c0) * R + r0;
#pragma unroll
    for (int j = 0; j < 4; j++) {
        float v = s[tx][ty + j * 8];
        __nv_bfloat16 h = __float2bfloat16(v);
        __nv_bfloat16 l = __float2bfloat16(v - __bfloat162float(h));
        dh[dbase + (size_t)(ty + j * 8) * R + tx] = h;
        dl[dbase + (size_t)(ty + j * 8) * R + tx] = l;
    }
}

// ---------------- router: one warp per token ----------------
__global__ void router_kernel(const float* __restrict__ x,
                              const float* __restrict__ gw) {
    int t = blockIdx.x * (blockDim.x >> 5) + (threadIdx.x >> 5);
    int lane = threadIdx.x & 31;
    if (t >= NTOK) return;
    const float* xr = x + (size_t)t * HDIM;
    float acc[EEXP];
#pragma unroll
    for (int e = 0; e < EEXP; e++) acc[e] = 0.f;
    for (int h = lane; h < HDIM; h += 32) {
        float xv = xr[h];
        const float* g = gw + h * EEXP;
#pragma unroll
        for (int e = 0; e < EEXP; e++) acc[e] = fmaf(xv, g[e], acc[e]);
    }
#pragma unroll
    for (int off = 16; off > 0; off >>= 1) {
#pragma unroll
        for (int e = 0; e < EEXP; e++)
            acc[e] += __shfl_down_sync(0xffffffffu, acc[e], off);
    }
    if (lane == 0) {
        float mx = acc[0];
#pragma unroll
        for (int e = 1; e < EEXP; e++) mx = fmaxf(mx, acc[e]);
        float p[EEXP];
        float s = 0.f;
#pragma unroll
        for (int e = 0; e < EEXP; e++) { p[e] = expf(acc[e] - mx); s += p[e]; }
        float inv = 1.f / s;
#pragma unroll
        for (int e = 0; e < EEXP; e++) p[e] *= inv;
        int e0 = 0;
#pragma unroll
        for (int e = 1; e < EEXP; e++) if (p[e] > p[e0]) e0 = e;
        int e1 = (e0 == 0) ? 1 : 0;
#pragma unroll
        for (int e = 0; e < EEXP; e++) if (e != e0 && p[e] > p[e1]) e1 = e;
        float w0 = p[e0], w1 = p[e1];
        float rs = 1.f / (w0 + w1);
        g_toke[2 * t] = e0;      g_toke[2 * t + 1] = e1;
        g_selw[2 * t] = w0;      g_selw[2 * t + 1] = w1;
        g_tokw[2 * t] = w0 * rs; g_tokw[2 * t + 1] = w1 * rs;
        int p0 = atomicAdd(&g_cnt[e0], 1);
        g_pairs[e0 * NTOK + p0] = 2 * t;
        int p1 = atomicAdd(&g_cnt[e1], 1);
        g_pairs[e1 * NTOK + p1] = 2 * t + 1;
    }
}

// ---------------- aux loss ----------------
__global__ void aux_kernel(float* __restrict__ out_aux) {
    __shared__ float sload[256][EEXP];
    int tid = threadIdx.x;
    float l[EEXP];
#pragma unroll
    for (int e = 0; e < EEXP; e++) l[e] = 0.f;
    for (int a = tid; a < NTOK * 2; a += 256)
        l[g_toke[a]] += g_selw[a];
#pragma unroll
    for (int e = 0; e < EEXP; e++) sload[tid][e] = l[e];
    __syncthreads();
    for (int s = 128; s > 0; s >>= 1) {
        if (tid < s) {
#pragma unroll
            for (int e = 0; e < EEXP; e++) sload[tid][e] += sload[tid + s][e];
        }
        __syncthreads();
    }
    if (tid == 0) {
        float aux = 0.f;
#pragma unroll
        for (int e = 0; e < EEXP; e++) {
            float pe = sload[0][e] / (float)NTOK;
            float pt = (float)g_cnt[e] / (float)(NTOK * TOPK);
            aux += pe * pt;
        }
        aux *= (float)EEXP * 1e-3f;
        *out_aux = aux;
    }
}

// ---------------- gate+up GEMM (bf16-split, ldmatrix + cp.async) ----------------
__global__ __launch_bounds__(256) void gateup_kernel() {
    int e = blockIdx.z;
    int M = g_cnt[e];
    int m0 = blockIdx.y * TM;
    if (m0 >= M) return;
    int n0 = blockIdx.x * TN;

    __shared__ __nv_bfloat16 Ah[2][TM][AP], Al[2][TM][AP];
    __shared__ __nv_bfloat16 Bgh[2][TN][AP], Bgl[2][TN][AP], Buh[2][TN][AP], Bul[2][TN][AP];
    __shared__ int prow[TM];
    __shared__ int toks[TM];

    int tid = threadIdx.x;
    if (tid < TM) {
        int r = m0 + tid;
        int pr = (r < M) ? g_pairs[e * NTOK + r] : g_pairs[e * NTOK];
        prow[tid] = pr;
        toks[tid] = pr >> 1;
    }
    __syncthreads();

    const __nv_bfloat16* wgh = g_wgh + (size_t)e * IDIM * HDIM;
    const __nv_bfloat16* wgl = g_wgl + (size_t)e * IDIM * HDIM;
    const __nv_bfloat16* wuh = g_wuh + (size_t)e * IDIM * HDIM;
    const __nv_bfloat16* wul = g_wul + (size_t)e * IDIM * HDIM;

    int wid = tid >> 5;
    int lane = tid & 31;
    int wm = wid >> 1;
    int wn = wid & 1;
    int g = lane >> 2;
    int q = lane & 3;

    int arow = tid >> 2;            // 0..63
    int achk = (tid & 3) * 8;

    unsigned offA0 = (unsigned)toks[arow] * HDIM + achk;
    unsigned offA1 = (unsigned)toks[arow + 64] * HDIM + achk;
    unsigned offB  = (unsigned)(n0 + arow) * HDIM + achk;

    // ldmatrix per-lane byte offsets within one stage's [rows][AP] buffer
    // A (m16x16 x4): lanes 0-15 -> rows 0-15 col kk; 16-31 -> rows 0-15 col kk+8
    unsigned aoff[2];
#pragma unroll
    for (int mf = 0; mf < 2; mf++)
        aoff[mf] = ((wm * 32 + mf * 16 + (lane & 15)) * AP + ((lane >> 4) << 3)) * 2;
    // B (two 8-row n-tiles x4): matrices 0,1 = nf even (cols kk, kk+8); 2,3 = nf odd
    unsigned boff[2];
#pragma unroll
    for (int nfp = 0; nfp < 2; nfp++)
        boff[nfp] = ((wn * 32 + nfp * 16 + ((lane >> 4) << 3) + (lane & 7)) * AP
                     + (((lane >> 3) & 1) << 3)) * 2;

    unsigned sAh = (unsigned)__cvta_generic_to_shared(&Ah[0][0][0]);
    unsigned sAl = (unsigned)__cvta_generic_to_shared(&Al[0][0][0]);
    unsigned sBgh = (unsigned)__cvta_generic_to_shared(&Bgh[0][0][0]);
    unsigned sBgl = (unsigned)__cvta_generic_to_shared(&Bgl[0][0][0]);
    unsigned sBuh = (unsigned)__cvta_generic_to_shared(&Buh[0][0][0]);
    unsigned sBul = (unsigned)__cvta_generic_to_shared(&Bul[0][0][0]);
    const unsigned strA = TM * AP * 2;
    const unsigned strB = TN * AP * 2;

    float accG[2][4][4], accU[2][4][4];
#pragma unroll
    for (int i = 0; i < 2; i++)
#pragma unroll
        for (int j = 0; j < 4; j++)
#pragma unroll
            for (int c = 0; c < 4; c++) { accG[i][j][c] = 0.f; accU[i][j][c] = 0.f; }

#define GU_LOAD(st, k0)                                            \
    do {                                                           \
        cpa16(&Ah[st][arow][achk],      g_xh + offA0 + (k0));      \
        cpa16(&Ah[st][arow + 64][achk], g_xh + offA1 + (k0));      \
        cpa16(&Al[st][arow][achk],      g_xl + offA0 + (k0));      \
        cpa16(&Al[st][arow + 64][achk], g_xl + offA1 + (k0));      \
        cpa16(&Bgh[st][arow][achk],     wgh + offB + (k0));        \
        cpa16(&Bgl[st][arow][achk],     wgl + offB + (k0));        \
        cpa16(&Buh[st][arow][achk],     wuh + offB + (k0));        \
        cpa16(&Bul[st][arow][achk],     wul + offB + (k0));        \
        cpa_commit();                                              \
    } while (0)

    GU_LOAD(0, 0);

    const int NIT = HDIM / TK;
    for (int it = 0; it < NIT; it++) {
        cpa_wait0();
        __syncthreads();
        if (it + 1 < NIT) GU_LOAD((it + 1) & 1, (it + 1) * TK);
        unsigned stA = (it & 1) * strA;
        unsigned stB = (it & 1) * strB;

#pragma unroll
        for (int kk = 0; kk < TK; kk += 16) {
            unsigned aH[2][4], aL[2][4];
#pragma unroll
            for (int mf = 0; mf < 2; mf++) {
                ldsm4(aH[mf][0], aH[mf][1], aH[mf][2], aH[mf][3], sAh + stA + aoff[mf] + kk * 2);
                ldsm4(aL[mf][0], aL[mf][1], aL[mf][2], aL[mf][3], sAl + stA + aoff[mf] + kk * 2);
            }
#pragma unroll
            for (int nfp = 0; nfp < 2; nfp++) {
                unsigned bH[4], bL[4];
                ldsm4(bH[0], bH[1], bH[2], bH[3], sBgh + stB + boff[nfp] + kk * 2);
                ldsm4(bL[0], bL[1], bL[2], bL[3], sBgl + stB + boff[nfp] + kk * 2);
#pragma unroll
                for (int h2 = 0; h2 < 2; h2++) {
                    int nf = nfp * 2 + h2;
#pragma unroll
                    for (int mf = 0; mf < 2; mf++) {
                        mma_bf16(accG[mf][nf], aH[mf], &bH[h2 * 2]);
                        mma_bf16(accG[mf][nf], aL[mf], &bH[h2 * 2]);
                        mma_bf16(accG[mf][nf], aH[mf], &bL[h2 * 2]);
                    }
                }
            }
#pragma unroll
            for (int nfp = 0; nfp < 2; nfp++) {
                unsigned bH[4], bL[4];
                ldsm4(bH[0], bH[1], bH[2], bH[3], sBuh + stB + boff[nfp] + kk * 2);
                ldsm4(bL[0], bL[1], bL[2], bL[3], sBul + stB + boff[nfp] + kk * 2);
#pragma unroll
                for (int h2 = 0; h2 < 2; h2++) {
                    int nf = nfp * 2 + h2;
#pragma unroll
                    for (int mf = 0; mf < 2; mf++) {
                        mma_bf16(accU[mf][nf], aH[mf], &bH[h2 * 2]);
                        mma_bf16(accU[mf][nf], aL[mf], &bH[h2 * 2]);
                        mma_bf16(accU[mf][nf], aH[mf], &bL[h2 * 2]);
                    }
                }
            }
        }
    }
#undef GU_LOAD

    // epilogue: h = silu(g) * u, pre-split to bf16 hi/lo
#pragma unroll
    for (int mf = 0; mf < 2; mf++) {
#pragma unroll
        for (int half = 0; half < 2; half++) {
            int lr = wm * 32 + mf * 16 + g + half * 8;
            int r = m0 + lr;
            if (r < M) {
                int p = prow[lr];
#pragma unroll
                for (int nf = 0; nf < 4; nf++) {
                    int col = n0 + wn * 32 + nf * 8 + 2 * q;
                    float gv0 = accG[mf][nf][half * 2 + 0];
                    float gv1 = accG[mf][nf][half * 2 + 1];
                    float uv0 = accU[mf][nf][half * 2 + 0];
                    float uv1 = accU[mf][nf][half * 2 + 1];
                    float hx = (gv0 / (1.f + expf(-gv0))) * uv0;
                    float hy = (gv1 / (1.f + expf(-gv1))) * uv1;
                    unsigned hb, lb;
                    bsplit2(hx, hy, hb, lb);
                    *(unsigned*)&g_hbh[(size_t)p * IDIM + col] = hb;
                    *(unsigned*)&g_hbl[(size_t)p * IDIM + col] = lb;
                }
            }
        }
    }
}

// ---------------- down GEMM (bf16-split, ldmatrix + cp.async) ----------------
__global__ __launch_bounds__(256) void down_kernel() {
    int e = blockIdx.z;
    int M = g_cnt[e];
    int m0 = blockIdx.y * TM;
    if (m0 >= M) return;
    int n0 = blockIdx.x * TN;

    __shared__ __nv_bfloat16 Ah[2][TM][AP], Al[2][TM][AP];
    __shared__ __nv_bfloat16 Bh[2][TN][AP], Bl[2][TN][AP];
    __shared__ int prow[TM];

    int tid = threadIdx.x;
    if (tid < TM) {
        int r = m0 + tid;
        prow[tid] = (r < M) ? g_pairs[e * NTOK + r] : g_pairs[e * NTOK];
    }
    __syncthreads();

    const __nv_bfloat16* wdh = g_wdh + (size_t)e * HDIM * IDIM;
    const __nv_bfloat16* wdl = g_wdl + (size_t)e * HDIM * IDIM;

    int wid = tid >> 5;
    int lane = tid & 31;
    int wm = wid >> 1;
    int wn = wid & 1;
    int g = lane >> 2;
    int q = lane & 3;

    int arow = tid >> 2;
    int achk = (tid & 3) * 8;

    unsigned offA0 = (unsigned)prow[arow] * IDIM + achk;
    unsigned offA1 = (unsigned)prow[arow + 64] * IDIM + achk;
    unsigned offB  = (unsigned)(n0 + arow) * IDIM + achk;

    unsigned aoff[2];
#pragma unroll
    for (int mf = 0; mf < 2; mf++)
        aoff[mf] = ((wm * 32 + mf * 16 + (lane & 15)) * AP + ((lane >> 4) << 3)) * 2;
    unsigned boff[2];
#pragma unroll
    for (int nfp = 0; nfp < 2; nfp++)
        boff[nfp] = ((wn * 32 + nfp * 16 + ((lane >> 4) << 3) + (lane & 7)) * AP
                     + (((lane >> 3) & 1) << 3)) * 2;

    unsigned sAh = (unsigned)__cvta_generic_to_shared(&Ah[0][0][0]);
    unsigned sAl = (unsigned)__cvta_generic_to_shared(&Al[0][0][0]);
    unsigned sBh = (unsigned)__cvta_generic_to_shared(&Bh[0][0][0]);
    unsigned sBl = (unsigned)__cvta_generic_to_shared(&Bl[0][0][0]);
    const unsigned strA = TM * AP * 2;
    const unsigned strB = TN * AP * 2;

    float acc[2][4][4];
#pragma unroll
    for (int i = 0; i < 2; i++)
#pragma unroll
        for (int j = 0; j < 4; j++)
#pragma unroll
            for (int c = 0; c < 4; c++) acc[i][j][c] = 0.f;

#define DN_LOAD(st, k0)                                            \
    do {                                                           \
        cpa16(&Ah[st][arow][achk],      g_hbh + offA0 + (k0));     \
        cpa16(&Ah[st][arow + 64][achk], g_hbh + offA1 + (k0));     \
        cpa16(&Al[st][arow][achk],      g_hbl + offA0 + (k0));     \
        cpa16(&Al[st][arow + 64][achk], g_hbl + offA1 + (k0));     \
        cpa16(&Bh[st][arow][achk],      wdh + offB + (k0));        \
        cpa16(&Bl[st][arow][achk],      wdl + offB + (k0));        \
        cpa_commit();                                              \
    } while (0)

    DN_LOAD(0, 0);

    const int NIT = IDIM / TK;
    for (int it = 0; it < NIT; it++) {
        cpa_wait0();
        __syncthreads();
        if (it + 1 < NIT) DN_LOAD((it + 1) & 1, (it + 1) * TK);
        unsigned stA = (it & 1) * strA;
        unsigned stB = (it & 1) * strB;

#pragma unroll
        for (int kk = 0; kk < TK; kk += 16) {
            unsigned aH[2][4], aL[2][4];
#pragma unroll
            for (int mf = 0; mf < 2; mf++) {
                ldsm4(aH[mf][0], aH[mf][1], aH[mf][2], aH[mf][3], sAh + stA + aoff[mf] + kk * 2);
                ldsm4(aL[mf][0], aL[mf][1], aL[mf][2], aL[mf][3], sAl + stA + aoff[mf] + kk * 2);
            }
#pragma unroll
            for (int nfp = 0; nfp < 2; nfp++) {
                unsigned bH[4], bL[4];
                ldsm4(bH[0], bH[1], bH[2], bH[3], sBh + stB + boff[nfp] + kk * 2);
                ldsm4(bL[0], bL[1], bL[2], bL[3], sBl + stB + boff[nfp] + kk * 2);
#pragma unroll
                for (int h2 = 0; h2 < 2; h2++) {
                    int nf = nfp * 2 + h2;
#pragma unroll
                    for (int mf = 0; mf < 2; mf++) {
                        mma_bf16(acc[mf][nf], aH[mf], &bH[h2 * 2]);
                        mma_bf16(acc[mf][nf], aL[mf], &bH[h2 * 2]);
                        mma_bf16(acc[mf][nf], aH[mf], &bL[h2 * 2]);
                    }
                }
            }
        }
    }
#undef DN_LOAD

#pragma unroll
    for (int mf = 0; mf < 2; mf++) {
#pragma unroll
        for (int half = 0; half < 2; half++) {
            int lr = wm * 32 + mf * 16 + g + half * 8;
            int r = m0 + lr;
            if (r < M) {
                int p = prow[lr];
#pragma unroll
                for (int nf = 0; nf < 4; nf++) {
                    int col = n0 + wn * 32 + nf * 8 + 2 * q;
                    float2 o;
                    o.x = acc[mf][nf][half * 2 + 0];
                    o.y = acc[mf][nf][half * 2 + 1];
                    *(float2*)&g_ybuf[(size_t)p * HDIM + col] = o;
                }
            }
        }
    }
}

// ---------------- combine ----------------
__global__ void combine_kernel(float* __restrict__ y) {
    int idx = blockIdx.x * blockDim.x + threadIdx.x;
    int t = idx / (HDIM / 4);
    int h4 = (idx - t * (HDIM / 4)) * 4;
    float w0 = g_tokw[2 * t], w1 = g_tokw[2 * t + 1];
    float4 a = *(const float4*)&g_ybuf[(size_t)(2 * t) * HDIM + h4];
    float4 b = *(const float4*)&g_ybuf[(size_t)(2 * t + 1) * HDIM + h4];
    float4 r;
    r.x = w0 * a.x + w1 * b.x;
    r.y = w0 * a.y + w1 * b.y;
    r.z = w0 * a.z + w1 * b.z;
    r.w = w0 * a.w + w1 * b.w;
    *(float4*)&y[(size_t)t * HDIM + h4] = r;
}

// ---------------- launch ----------------
extern "C" void kernel_launch(void* const* d_in, const int* in_sizes, int n_in,
                              void* d_out, int out_size) {
    const float* x  = (const float*)d_in[0];
    const float* gw = (const float*)d_in[1];
    const float* wg = (const float*)d_in[2];
    const float* wu = (const float*)d_in[3];
    const float* wd = (const float*)d_in[4];
    float* y = (float*)d_out;

    reset_kernel<<<1, 32>>>();
    router_kernel<<<NTOK / 8, 256>>>(x, gw);
    aux_kernel<<<1, 256>>>(y + (out_size - 1));

    split_x_kernel<<<(NTOK * HDIM / 4) / 256, 256>>>(x);
    transpose_split_kernel<0><<<dim3(IDIM / 32, HDIM / 32, EEXP), 256>>>(wg, HDIM, IDIM);
    transpose_split_kernel<1><<<dim3(IDIM / 32, HDIM / 32, EEXP), 256>>>(wu, HDIM, IDIM);
    transpose_split_kernel<2><<<dim3(HDIM / 32, IDIM / 32, EEXP), 256>>>(wd, IDIM, HDIM);

    gateup_kernel<<<dim3(IDIM / TN, (NTOK * 2) / TM, EEXP), 256>>>();
    down_kernel<<<dim3(HDIM / TN, (NTOK * 2) / TM, EEXP), 256>>>();
    combine_kernel<<<(NTOK * HDIM / 4) / 256, 256>>>(y);
}

// round 8
// speedup vs baseline: 2.6470x; 1.1868x over previous
#include <cuda_runtime.h>
#include <cuda_fp16.h>
#include <math.h>

// Problem constants (fixed by setup_inputs)
#define NTOK 8192      // B*S
#define HDIM 1024
#define IDIM 2048
#define EEXP 8
#define TOPK 2

// GEMM tiling
#define TM 128
#define TN 64
#define TK 32
#define AP 40          // padded k-row length (fp16): 80B stride, conflict-free LDSM

// ---------------- device scratch ----------------
__device__ int   g_cnt[EEXP];
__device__ int   g_pairs[EEXP * NTOK];
__device__ float g_tokw[NTOK * 2];
__device__ int   g_toke[NTOK * 2];
__device__ float g_selw[NTOK * 2];

// activations: exact fp16 hi/lo split; weights: single-rounded fp16
__device__ __half g_xh[NTOK * HDIM];
__device__ __half g_xl[NTOK * HDIM];
__device__ __half g_wg[EEXP * IDIM * HDIM];   // gate, transposed [e][i][h]
__device__ __half g_wu[EEXP * IDIM * HDIM];   // up, transposed [e][i][h]
__device__ __half g_wd[EEXP * HDIM * IDIM];   // down, transposed [e][h][i]
__device__ __half g_hbh[NTOK * 2 * IDIM];     // silu(g)*u hi  [pair][I]
__device__ __half g_hbl[NTOK * 2 * IDIM];     // silu(g)*u lo
__device__ float g_ybuf[NTOK * 2 * HDIM];     // expert outputs [pair][H]

// ---------------- helpers ----------------
__device__ __forceinline__ void hsplit2(float a, float b, unsigned &hi, unsigned &lo) {
    __half2 h = __floats2half2_rn(a, b);
    float lx = a - __half2float(__low2half(h));
    float ly = b - __half2float(__high2half(h));
    __half2 l = __floats2half2_rn(lx, ly);
    hi = *reinterpret_cast<unsigned*>(&h);
    lo = *reinterpret_cast<unsigned*>(&l);
}

__device__ __forceinline__ void mma_f16(float *d, const unsigned *a, const unsigned *b) {
    asm volatile("mma.sync.aligned.m16n8k16.row.col.f32.f16.f16.f32 "
        "{%0,%1,%2,%3}, {%4,%5,%6,%7}, {%8,%9}, {%0,%1,%2,%3};\n"
        : "+f"(d[0]), "+f"(d[1]), "+f"(d[2]), "+f"(d[3])
        : "r"(a[0]), "r"(a[1]), "r"(a[2]), "r"(a[3]), "r"(b[0]), "r"(b[1]));
}

__device__ __forceinline__ void ldsm4(unsigned &r0, unsigned &r1, unsigned &r2, unsigned &r3,
                                      unsigned a) {
    asm volatile("ldmatrix.sync.aligned.m8n8.x4.shared.b16 {%0,%1,%2,%3}, [%4];\n"
        : "=r"(r0), "=r"(r1), "=r"(r2), "=r"(r3) : "r"(a));
}

__device__ __forceinline__ void cpa16(void* smem, const void* g) {
    unsigned s = (unsigned)__cvta_generic_to_shared(smem);
    asm volatile("cp.async.cg.shared.global [%0], [%1], 16;\n" :: "r"(s), "l"(g));
}
__device__ __forceinline__ void cpa_commit() {
    asm volatile("cp.async.commit_group;\n");
}
__device__ __forceinline__ void cpa_wait0() {
    asm volatile("cp.async.wait_group 0;\n");
}

// ---------------- reset ----------------
__global__ void reset_kernel() {
    if (threadIdx.x < EEXP) g_cnt[threadIdx.x] = 0;
}

// ---------------- split x into fp16 hi/lo ----------------
__global__ void split_x_kernel(const float* __restrict__ x) {
    int idx = blockIdx.x * blockDim.x + threadIdx.x;
    float4 v = ((const float4*)x)[idx];
    unsigned h0, l0, h1, l1;
    hsplit2(v.x, v.y, h0, l0);
    hsplit2(v.z, v.w, h1, l1);
    uint2 hh; hh.x = h0; hh.y = h1;
    uint2 ll; ll.x = l0; ll.y = l1;
    ((uint2*)g_xh)[idx] = hh;
    ((uint2*)g_xl)[idx] = ll;
}

// ---------------- transpose weights to fp16: src [E][R][C] -> dst [E][C][R] ----------------
// W selects destinations IN DEVICE CODE (never pass __device__ globals from host:
// that passes the host shadow symbol; ATS silently dereferences host memory).
template<int W>
__global__ void transpose_half_kernel(const float* __restrict__ src, int R, int C) {
    __half* dh = (W == 0) ? g_wg : (W == 1) ? g_wu : g_wd;
    __shared__ float s[32][33];
    int e = blockIdx.z;
    int r0 = blockIdx.y * 32, c0 = blockIdx.x * 32;
    int tx = threadIdx.x & 31, ty = threadIdx.x >> 5;
    const float* sp = src + ((size_t)e * R + r0) * C + c0;
#pragma unroll
    for (int j = 0; j < 4; j++)
        s[ty + j * 8][tx] = sp[(size_t)(ty + j * 8) * C + tx];
    __syncthreads();
    size_t dbase = ((size_t)e * C + c0) * R + r0;
#pragma unroll
    for (int j = 0; j < 4; j++)
        dh[dbase + (size_t)(ty + j * 8) * R + tx] = __float2half(s[tx][ty + j * 8]);
}

// ---------------- router: one warp per token ----------------
__global__ void router_kernel(const float* __restrict__ x,
                              const float* __restrict__ gw) {
    int t = blockIdx.x * (blockDim.x >> 5) + (threadIdx.x >> 5);
    int lane = threadIdx.x & 31;
    if (t >= NTOK) return;
    const float* xr = x + (size_t)t * HDIM;
    float acc[EEXP];
#pragma unroll
    for (int e = 0; e < EEXP; e++) acc[e] = 0.f;
    for (int h = lane; h < HDIM; h += 32) {
        float xv = xr[h];
        const float* g = gw + h * EEXP;
#pragma unroll
        for (int e = 0; e < EEXP; e++) acc[e] = fmaf(xv, g[e], acc[e]);
    }
#pragma unroll
    for (int off = 16; off > 0; off >>= 1) {
#pragma unroll
        for (int e = 0; e < EEXP; e++)
            acc[e] += __shfl_down_sync(0xffffffffu, acc[e], off);
    }
    if (lane == 0) {
        float mx = acc[0];
#pragma unroll
        for (int e = 1; e < EEXP; e++) mx = fmaxf(mx, acc[e]);
        float p[EEXP];
        float s = 0.f;
#pragma unroll
        for (int e = 0; e < EEXP; e++) { p[e] = expf(acc[e] - mx); s += p[e]; }
        float inv = 1.f / s;
#pragma unroll
        for (int e = 0; e < EEXP; e++) p[e] *= inv;
        int e0 = 0;
#pragma unroll
        for (int e = 1; e < EEXP; e++) if (p[e] > p[e0]) e0 = e;
        int e1 = (e0 == 0) ? 1 : 0;
#pragma unroll
        for (int e = 0; e < EEXP; e++) if (e != e0 && p[e] > p[e1]) e1 = e;
        float w0 = p[e0], w1 = p[e1];
        float rs = 1.f / (w0 + w1);
        g_toke[2 * t] = e0;      g_toke[2 * t + 1] = e1;
        g_selw[2 * t] = w0;      g_selw[2 * t + 1] = w1;
        g_tokw[2 * t] = w0 * rs; g_tokw[2 * t + 1] = w1 * rs;
        int p0 = atomicAdd(&g_cnt[e0], 1);
        g_pairs[e0 * NTOK + p0] = 2 * t;
        int p1 = atomicAdd(&g_cnt[e1], 1);
        g_pairs[e1 * NTOK + p1] = 2 * t + 1;
    }
}

// ---------------- aux loss ----------------
__global__ void aux_kernel(float* __restrict__ out_aux) {
    __shared__ float sload[256][EEXP];
    int tid = threadIdx.x;
    float l[EEXP];
#pragma unroll
    for (int e = 0; e < EEXP; e++) l[e] = 0.f;
    for (int a = tid; a < NTOK * 2; a += 256)
        l[g_toke[a]] += g_selw[a];
#pragma unroll
    for (int e = 0; e < EEXP; e++) sload[tid][e] = l[e];
    __syncthreads();
    for (int s = 128; s > 0; s >>= 1) {
        if (tid < s) {
#pragma unroll
            for (int e = 0; e < EEXP; e++) sload[tid][e] += sload[tid + s][e];
        }
        __syncthreads();
    }
    if (tid == 0) {
        float aux = 0.f;
#pragma unroll
        for (int e = 0; e < EEXP; e++) {
            float pe = sload[0][e] / (float)NTOK;
            float pt = (float)g_cnt[e] / (float)(NTOK * TOPK);
            aux += pe * pt;
        }
        aux *= (float)EEXP * 1e-3f;
        *out_aux = aux;
    }
}

// ---------------- gate+up GEMM (fp16 2-MMA split, ldmatrix + cp.async) ----------------
__global__ __launch_bounds__(256) void gateup_kernel() {
    int e = blockIdx.z;
    int M = g_cnt[e];
    int m0 = blockIdx.y * TM;
    if (m0 >= M) return;
    int n0 = blockIdx.x * TN;

    __shared__ __half Ah[2][TM][AP], Al[2][TM][AP];
    __shared__ __half Bg[2][TN][AP], Bu[2][TN][AP];
    __shared__ int prow[TM];
    __shared__ int toks[TM];

    int tid = threadIdx.x;
    if (tid < TM) {
        int r = m0 + tid;
        int pr = (r < M) ? g_pairs[e * NTOK + r] : g_pairs[e * NTOK];
        prow[tid] = pr;
        toks[tid] = pr >> 1;
    }
    __syncthreads();

    const __half* wg = g_wg + (size_t)e * IDIM * HDIM;
    const __half* wu = g_wu + (size_t)e * IDIM * HDIM;

    int wid = tid >> 5;
    int lane = tid & 31;
    int wm = wid >> 1;
    int wn = wid & 1;
    int g = lane >> 2;
    int q = lane & 3;

    int arow = tid >> 2;            // 0..63
    int achk = (tid & 3) * 8;

    unsigned offA0 = (unsigned)toks[arow] * HDIM + achk;
    unsigned offA1 = (unsigned)toks[arow + 64] * HDIM + achk;
    unsigned offB  = (unsigned)(n0 + arow) * HDIM + achk;

    unsigned aoff[2];
#pragma unroll
    for (int mf = 0; mf < 2; mf++)
        aoff[mf] = ((wm * 32 + mf * 16 + (lane & 15)) * AP + ((lane >> 4) << 3)) * 2;
    unsigned boff[2];
#pragma unroll
    for (int nfp = 0; nfp < 2; nfp++)
        boff[nfp] = ((wn * 32 + nfp * 16 + ((lane >> 4) << 3) + (lane & 7)) * AP
                     + (((lane >> 3) & 1) << 3)) * 2;

    unsigned sAh = (unsigned)__cvta_generic_to_shared(&Ah[0][0][0]);
    unsigned sAl = (unsigned)__cvta_generic_to_shared(&Al[0][0][0]);
    unsigned sBg = (unsigned)__cvta_generic_to_shared(&Bg[0][0][0]);
    unsigned sBu = (unsigned)__cvta_generic_to_shared(&Bu[0][0][0]);
    const unsigned strA = TM * AP * 2;
    const unsigned strB = TN * AP * 2;

    float accG[2][4][4], accU[2][4][4];
#pragma unroll
    for (int i = 0; i < 2; i++)
#pragma unroll
        for (int j = 0; j < 4; j++)
#pragma unroll
            for (int c = 0; c < 4; c++) { accG[i][j][c] = 0.f; accU[i][j][c] = 0.f; }

#define GU_LOAD(st, k0)                                            \
    do {                                                           \
        cpa16(&Ah[st][arow][achk],      g_xh + offA0 + (k0));      \
        cpa16(&Ah[st][arow + 64][achk], g_xh + offA1 + (k0));      \
        cpa16(&Al[st][arow][achk],      g_xl + offA0 + (k0));      \
        cpa16(&Al[st][arow + 64][achk], g_xl + offA1 + (k0));      \
        cpa16(&Bg[st][arow][achk],      wg + offB + (k0));         \
        cpa16(&Bu[st][arow][achk],      wu + offB + (k0));         \
        cpa_commit();                                              \
    } while (0)

    GU_LOAD(0, 0);

    const int NIT = HDIM / TK;
    for (int it = 0; it < NIT; it++) {
        cpa_wait0();
        __syncthreads();
        if (it + 1 < NIT) GU_LOAD((it + 1) & 1, (it + 1) * TK);
        unsigned stA = (it & 1) * strA;
        unsigned stB = (it & 1) * strB;

#pragma unroll
        for (int kk = 0; kk < TK; kk += 16) {
            unsigned aH[2][4], aL[2][4];
#pragma unroll
            for (int mf = 0; mf < 2; mf++) {
                ldsm4(aH[mf][0], aH[mf][1], aH[mf][2], aH[mf][3], sAh + stA + aoff[mf] + kk * 2);
                ldsm4(aL[mf][0], aL[mf][1], aL[mf][2], aL[mf][3], sAl + stA + aoff[mf] + kk * 2);
            }
#pragma unroll
            for (int nfp = 0; nfp < 2; nfp++) {
                unsigned bG[4];
                ldsm4(bG[0], bG[1], bG[2], bG[3], sBg + stB + boff[nfp] + kk * 2);
#pragma unroll
                for (int h2 = 0; h2 < 2; h2++) {
                    int nf = nfp * 2 + h2;
#pragma unroll
                    for (int mf = 0; mf < 2; mf++) {
                        mma_f16(accG[mf][nf], aH[mf], &bG[h2 * 2]);
                        mma_f16(accG[mf][nf], aL[mf], &bG[h2 * 2]);
                    }
                }
            }
#pragma unroll
            for (int nfp = 0; nfp < 2; nfp++) {
                unsigned bU[4];
                ldsm4(bU[0], bU[1], bU[2], bU[3], sBu + stB + boff[nfp] + kk * 2);
#pragma unroll
                for (int h2 = 0; h2 < 2; h2++) {
                    int nf = nfp * 2 + h2;
#pragma unroll
                    for (int mf = 0; mf < 2; mf++) {
                        mma_f16(accU[mf][nf], aH[mf], &bU[h2 * 2]);
                        mma_f16(accU[mf][nf], aL[mf], &bU[h2 * 2]);
                    }
                }
            }
        }
    }
#undef GU_LOAD

    // epilogue: h = silu(g) * u, exact fp16 hi/lo split
#pragma unroll
    for (int mf = 0; mf < 2; mf++) {
#pragma unroll
        for (int half = 0; half < 2; half++) {
            int lr = wm * 32 + mf * 16 + g + half * 8;
            int r = m0 + lr;
            if (r < M) {
                int p = prow[lr];
#pragma unroll
                for (int nf = 0; nf < 4; nf++) {
                    int col = n0 + wn * 32 + nf * 8 + 2 * q;
                    float gv0 = accG[mf][nf][half * 2 + 0];
                    float gv1 = accG[mf][nf][half * 2 + 1];
                    float uv0 = accU[mf][nf][half * 2 + 0];
                    float uv1 = accU[mf][nf][half * 2 + 1];
                    float hx = (gv0 / (1.f + expf(-gv0))) * uv0;
                    float hy = (gv1 / (1.f + expf(-gv1))) * uv1;
                    unsigned hb, lb;
                    hsplit2(hx, hy, hb, lb);
                    *(unsigned*)&g_hbh[(size_t)p * IDIM + col] = hb;
                    *(unsigned*)&g_hbl[(size_t)p * IDIM + col] = lb;
                }
            }
        }
    }
}

// ---------------- down GEMM (fp16 2-MMA split, ldmatrix + cp.async) ----------------
__global__ __launch_bounds__(256) void down_kernel() {
    int e = blockIdx.z;
    int M = g_cnt[e];
    int m0 = blockIdx.y * TM;
    if (m0 >= M) return;
    int n0 = blockIdx.x * TN;

    __shared__ __half Ah[2][TM][AP], Al[2][TM][AP];
    __shared__ __half Bs[2][TN][AP];
    __shared__ int prow[TM];

    int tid = threadIdx.x;
    if (tid < TM) {
        int r = m0 + tid;
        prow[tid] = (r < M) ? g_pairs[e * NTOK + r] : g_pairs[e * NTOK];
    }
    __syncthreads();

    const __half* wd = g_wd + (size_t)e * HDIM * IDIM;

    int wid = tid >> 5;
    int lane = tid & 31;
    int wm = wid >> 1;
    int wn = wid & 1;
    int g = lane >> 2;
    int q = lane & 3;

    int arow = tid >> 2;
    int achk = (tid & 3) * 8;

    unsigned offA0 = (unsigned)prow[arow] * IDIM + achk;
    unsigned offA1 = (unsigned)prow[arow + 64] * IDIM + achk;
    unsigned offB  = (unsigned)(n0 + arow) * IDIM + achk;

    unsigned aoff[2];
#pragma unroll
    for (int mf = 0; mf < 2; mf++)
        aoff[mf] = ((wm * 32 + mf * 16 + (lane & 15)) * AP + ((lane >> 4) << 3)) * 2;
    unsigned boff[2];
#pragma unroll
    for (int nfp = 0; nfp < 2; nfp++)
        boff[nfp] = ((wn * 32 + nfp * 16 + ((lane >> 4) << 3) + (lane & 7)) * AP
                     + (((lane >> 3) & 1) << 3)) * 2;

    unsigned sAh = (unsigned)__cvta_generic_to_shared(&Ah[0][0][0]);
    unsigned sAl = (unsigned)__cvta_generic_to_shared(&Al[0][0][0]);
    unsigned sBs = (unsigned)__cvta_generic_to_shared(&Bs[0][0][0]);
    const unsigned strA = TM * AP * 2;
    const unsigned strB = TN * AP * 2;

    float acc[2][4][4];
#pragma unroll
    for (int i = 0; i < 2; i++)
#pragma unroll
        for (int j = 0; j < 4; j++)
#pragma unroll
            for (int c = 0; c < 4; c++) acc[i][j][c] = 0.f;

#define DN_LOAD(st, k0)                                            \
    do {                                                           \
        cpa16(&Ah[st][arow][achk],      g_hbh + offA0 + (k0));     \
        cpa16(&Ah[st][arow + 64][achk], g_hbh + offA1 + (k0));     \
        cpa16(&Al[st][arow][achk],      g_hbl + offA0 + (k0));     \
        cpa16(&Al[st][arow + 64][achk], g_hbl + offA1 + (k0));     \
        cpa16(&Bs[st][arow][achk],      wd + offB + (k0));         \
        cpa_commit();                                              \
    } while (0)

    DN_LOAD(0, 0);

    const int NIT = IDIM / TK;
    for (int it = 0; it < NIT; it++) {
        cpa_wait0();
        __syncthreads();
        if (it + 1 < NIT) DN_LOAD((it + 1) & 1, (it + 1) * TK);
        unsigned stA = (it & 1) * strA;
        unsigned stB = (it & 1) * strB;

#pragma unroll
        for (int kk = 0; kk < TK; kk += 16) {
            unsigned aH[2][4], aL[2][4];
#pragma unroll
            for (int mf = 0; mf < 2; mf++) {
                ldsm4(aH[mf][0], aH[mf][1], aH[mf][2], aH[mf][3], sAh + stA + aoff[mf] + kk * 2);
                ldsm4(aL[mf][0], aL[mf][1], aL[mf][2], aL[mf][3], sAl + stA + aoff[mf] + kk * 2);
            }
#pragma unroll
            for (int nfp = 0; nfp < 2; nfp++) {
                unsigned bB[4];
                ldsm4(bB[0], bB[1], bB[2], bB[3], sBs + stB + boff[nfp] + kk * 2);
#pragma unroll
                for (int h2 = 0; h2 < 2; h2++) {
                    int nf = nfp * 2 + h2;
#pragma unroll
                    for (int mf = 0; mf < 2; mf++) {
                        mma_f16(acc[mf][nf], aH[mf], &bB[h2 * 2]);
                        mma_f16(acc[mf][nf], aL[mf], &bB[h2 * 2]);
                    }
                }
            }
        }
    }
#undef DN_LOAD

#pragma unroll
    for (int mf = 0; mf < 2; mf++) {
#pragma unroll
        for (int half = 0; half < 2; half++) {
            int lr = wm * 32 + mf * 16 + g + half * 8;
            int r = m0 + lr;
            if (r < M) {
                int p = prow[lr];
#pragma unroll
                for (int nf = 0; nf < 4; nf++) {
                    int col = n0 + wn * 32 + nf * 8 + 2 * q;
                    float2 o;
                    o.x = acc[mf][nf][half * 2 + 0];
                    o.y = acc[mf][nf][half * 2 + 1];
                    *(float2*)&g_ybuf[(size_t)p * HDIM + col] = o;
                }
            }
        }
    }
}

// ---------------- combine ----------------
__global__ void combine_kernel(float* __restrict__ y) {
    int idx = blockIdx.x * blockDim.x + threadIdx.x;
    int t = idx / (HDIM / 4);
    int h4 = (idx - t * (HDIM / 4)) * 4;
    float w0 = g_tokw[2 * t], w1 = g_tokw[2 * t + 1];
    float4 a = *(const float4*)&g_ybuf[(size_t)(2 * t) * HDIM + h4];
    float4 b = *(const float4*)&g_ybuf[(size_t)(2 * t + 1) * HDIM + h4];
    float4 r;
    r.x = w0 * a.x + w1 * b.x;
    r.y = w0 * a.y + w1 * b.y;
    r.z = w0 * a.z + w1 * b.z;
    r.w = w0 * a.w + w1 * b.w;
    *(float4*)&y[(size_t)t * HDIM + h4] = r;
}

// ---------------- launch ----------------
extern "C" void kernel_launch(void* const* d_in, const int* in_sizes, int n_in,
                              void* d_out, int out_size) {
    const float* x  = (const float*)d_in[0];
    const float* gw = (const float*)d_in[1];
    const float* wg = (const float*)d_in[2];
    const float* wu = (const float*)d_in[3];
    const float* wd = (const float*)d_in[4];
    float* y = (float*)d_out;

    reset_kernel<<<1, 32>>>();
    router_kernel<<<NTOK / 8, 256>>>(x, gw);
    aux_kernel<<<1, 256>>>(y + (out_size - 1));

    split_x_kernel<<<(NTOK * HDIM / 4) / 256, 256>>>(x);
    transpose_half_kernel<0><<<dim3(IDIM / 32, HDIM / 32, EEXP), 256>>>(wg, HDIM, IDIM);
    transpose_half_kernel<1><<<dim3(IDIM / 32, HDIM / 32, EEXP), 256>>>(wu, HDIM, IDIM);
    transpose_half_kernel<2><<<dim3(HDIM / 32, IDIM / 32, EEXP), 256>>>(wd, IDIM, HDIM);

    gateup_kernel<<<dim3(IDIM / TN, (NTOK * 2) / TM, EEXP), 256>>>();
    down_kernel<<<dim3(HDIM / TN, (NTOK * 2) / TM, EEXP), 256>>>();
    combine_kernel<<<(NTOK * HDIM / 4) / 256, 256>>>(y);
}

// round 9
// speedup vs baseline: 2.9879x; 1.1288x over previous
#include <cuda_runtime.h>
#include <cuda_fp16.h>
#include <math.h>

// Problem constants (fixed by setup_inputs)
#define NTOK 8192      // B*S
#define HDIM 1024
#define IDIM 2048
#define EEXP 8
#define TOPK 2

// GEMM tiling
#define TM 128
#define TN 64
#define TK 32
#define AP 40          // padded k-row length (fp16): 80B stride, conflict-free LDSM

// ---------------- device scratch ----------------
__device__ int   g_cnt[EEXP];
__device__ int   g_pairs[EEXP * NTOK];
__device__ float g_tokw[NTOK * 2];
__device__ int   g_toke[NTOK * 2];
__device__ float g_selw[NTOK * 2];

// activations: exact fp16 hi/lo split; weights + h: single-rounded fp16
__device__ __half g_xh[NTOK * HDIM];
__device__ __half g_xl[NTOK * HDIM];
__device__ __half g_wg[EEXP * IDIM * HDIM];   // gate, transposed [e][i][h]
__device__ __half g_wu[EEXP * IDIM * HDIM];   // up, transposed [e][i][h]
__device__ __half g_wd[EEXP * HDIM * IDIM];   // down, transposed [e][h][i]
__device__ __half g_hb[NTOK * 2 * IDIM];      // silu(g)*u (fp16)  [pair][I]
__device__ float g_ybuf[NTOK * 2 * HDIM];     // expert outputs [pair][H]

// ---------------- helpers ----------------
__device__ __forceinline__ void hsplit2(float a, float b, unsigned &hi, unsigned &lo) {
    __half2 h = __floats2half2_rn(a, b);
    float lx = a - __half2float(__low2half(h));
    float ly = b - __half2float(__high2half(h));
    __half2 l = __floats2half2_rn(lx, ly);
    hi = *reinterpret_cast<unsigned*>(&h);
    lo = *reinterpret_cast<unsigned*>(&l);
}

__device__ __forceinline__ void mma_f16(float *d, const unsigned *a, const unsigned *b) {
    asm volatile("mma.sync.aligned.m16n8k16.row.col.f32.f16.f16.f32 "
        "{%0,%1,%2,%3}, {%4,%5,%6,%7}, {%8,%9}, {%0,%1,%2,%3};\n"
        : "+f"(d[0]), "+f"(d[1]), "+f"(d[2]), "+f"(d[3])
        : "r"(a[0]), "r"(a[1]), "r"(a[2]), "r"(a[3]), "r"(b[0]), "r"(b[1]));
}

__device__ __forceinline__ void ldsm4(unsigned &r0, unsigned &r1, unsigned &r2, unsigned &r3,
                                      unsigned a) {
    asm volatile("ldmatrix.sync.aligned.m8n8.x4.shared.b16 {%0,%1,%2,%3}, [%4];\n"
        : "=r"(r0), "=r"(r1), "=r"(r2), "=r"(r3) : "r"(a));
}

__device__ __forceinline__ void cpa16(void* smem, const void* g) {
    unsigned s = (unsigned)__cvta_generic_to_shared(smem);
    asm volatile("cp.async.cg.shared.global [%0], [%1], 16;\n" :: "r"(s), "l"(g));
}
__device__ __forceinline__ void cpa_commit() {
    asm volatile("cp.async.commit_group;\n");
}
__device__ __forceinline__ void cpa_wait0() {
    asm volatile("cp.async.wait_group 0;\n");
}

// ---------------- reset ----------------
__global__ void reset_kernel() {
    if (threadIdx.x < EEXP) g_cnt[threadIdx.x] = 0;
}

// ---------------- split x into fp16 hi/lo ----------------
__global__ void split_x_kernel(const float* __restrict__ x) {
    int idx = blockIdx.x * blockDim.x + threadIdx.x;
    float4 v = ((const float4*)x)[idx];
    unsigned h0, l0, h1, l1;
    hsplit2(v.x, v.y, h0, l0);
    hsplit2(v.z, v.w, h1, l1);
    uint2 hh; hh.x = h0; hh.y = h1;
    uint2 ll; ll.x = l0; ll.y = l1;
    ((uint2*)g_xh)[idx] = hh;
    ((uint2*)g_xl)[idx] = ll;
}

// ---------------- transpose weights to fp16: src [E][R][C] -> dst [E][C][R] ----------------
// W selects destinations IN DEVICE CODE (never pass __device__ globals from host:
// that passes the host shadow symbol; ATS silently dereferences host memory).
template<int W>
__global__ void transpose_half_kernel(const float* __restrict__ src, int R, int C) {
    __half* dh = (W == 0) ? g_wg : (W == 1) ? g_wu : g_wd;
    __shared__ float s[32][33];
    int e = blockIdx.z;
    int r0 = blockIdx.y * 32, c0 = blockIdx.x * 32;
    int tx = threadIdx.x & 31, ty = threadIdx.x >> 5;
    const float* sp = src + ((size_t)e * R + r0) * C + c0;
#pragma unroll
    for (int j = 0; j < 4; j++)
        s[ty + j * 8][tx] = sp[(size_t)(ty + j * 8) * C + tx];
    __syncthreads();
    size_t dbase = ((size_t)e * C + c0) * R + r0;
#pragma unroll
    for (int j = 0; j < 4; j++)
        dh[dbase + (size_t)(ty + j * 8) * R + tx] = __float2half(s[tx][ty + j * 8]);
}

// ---------------- router: one warp per token ----------------
__global__ void router_kernel(const float* __restrict__ x,
                              const float* __restrict__ gw) {
    int t = blockIdx.x * (blockDim.x >> 5) + (threadIdx.x >> 5);
    int lane = threadIdx.x & 31;
    if (t >= NTOK) return;
    const float* xr = x + (size_t)t * HDIM;
    float acc[EEXP];
#pragma unroll
    for (int e = 0; e < EEXP; e++) acc[e] = 0.f;
    for (int h = lane; h < HDIM; h += 32) {
        float xv = xr[h];
        const float* g = gw + h * EEXP;
#pragma unroll
        for (int e = 0; e < EEXP; e++) acc[e] = fmaf(xv, g[e], acc[e]);
    }
#pragma unroll
    for (int off = 16; off > 0; off >>= 1) {
#pragma unroll
        for (int e = 0; e < EEXP; e++)
            acc[e] += __shfl_down_sync(0xffffffffu, acc[e], off);
    }
    if (lane == 0) {
        float mx = acc[0];
#pragma unroll
        for (int e = 1; e < EEXP; e++) mx = fmaxf(mx, acc[e]);
        float p[EEXP];
        float s = 0.f;
#pragma unroll
        for (int e = 0; e < EEXP; e++) { p[e] = expf(acc[e] - mx); s += p[e]; }
        float inv = 1.f / s;
#pragma unroll
        for (int e = 0; e < EEXP; e++) p[e] *= inv;
        int e0 = 0;
#pragma unroll
        for (int e = 1; e < EEXP; e++) if (p[e] > p[e0]) e0 = e;
        int e1 = (e0 == 0) ? 1 : 0;
#pragma unroll
        for (int e = 0; e < EEXP; e++) if (e != e0 && p[e] > p[e1]) e1 = e;
        float w0 = p[e0], w1 = p[e1];
        float rs = 1.f / (w0 + w1);
        g_toke[2 * t] = e0;      g_toke[2 * t + 1] = e1;
        g_selw[2 * t] = w0;      g_selw[2 * t + 1] = w1;
        g_tokw[2 * t] = w0 * rs; g_tokw[2 * t + 1] = w1 * rs;
        int p0 = atomicAdd(&g_cnt[e0], 1);
        g_pairs[e0 * NTOK + p0] = 2 * t;
        int p1 = atomicAdd(&g_cnt[e1], 1);
        g_pairs[e1 * NTOK + p1] = 2 * t + 1;
    }
}

// ---------------- aux loss ----------------
__global__ void aux_kernel(float* __restrict__ out_aux) {
    __shared__ float sload[256][EEXP];
    int tid = threadIdx.x;
    float l[EEXP];
#pragma unroll
    for (int e = 0; e < EEXP; e++) l[e] = 0.f;
    for (int a = tid; a < NTOK * 2; a += 256)
        l[g_toke[a]] += g_selw[a];
#pragma unroll
    for (int e = 0; e < EEXP; e++) sload[tid][e] = l[e];
    __syncthreads();
    for (int s = 128; s > 0; s >>= 1) {
        if (tid < s) {
#pragma unroll
            for (int e = 0; e < EEXP; e++) sload[tid][e] += sload[tid + s][e];
        }
        __syncthreads();
    }
    if (tid == 0) {
        float aux = 0.f;
#pragma unroll
        for (int e = 0; e < EEXP; e++) {
            float pe = sload[0][e] / (float)NTOK;
            float pt = (float)g_cnt[e] / (float)(NTOK * TOPK);
            aux += pe * pt;
        }
        aux *= (float)EEXP * 1e-3f;
        *out_aux = aux;
    }
}

// ---------------- gate+up GEMM (fp16 2-MMA split, ldmatrix + cp.async) ----------------
__global__ __launch_bounds__(256) void gateup_kernel() {
    int e = blockIdx.z;
    int M = g_cnt[e];
    int m0 = blockIdx.y * TM;
    if (m0 >= M) return;
    int n0 = blockIdx.x * TN;

    __shared__ __half Ah[2][TM][AP], Al[2][TM][AP];
    __shared__ __half Bg[2][TN][AP], Bu[2][TN][AP];
    __shared__ int prow[TM];
    __shared__ int toks[TM];

    int tid = threadIdx.x;
    if (tid < TM) {
        int r = m0 + tid;
        int pr = (r < M) ? g_pairs[e * NTOK + r] : g_pairs[e * NTOK];
        prow[tid] = pr;
        toks[tid] = pr >> 1;
    }
    __syncthreads();

    const __half* wg = g_wg + (size_t)e * IDIM * HDIM;
    const __half* wu = g_wu + (size_t)e * IDIM * HDIM;

    int wid = tid >> 5;
    int lane = tid & 31;
    int wm = wid >> 1;
    int wn = wid & 1;
    int g = lane >> 2;
    int q = lane & 3;

    int arow = tid >> 2;            // 0..63
    int achk = (tid & 3) * 8;

    unsigned offA0 = (unsigned)toks[arow] * HDIM + achk;
    unsigned offA1 = (unsigned)toks[arow + 64] * HDIM + achk;
    unsigned offB  = (unsigned)(n0 + arow) * HDIM + achk;

    unsigned aoff[2];
#pragma unroll
    for (int mf = 0; mf < 2; mf++)
        aoff[mf] = ((wm * 32 + mf * 16 + (lane & 15)) * AP + ((lane >> 4) << 3)) * 2;
    unsigned boff[2];
#pragma unroll
    for (int nfp = 0; nfp < 2; nfp++)
        boff[nfp] = ((wn * 32 + nfp * 16 + ((lane >> 4) << 3) + (lane & 7)) * AP
                     + (((lane >> 3) & 1) << 3)) * 2;

    unsigned sAh = (unsigned)__cvta_generic_to_shared(&Ah[0][0][0]);
    unsigned sAl = (unsigned)__cvta_generic_to_shared(&Al[0][0][0]);
    unsigned sBg = (unsigned)__cvta_generic_to_shared(&Bg[0][0][0]);
    unsigned sBu = (unsigned)__cvta_generic_to_shared(&Bu[0][0][0]);
    const unsigned strA = TM * AP * 2;
    const unsigned strB = TN * AP * 2;

    float accG[2][4][4], accU[2][4][4];
#pragma unroll
    for (int i = 0; i < 2; i++)
#pragma unroll
        for (int j = 0; j < 4; j++)
#pragma unroll
            for (int c = 0; c < 4; c++) { accG[i][j][c] = 0.f; accU[i][j][c] = 0.f; }

#define GU_LOAD(st, k0)                                            \
    do {                                                           \
        cpa16(&Ah[st][arow][achk],      g_xh + offA0 + (k0));      \
        cpa16(&Ah[st][arow + 64][achk], g_xh + offA1 + (k0));      \
        cpa16(&Al[st][arow][achk],      g_xl + offA0 + (k0));      \
        cpa16(&Al[st][arow + 64][achk], g_xl + offA1 + (k0));      \
        cpa16(&Bg[st][arow][achk],      wg + offB + (k0));         \
        cpa16(&Bu[st][arow][achk],      wu + offB + (k0));         \
        cpa_commit();                                              \
    } while (0)

    GU_LOAD(0, 0);

    const int NIT = HDIM / TK;
    for (int it = 0; it < NIT; it++) {
        cpa_wait0();
        __syncthreads();
        if (it + 1 < NIT) GU_LOAD((it + 1) & 1, (it + 1) * TK);
        unsigned stA = (it & 1) * strA;
        unsigned stB = (it & 1) * strB;

#pragma unroll
        for (int kk = 0; kk < TK; kk += 16) {
            unsigned aH[2][4], aL[2][4];
#pragma unroll
            for (int mf = 0; mf < 2; mf++) {
                ldsm4(aH[mf][0], aH[mf][1], aH[mf][2], aH[mf][3], sAh + stA + aoff[mf] + kk * 2);
                ldsm4(aL[mf][0], aL[mf][1], aL[mf][2], aL[mf][3], sAl + stA + aoff[mf] + kk * 2);
            }
#pragma unroll
            for (int nfp = 0; nfp < 2; nfp++) {
                unsigned bG[4];
                ldsm4(bG[0], bG[1], bG[2], bG[3], sBg + stB + boff[nfp] + kk * 2);
#pragma unroll
                for (int h2 = 0; h2 < 2; h2++) {
                    int nf = nfp * 2 + h2;
#pragma unroll
                    for (int mf = 0; mf < 2; mf++) {
                        mma_f16(accG[mf][nf], aH[mf], &bG[h2 * 2]);
                        mma_f16(accG[mf][nf], aL[mf], &bG[h2 * 2]);
                    }
                }
            }
#pragma unroll
            for (int nfp = 0; nfp < 2; nfp++) {
                unsigned bU[4];
                ldsm4(bU[0], bU[1], bU[2], bU[3], sBu + stB + boff[nfp] + kk * 2);
#pragma unroll
                for (int h2 = 0; h2 < 2; h2++) {
                    int nf = nfp * 2 + h2;
#pragma unroll
                    for (int mf = 0; mf < 2; mf++) {
                        mma_f16(accU[mf][nf], aH[mf], &bU[h2 * 2]);
                        mma_f16(accU[mf][nf], aL[mf], &bU[h2 * 2]);
                    }
                }
            }
        }
    }
#undef GU_LOAD

    // epilogue: h = silu(g) * u, single-rounded fp16
#pragma unroll
    for (int mf = 0; mf < 2; mf++) {
#pragma unroll
        for (int half = 0; half < 2; half++) {
            int lr = wm * 32 + mf * 16 + g + half * 8;
            int r = m0 + lr;
            if (r < M) {
                int p = prow[lr];
#pragma unroll
                for (int nf = 0; nf < 4; nf++) {
                    int col = n0 + wn * 32 + nf * 8 + 2 * q;
                    float gv0 = accG[mf][nf][half * 2 + 0];
                    float gv1 = accG[mf][nf][half * 2 + 1];
                    float uv0 = accU[mf][nf][half * 2 + 0];
                    float uv1 = accU[mf][nf][half * 2 + 1];
                    float hx = (gv0 / (1.f + expf(-gv0))) * uv0;
                    float hy = (gv1 / (1.f + expf(-gv1))) * uv1;
                    __half2 hv = __floats2half2_rn(hx, hy);
                    *(unsigned*)&g_hb[(size_t)p * IDIM + col] =
                        *reinterpret_cast<unsigned*>(&hv);
                }
            }
        }
    }
}

// ---------------- down GEMM (plain fp16, 1 MMA, ldmatrix + cp.async) ----------------
__global__ __launch_bounds__(256) void down_kernel() {
    int e = blockIdx.z;
    int M = g_cnt[e];
    int m0 = blockIdx.y * TM;
    if (m0 >= M) return;
    int n0 = blockIdx.x * TN;

    __shared__ __half Ah[2][TM][AP];
    __shared__ __half Bs[2][TN][AP];
    __shared__ int prow[TM];

    int tid = threadIdx.x;
    if (tid < TM) {
        int r = m0 + tid;
        prow[tid] = (r < M) ? g_pairs[e * NTOK + r] : g_pairs[e * NTOK];
    }
    __syncthreads();

    const __half* wd = g_wd + (size_t)e * HDIM * IDIM;

    int wid = tid >> 5;
    int lane = tid & 31;
    int wm = wid >> 1;
    int wn = wid & 1;
    int g = lane >> 2;
    int q = lane & 3;

    int arow = tid >> 2;
    int achk = (tid & 3) * 8;

    unsigned offA0 = (unsigned)prow[arow] * IDIM + achk;
    unsigned offA1 = (unsigned)prow[arow + 64] * IDIM + achk;
    unsigned offB  = (unsigned)(n0 + arow) * IDIM + achk;

    unsigned aoff[2];
#pragma unroll
    for (int mf = 0; mf < 2; mf++)
        aoff[mf] = ((wm * 32 + mf * 16 + (lane & 15)) * AP + ((lane >> 4) << 3)) * 2;
    unsigned boff[2];
#pragma unroll
    for (int nfp = 0; nfp < 2; nfp++)
        boff[nfp] = ((wn * 32 + nfp * 16 + ((lane >> 4) << 3) + (lane & 7)) * AP
                     + (((lane >> 3) & 1) << 3)) * 2;

    unsigned sAh = (unsigned)__cvta_generic_to_shared(&Ah[0][0][0]);
    unsigned sBs = (unsigned)__cvta_generic_to_shared(&Bs[0][0][0]);
    const unsigned strA = TM * AP * 2;
    const unsigned strB = TN * AP * 2;

    float acc[2][4][4];
#pragma unroll
    for (int i = 0; i < 2; i++)
#pragma unroll
        for (int j = 0; j < 4; j++)
#pragma unroll
            for (int c = 0; c < 4; c++) acc[i][j][c] = 0.f;

#define DN_LOAD(st, k0)                                            \
    do {                                                           \
        cpa16(&Ah[st][arow][achk],      g_hb + offA0 + (k0));      \
        cpa16(&Ah[st][arow + 64][achk], g_hb + offA1 + (k0));      \
        cpa16(&Bs[st][arow][achk],      wd + offB + (k0));         \
        cpa_commit();                                              \
    } while (0)

    DN_LOAD(0, 0);

    const int NIT = IDIM / TK;
    for (int it = 0; it < NIT; it++) {
        cpa_wait0();
        __syncthreads();
        if (it + 1 < NIT) DN_LOAD((it + 1) & 1, (it + 1) * TK);
        unsigned stA = (it & 1) * strA;
        unsigned stB = (it & 1) * strB;

#pragma unroll
        for (int kk = 0; kk < TK; kk += 16) {
            unsigned aH[2][4];
#pragma unroll
            for (int mf = 0; mf < 2; mf++)
                ldsm4(aH[mf][0], aH[mf][1], aH[mf][2], aH[mf][3], sAh + stA + aoff[mf] + kk * 2);
#pragma unroll
            for (int nfp = 0; nfp < 2; nfp++) {
                unsigned bB[4];
                ldsm4(bB[0], bB[1], bB[2], bB[3], sBs + stB + boff[nfp] + kk * 2);
#pragma unroll
                for (int h2 = 0; h2 < 2; h2++) {
                    int nf = nfp * 2 + h2;
#pragma unroll
                    for (int mf = 0; mf < 2; mf++)
                        mma_f16(acc[mf][nf], aH[mf], &bB[h2 * 2]);
                }
            }
        }
    }
#undef DN_LOAD

#pragma unroll
    for (int mf = 0; mf < 2; mf++) {
#pragma unroll
        for (int half = 0; half < 2; half++) {
            int lr = wm * 32 + mf * 16 + g + half * 8;
            int r = m0 + lr;
            if (r < M) {
                int p = prow[lr];
#pragma unroll
                for (int nf = 0; nf < 4; nf++) {
                    int col = n0 + wn * 32 + nf * 8 + 2 * q;
                    float2 o;
                    o.x = acc[mf][nf][half * 2 + 0];
                    o.y = acc[mf][nf][half * 2 + 1];
                    *(float2*)&g_ybuf[(size_t)p * HDIM + col] = o;
                }
            }
        }
    }
}

// ---------------- combine ----------------
__global__ void combine_kernel(float* __restrict__ y) {
    int idx = blockIdx.x * blockDim.x + threadIdx.x;
    int t = idx / (HDIM / 4);
    int h4 = (idx - t * (HDIM / 4)) * 4;
    float w0 = g_tokw[2 * t], w1 = g_tokw[2 * t + 1];
    float4 a = *(const float4*)&g_ybuf[(size_t)(2 * t) * HDIM + h4];
    float4 b = *(const float4*)&g_ybuf[(size_t)(2 * t + 1) * HDIM + h4];
    float4 r;
    r.x = w0 * a.x + w1 * b.x;
    r.y = w0 * a.y + w1 * b.y;
    r.z = w0 * a.z + w1 * b.z;
    r.w = w0 * a.w + w1 * b.w;
    *(float4*)&y[(size_t)t * HDIM + h4] = r;
}

// ---------------- launch ----------------
extern "C" void kernel_launch(void* const* d_in, const int* in_sizes, int n_in,
                              void* d_out, int out_size) {
    const float* x  = (const float*)d_in[0];
    const float* gw = (const float*)d_in[1];
    const float* wg = (const float*)d_in[2];
    const float* wu = (const float*)d_in[3];
    const float* wd = (const float*)d_in[4];
    float* y = (float*)d_out;

    reset_kernel<<<1, 32>>>();
    router_kernel<<<NTOK / 8, 256>>>(x, gw);
    aux_kernel<<<1, 256>>>(y + (out_size - 1));

    split_x_kernel<<<(NTOK * HDIM / 4) / 256, 256>>>(x);
    transpose_half_kernel<0><<<dim3(IDIM / 32, HDIM / 32, EEXP), 256>>>(wg, HDIM, IDIM);
    transpose_half_kernel<1><<<dim3(IDIM / 32, HDIM / 32, EEXP), 256>>>(wu, HDIM, IDIM);
    transpose_half_kernel<2><<<dim3(HDIM / 32, IDIM / 32, EEXP), 256>>>(wd, IDIM, HDIM);

    gateup_kernel<<<dim3(IDIM / TN, (NTOK * 2) / TM, EEXP), 256>>>();
    down_kernel<<<dim3(HDIM / TN, (NTOK * 2) / TM, EEXP), 256>>>();
    combine_kernel<<<(NTOK * HDIM / 4) / 256, 256>>>(y);
}

// round 10
// speedup vs baseline: 3.1767x; 1.0632x over previous
#include <cuda_runtime.h>
#include <cuda_fp16.h>
#include <math.h>

// Problem constants (fixed by setup_inputs)
#define NTOK 8192      // B*S
#define HDIM 1024
#define IDIM 2048
#define EEXP 8
#define TOPK 2

// GEMM tiling
#define TM 128
#define TN 64
#define TK 32
#define AP 40          // padded k-row length (fp16): 80B stride, conflict-free LDSM

// ---------------- device scratch ----------------
__device__ int   g_cnt[EEXP];
__device__ int   g_pairs[EEXP * NTOK];
__device__ float g_tokw[NTOK * 2];
__device__ int   g_toke[NTOK * 2];
__device__ float g_selw[NTOK * 2];

// activations: exact fp16 hi/lo split (lo used by gate only); weights + h: fp16
__device__ __half g_xh[NTOK * HDIM];
__device__ __half g_xl[NTOK * HDIM];
__device__ __half g_wg[EEXP * IDIM * HDIM];   // gate, transposed [e][i][h]
__device__ __half g_wu[EEXP * IDIM * HDIM];   // up, transposed [e][i][h]
__device__ __half g_wd[EEXP * HDIM * IDIM];   // down, transposed [e][h][i]
__device__ __half g_hb[NTOK * 2 * IDIM];      // silu(g)*u (fp16)  [pair][I]
__device__ float g_ybuf[NTOK * 2 * HDIM];     // expert outputs [pair][H]

// ---------------- helpers ----------------
__device__ __forceinline__ void hsplit2(float a, float b, unsigned &hi, unsigned &lo) {
    __half2 h = __floats2half2_rn(a, b);
    float lx = a - __half2float(__low2half(h));
    float ly = b - __half2float(__high2half(h));
    __half2 l = __floats2half2_rn(lx, ly);
    hi = *reinterpret_cast<unsigned*>(&h);
    lo = *reinterpret_cast<unsigned*>(&l);
}

__device__ __forceinline__ void mma_f16(float *d, const unsigned *a, const unsigned *b) {
    asm volatile("mma.sync.aligned.m16n8k16.row.col.f32.f16.f16.f32 "
        "{%0,%1,%2,%3}, {%4,%5,%6,%7}, {%8,%9}, {%0,%1,%2,%3};\n"
        : "+f"(d[0]), "+f"(d[1]), "+f"(d[2]), "+f"(d[3])
        : "r"(a[0]), "r"(a[1]), "r"(a[2]), "r"(a[3]), "r"(b[0]), "r"(b[1]));
}

__device__ __forceinline__ void ldsm4(unsigned &r0, unsigned &r1, unsigned &r2, unsigned &r3,
                                      unsigned a) {
    asm volatile("ldmatrix.sync.aligned.m8n8.x4.shared.b16 {%0,%1,%2,%3}, [%4];\n"
        : "=r"(r0), "=r"(r1), "=r"(r2), "=r"(r3) : "r"(a));
}

__device__ __forceinline__ void cpa16(void* smem, const void* g) {
    unsigned s = (unsigned)__cvta_generic_to_shared(smem);
    asm volatile("cp.async.cg.shared.global [%0], [%1], 16;\n" :: "r"(s), "l"(g));
}
__device__ __forceinline__ void cpa_commit() {
    asm volatile("cp.async.commit_group;\n");
}
__device__ __forceinline__ void cpa_wait0() {
    asm volatile("cp.async.wait_group 0;\n");
}

// ---------------- reset ----------------
__global__ void reset_kernel() {
    if (threadIdx.x < EEXP) g_cnt[threadIdx.x] = 0;
}

// ---------------- split x into fp16 hi/lo ----------------
__global__ void split_x_kernel(const float* __restrict__ x) {
    int idx = blockIdx.x * blockDim.x + threadIdx.x;
    float4 v = ((const float4*)x)[idx];
    unsigned h0, l0, h1, l1;
    hsplit2(v.x, v.y, h0, l0);
    hsplit2(v.z, v.w, h1, l1);
    uint2 hh; hh.x = h0; hh.y = h1;
    uint2 ll; ll.x = l0; ll.y = l1;
    ((uint2*)g_xh)[idx] = hh;
    ((uint2*)g_xl)[idx] = ll;
}

// ---------------- transpose weights to fp16: src [E][R][C] -> dst [E][C][R] ----------------
// W selects destinations IN DEVICE CODE (never pass __device__ globals from host:
// that passes the host shadow symbol; ATS silently dereferences host memory).
template<int W>
__global__ void transpose_half_kernel(const float* __restrict__ src, int R, int C) {
    __half* dh = (W == 0) ? g_wg : (W == 1) ? g_wu : g_wd;
    __shared__ float s[32][33];
    int e = blockIdx.z;
    int r0 = blockIdx.y * 32, c0 = blockIdx.x * 32;
    int tx = threadIdx.x & 31, ty = threadIdx.x >> 5;
    const float* sp = src + ((size_t)e * R + r0) * C + c0;
#pragma unroll
    for (int j = 0; j < 4; j++)
        s[ty + j * 8][tx] = sp[(size_t)(ty + j * 8) * C + tx];
    __syncthreads();
    size_t dbase = ((size_t)e * C + c0) * R + r0;
#pragma unroll
    for (int j = 0; j < 4; j++)
        dh[dbase + (size_t)(ty + j * 8) * R + tx] = __float2half(s[tx][ty + j * 8]);
}

// ---------------- router: one warp per token ----------------
__global__ void router_kernel(const float* __restrict__ x,
                              const float* __restrict__ gw) {
    int t = blockIdx.x * (blockDim.x >> 5) + (threadIdx.x >> 5);
    int lane = threadIdx.x & 31;
    if (t >= NTOK) return;
    const float* xr = x + (size_t)t * HDIM;
    float acc[EEXP];
#pragma unroll
    for (int e = 0; e < EEXP; e++) acc[e] = 0.f;
    for (int h = lane; h < HDIM; h += 32) {
        float xv = xr[h];
        const float* g = gw + h * EEXP;
#pragma unroll
        for (int e = 0; e < EEXP; e++) acc[e] = fmaf(xv, g[e], acc[e]);
    }
#pragma unroll
    for (int off = 16; off > 0; off >>= 1) {
#pragma unroll
        for (int e = 0; e < EEXP; e++)
            acc[e] += __shfl_down_sync(0xffffffffu, acc[e], off);
    }
    if (lane == 0) {
        float mx = acc[0];
#pragma unroll
        for (int e = 1; e < EEXP; e++) mx = fmaxf(mx, acc[e]);
        float p[EEXP];
        float s = 0.f;
#pragma unroll
        for (int e = 0; e < EEXP; e++) { p[e] = expf(acc[e] - mx); s += p[e]; }
        float inv = 1.f / s;
#pragma unroll
        for (int e = 0; e < EEXP; e++) p[e] *= inv;
        int e0 = 0;
#pragma unroll
        for (int e = 1; e < EEXP; e++) if (p[e] > p[e0]) e0 = e;
        int e1 = (e0 == 0) ? 1 : 0;
#pragma unroll
        for (int e = 0; e < EEXP; e++) if (e != e0 && p[e] > p[e1]) e1 = e;
        float w0 = p[e0], w1 = p[e1];
        float rs = 1.f / (w0 + w1);
        g_toke[2 * t] = e0;      g_toke[2 * t + 1] = e1;
        g_selw[2 * t] = w0;      g_selw[2 * t + 1] = w1;
        g_tokw[2 * t] = w0 * rs; g_tokw[2 * t + 1] = w1 * rs;
        int p0 = atomicAdd(&g_cnt[e0], 1);
        g_pairs[e0 * NTOK + p0] = 2 * t;
        int p1 = atomicAdd(&g_cnt[e1], 1);
        g_pairs[e1 * NTOK + p1] = 2 * t + 1;
    }
}

// ---------------- aux loss ----------------
__global__ void aux_kernel(float* __restrict__ out_aux) {
    __shared__ float sload[256][EEXP];
    int tid = threadIdx.x;
    float l[EEXP];
#pragma unroll
    for (int e = 0; e < EEXP; e++) l[e] = 0.f;
    for (int a = tid; a < NTOK * 2; a += 256)
        l[g_toke[a]] += g_selw[a];
#pragma unroll
    for (int e = 0; e < EEXP; e++) sload[tid][e] = l[e];
    __syncthreads();
    for (int s = 128; s > 0; s >>= 1) {
        if (tid < s) {
#pragma unroll
            for (int e = 0; e < EEXP; e++) sload[tid][e] += sload[tid + s][e];
        }
        __syncthreads();
    }
    if (tid == 0) {
        float aux = 0.f;
#pragma unroll
        for (int e = 0; e < EEXP; e++) {
            float pe = sload[0][e] / (float)NTOK;
            float pt = (float)g_cnt[e] / (float)(NTOK * TOPK);
            aux += pe * pt;
        }
        aux *= (float)EEXP * 1e-3f;
        *out_aux = aux;
    }
}

// ---------------- gate+up GEMM (gate: 2-MMA split, up: 1-MMA; ldmatrix + cp.async) ----------------
__global__ __launch_bounds__(256) void gateup_kernel() {
    int e = blockIdx.z;
    int M = g_cnt[e];
    int m0 = blockIdx.y * TM;
    if (m0 >= M) return;
    int n0 = blockIdx.x * TN;

    __shared__ __half Ah[2][TM][AP], Al[2][TM][AP];
    __shared__ __half Bg[2][TN][AP], Bu[2][TN][AP];
    __shared__ int prow[TM];
    __shared__ int toks[TM];

    int tid = threadIdx.x;
    if (tid < TM) {
        int r = m0 + tid;
        int pr = (r < M) ? g_pairs[e * NTOK + r] : g_pairs[e * NTOK];
        prow[tid] = pr;
        toks[tid] = pr >> 1;
    }
    __syncthreads();

    const __half* wg = g_wg + (size_t)e * IDIM * HDIM;
    const __half* wu = g_wu + (size_t)e * IDIM * HDIM;

    int wid = tid >> 5;
    int lane = tid & 31;
    int wm = wid >> 1;
    int wn = wid & 1;
    int g = lane >> 2;
    int q = lane & 3;

    int arow = tid >> 2;            // 0..63
    int achk = (tid & 3) * 8;

    unsigned offA0 = (unsigned)toks[arow] * HDIM + achk;
    unsigned offA1 = (unsigned)toks[arow + 64] * HDIM + achk;
    unsigned offB  = (unsigned)(n0 + arow) * HDIM + achk;

    unsigned aoff[2];
#pragma unroll
    for (int mf = 0; mf < 2; mf++)
        aoff[mf] = ((wm * 32 + mf * 16 + (lane & 15)) * AP + ((lane >> 4) << 3)) * 2;
    unsigned boff[2];
#pragma unroll
    for (int nfp = 0; nfp < 2; nfp++)
        boff[nfp] = ((wn * 32 + nfp * 16 + ((lane >> 4) << 3) + (lane & 7)) * AP
                     + (((lane >> 3) & 1) << 3)) * 2;

    unsigned sAh = (unsigned)__cvta_generic_to_shared(&Ah[0][0][0]);
    unsigned sAl = (unsigned)__cvta_generic_to_shared(&Al[0][0][0]);
    unsigned sBg = (unsigned)__cvta_generic_to_shared(&Bg[0][0][0]);
    unsigned sBu = (unsigned)__cvta_generic_to_shared(&Bu[0][0][0]);
    const unsigned strA = TM * AP * 2;
    const unsigned strB = TN * AP * 2;

    float accG[2][4][4], accU[2][4][4];
#pragma unroll
    for (int i = 0; i < 2; i++)
#pragma unroll
        for (int j = 0; j < 4; j++)
#pragma unroll
            for (int c = 0; c < 4; c++) { accG[i][j][c] = 0.f; accU[i][j][c] = 0.f; }

#define GU_LOAD(st, k0)                                            \
    do {                                                           \
        cpa16(&Ah[st][arow][achk],      g_xh + offA0 + (k0));      \
        cpa16(&Ah[st][arow + 64][achk], g_xh + offA1 + (k0));      \
        cpa16(&Al[st][arow][achk],      g_xl + offA0 + (k0));      \
        cpa16(&Al[st][arow + 64][achk], g_xl + offA1 + (k0));      \
        cpa16(&Bg[st][arow][achk],      wg + offB + (k0));         \
        cpa16(&Bu[st][arow][achk],      wu + offB + (k0));         \
        cpa_commit();                                              \
    } while (0)

    GU_LOAD(0, 0);

    const int NIT = HDIM / TK;
    for (int it = 0; it < NIT; it++) {
        cpa_wait0();
        __syncthreads();
        if (it + 1 < NIT) GU_LOAD((it + 1) & 1, (it + 1) * TK);
        unsigned stA = (it & 1) * strA;
        unsigned stB = (it & 1) * strB;

#pragma unroll
        for (int kk = 0; kk < TK; kk += 16) {
            unsigned aH[2][4], aL[2][4];
#pragma unroll
            for (int mf = 0; mf < 2; mf++) {
                ldsm4(aH[mf][0], aH[mf][1], aH[mf][2], aH[mf][3], sAh + stA + aoff[mf] + kk * 2);
                ldsm4(aL[mf][0], aL[mf][1], aL[mf][2], aL[mf][3], sAl + stA + aoff[mf] + kk * 2);
            }
#pragma unroll
            for (int nfp = 0; nfp < 2; nfp++) {
                unsigned bG[4];
                ldsm4(bG[0], bG[1], bG[2], bG[3], sBg + stB + boff[nfp] + kk * 2);
#pragma unroll
                for (int h2 = 0; h2 < 2; h2++) {
                    int nf = nfp * 2 + h2;
#pragma unroll
                    for (int mf = 0; mf < 2; mf++) {
                        mma_f16(accG[mf][nf], aH[mf], &bG[h2 * 2]);
                        mma_f16(accG[mf][nf], aL[mf], &bG[h2 * 2]);
                    }
                }
            }
#pragma unroll
            for (int nfp = 0; nfp < 2; nfp++) {
                unsigned bU[4];
                ldsm4(bU[0], bU[1], bU[2], bU[3], sBu + stB + boff[nfp] + kk * 2);
#pragma unroll
                for (int h2 = 0; h2 < 2; h2++) {
                    int nf = nfp * 2 + h2;
#pragma unroll
                    for (int mf = 0; mf < 2; mf++)
                        mma_f16(accU[mf][nf], aH[mf], &bU[h2 * 2]);   // up: hi only
                }
            }
        }
    }
#undef GU_LOAD

    // epilogue: h = silu(g) * u, single-rounded fp16
#pragma unroll
    for (int mf = 0; mf < 2; mf++) {
#pragma unroll
        for (int half = 0; half < 2; half++) {
            int lr = wm * 32 + mf * 16 + g + half * 8;
            int r = m0 + lr;
            if (r < M) {
                int p = prow[lr];
#pragma unroll
                for (int nf = 0; nf < 4; nf++) {
                    int col = n0 + wn * 32 + nf * 8 + 2 * q;
                    float gv0 = accG[mf][nf][half * 2 + 0];
                    float gv1 = accG[mf][nf][half * 2 + 1];
                    float uv0 = accU[mf][nf][half * 2 + 0];
                    float uv1 = accU[mf][nf][half * 2 + 1];
                    float hx = (gv0 / (1.f + expf(-gv0))) * uv0;
                    float hy = (gv1 / (1.f + expf(-gv1))) * uv1;
                    __half2 hv = __floats2half2_rn(hx, hy);
                    *(unsigned*)&g_hb[(size_t)p * IDIM + col] =
                        *reinterpret_cast<unsigned*>(&hv);
                }
            }
        }
    }
}

// ---------------- down GEMM (plain fp16, 1 MMA, ldmatrix + cp.async) ----------------
__global__ __launch_bounds__(256) void down_kernel() {
    int e = blockIdx.z;
    int M = g_cnt[e];
    int m0 = blockIdx.y * TM;
    if (m0 >= M) return;
    int n0 = blockIdx.x * TN;

    __shared__ __half Ah[2][TM][AP];
    __shared__ __half Bs[2][TN][AP];
    __shared__ int prow[TM];

    int tid = threadIdx.x;
    if (tid < TM) {
        int r = m0 + tid;
        prow[tid] = (r < M) ? g_pairs[e * NTOK + r] : g_pairs[e * NTOK];
    }
    __syncthreads();

    const __half* wd = g_wd + (size_t)e * HDIM * IDIM;

    int wid = tid >> 5;
    int lane = tid & 31;
    int wm = wid >> 1;
    int wn = wid & 1;
    int g = lane >> 2;
    int q = lane & 3;

    int arow = tid >> 2;
    int achk = (tid & 3) * 8;

    unsigned offA0 = (unsigned)prow[arow] * IDIM + achk;
    unsigned offA1 = (unsigned)prow[arow + 64] * IDIM + achk;
    unsigned offB  = (unsigned)(n0 + arow) * IDIM + achk;

    unsigned aoff[2];
#pragma unroll
    for (int mf = 0; mf < 2; mf++)
        aoff[mf] = ((wm * 32 + mf * 16 + (lane & 15)) * AP + ((lane >> 4) << 3)) * 2;
    unsigned boff[2];
#pragma unroll
    for (int nfp = 0; nfp < 2; nfp++)
        boff[nfp] = ((wn * 32 + nfp * 16 + ((lane >> 4) << 3) + (lane & 7)) * AP
                     + (((lane >> 3) & 1) << 3)) * 2;

    unsigned sAh = (unsigned)__cvta_generic_to_shared(&Ah[0][0][0]);
    unsigned sBs = (unsigned)__cvta_generic_to_shared(&Bs[0][0][0]);
    const unsigned strA = TM * AP * 2;
    const unsigned strB = TN * AP * 2;

    float acc[2][4][4];
#pragma unroll
    for (int i = 0; i < 2; i++)
#pragma unroll
        for (int j = 0; j < 4; j++)
#pragma unroll
            for (int c = 0; c < 4; c++) acc[i][j][c] = 0.f;

#define DN_LOAD(st, k0)                                            \
    do {                                                           \
        cpa16(&Ah[st][arow][achk],      g_hb + offA0 + (k0));      \
        cpa16(&Ah[st][arow + 64][achk], g_hb + offA1 + (k0));      \
        cpa16(&Bs[st][arow][achk],      wd + offB + (k0));         \
        cpa_commit();                                              \
    } while (0)

    DN_LOAD(0, 0);

    const int NIT = IDIM / TK;
    for (int it = 0; it < NIT; it++) {
        cpa_wait0();
        __syncthreads();
        if (it + 1 < NIT) DN_LOAD((it + 1) & 1, (it + 1) * TK);
        unsigned stA = (it & 1) * strA;
        unsigned stB = (it & 1) * strB;

#pragma unroll
        for (int kk = 0; kk < TK; kk += 16) {
            unsigned aH[2][4];
#pragma unroll
            for (int mf = 0; mf < 2; mf++)
                ldsm4(aH[mf][0], aH[mf][1], aH[mf][2], aH[mf][3], sAh + stA + aoff[mf] + kk * 2);
#pragma unroll
            for (int nfp = 0; nfp < 2; nfp++) {
                unsigned bB[4];
                ldsm4(bB[0], bB[1], bB[2], bB[3], sBs + stB + boff[nfp] + kk * 2);
#pragma unroll
                for (int h2 = 0; h2 < 2; h2++) {
                    int nf = nfp * 2 + h2;
#pragma unroll
                    for (int mf = 0; mf < 2; mf++)
                        mma_f16(acc[mf][nf], aH[mf], &bB[h2 * 2]);
                }
            }
        }
    }
#undef DN_LOAD

#pragma unroll
    for (int mf = 0; mf < 2; mf++) {
#pragma unroll
        for (int half = 0; half < 2; half++) {
            int lr = wm * 32 + mf * 16 + g + half * 8;
            int r = m0 + lr;
            if (r < M) {
                int p = prow[lr];
#pragma unroll
                for (int nf = 0; nf < 4; nf++) {
                    int col = n0 + wn * 32 + nf * 8 + 2 * q;
                    float2 o;
                    o.x = acc[mf][nf][half * 2 + 0];
                    o.y = acc[mf][nf][half * 2 + 1];
                    *(float2*)&g_ybuf[(size_t)p * HDIM + col] = o;
                }
            }
        }
    }
}

// ---------------- combine ----------------
__global__ void combine_kernel(float* __restrict__ y) {
    int idx = blockIdx.x * blockDim.x + threadIdx.x;
    int t = idx / (HDIM / 4);
    int h4 = (idx - t * (HDIM / 4)) * 4;
    float w0 = g_tokw[2 * t], w1 = g_tokw[2 * t + 1];
    float4 a = *(const float4*)&g_ybuf[(size_t)(2 * t) * HDIM + h4];
    float4 b = *(const float4*)&g_ybuf[(size_t)(2 * t + 1) * HDIM + h4];
    float4 r;
    r.x = w0 * a.x + w1 * b.x;
    r.y = w0 * a.y + w1 * b.y;
    r.z = w0 * a.z + w1 * b.z;
    r.w = w0 * a.w + w1 * b.w;
    *(float4*)&y[(size_t)t * HDIM + h4] = r;
}

// ---------------- launch ----------------
extern "C" void kernel_launch(void* const* d_in, const int* in_sizes, int n_in,
                              void* d_out, int out_size) {
    const float* x  = (const float*)d_in[0];
    const float* gw = (const float*)d_in[1];
    const float* wg = (const float*)d_in[2];
    const float* wu = (const float*)d_in[3];
    const float* wd = (const float*)d_in[4];
    float* y = (float*)d_out;

    reset_kernel<<<1, 32>>>();
    router_kernel<<<NTOK / 8, 256>>>(x, gw);
    aux_kernel<<<1, 256>>>(y + (out_size - 1));

    split_x_kernel<<<(NTOK * HDIM / 4) / 256, 256>>>(x);
    transpose_half_kernel<0><<<dim3(IDIM / 32, HDIM / 32, EEXP), 256>>>(wg, HDIM, IDIM);
    transpose_half_kernel<1><<<dim3(IDIM / 32, HDIM / 32, EEXP), 256>>>(wu, HDIM, IDIM);
    transpose_half_kernel<2><<<dim3(HDIM / 32, IDIM / 32, EEXP), 256>>>(wd, IDIM, HDIM);

    gateup_kernel<<<dim3(IDIM / TN, (NTOK * 2) / TM, EEXP), 256>>>();
    down_kernel<<<dim3(HDIM / TN, (NTOK * 2) / TM, EEXP), 256>>>();
    combine_kernel<<<(NTOK * HDIM / 4) / 256, 256>>>(y);
}

// round 11
// speedup vs baseline: 4.6285x; 1.4570x over previous
#include <cuda_runtime.h>
#include <cuda_fp16.h>
#include <math.h>

// Problem constants (fixed by setup_inputs)
#define NTOK 8192      // B*S
#define HDIM 1024
#define IDIM 2048
#define EEXP 8
#define TOPK 2

// GEMM tiling
#define TM 128
#define TN 64
#define TK 32
#define AP 40          // padded k-row length (fp16): 80B stride, conflict-free LDSM

// ---------------- device scratch ----------------
__device__ int   g_cnt[EEXP];
__device__ int   g_pairs[EEXP * NTOK];
__device__ float g_tokw[NTOK * 2];
__device__ int   g_toke[NTOK * 2];
__device__ float g_selw[NTOK * 2];

// all GEMM operands single-rounded fp16
__device__ __half g_xh[NTOK * HDIM];
__device__ __half g_wg[EEXP * IDIM * HDIM];   // gate, transposed [e][i][h]
__device__ __half g_wu[EEXP * IDIM * HDIM];   // up, transposed [e][i][h]
__device__ __half g_wd[EEXP * HDIM * IDIM];   // down, transposed [e][h][i]
__device__ __half g_hb[NTOK * 2 * IDIM];      // silu(g)*u (fp16)  [pair][I]
__device__ float g_ybuf[NTOK * 2 * HDIM];     // expert outputs [pair][H]

// ---------------- helpers ----------------
__device__ __forceinline__ void mma_f16(float *d, const unsigned *a, const unsigned *b) {
    asm volatile("mma.sync.aligned.m16n8k16.row.col.f32.f16.f16.f32 "
        "{%0,%1,%2,%3}, {%4,%5,%6,%7}, {%8,%9}, {%0,%1,%2,%3};\n"
        : "+f"(d[0]), "+f"(d[1]), "+f"(d[2]), "+f"(d[3])
        : "r"(a[0]), "r"(a[1]), "r"(a[2]), "r"(a[3]), "r"(b[0]), "r"(b[1]));
}

__device__ __forceinline__ void ldsm4(unsigned &r0, unsigned &r1, unsigned &r2, unsigned &r3,
                                      unsigned a) {
    asm volatile("ldmatrix.sync.aligned.m8n8.x4.shared.b16 {%0,%1,%2,%3}, [%4];\n"
        : "=r"(r0), "=r"(r1), "=r"(r2), "=r"(r3) : "r"(a));
}

__device__ __forceinline__ void cpa16(void* smem, const void* g) {
    unsigned s = (unsigned)__cvta_generic_to_shared(smem);
    asm volatile("cp.async.cg.shared.global [%0], [%1], 16;\n" :: "r"(s), "l"(g));
}
__device__ __forceinline__ void cpa_commit() {
    asm volatile("cp.async.commit_group;\n");
}
__device__ __forceinline__ void cpa_wait0() {
    asm volatile("cp.async.wait_group 0;\n");
}

// ---------------- reset ----------------
__global__ void reset_kernel() {
    if (threadIdx.x < EEXP) g_cnt[threadIdx.x] = 0;
}

// ---------------- convert x to fp16 ----------------
__global__ void split_x_kernel(const float* __restrict__ x) {
    int idx = blockIdx.x * blockDim.x + threadIdx.x;
    float4 v = ((const float4*)x)[idx];
    __half2 h0 = __floats2half2_rn(v.x, v.y);
    __half2 h1 = __floats2half2_rn(v.z, v.w);
    uint2 hh;
    hh.x = *reinterpret_cast<unsigned*>(&h0);
    hh.y = *reinterpret_cast<unsigned*>(&h1);
    ((uint2*)g_xh)[idx] = hh;
}

// ---------------- transpose weights to fp16: src [E][R][C] -> dst [E][C][R] ----------------
// W selects destinations IN DEVICE CODE (never pass __device__ globals from host:
// that passes the host shadow symbol; ATS silently dereferences host memory).
template<int W>
__global__ void transpose_half_kernel(const float* __restrict__ src, int R, int C) {
    __half* dh = (W == 0) ? g_wg : (W == 1) ? g_wu : g_wd;
    __shared__ float s[32][33];
    int e = blockIdx.z;
    int r0 = blockIdx.y * 32, c0 = blockIdx.x * 32;
    int tx = threadIdx.x & 31, ty = threadIdx.x >> 5;
    const float* sp = src + ((size_t)e * R + r0) * C + c0;
#pragma unroll
    for (int j = 0; j < 4; j++)
        s[ty + j * 8][tx] = sp[(size_t)(ty + j * 8) * C + tx];
    __syncthreads();
    size_t dbase = ((size_t)e * C + c0) * R + r0;
#pragma unroll
    for (int j = 0; j < 4; j++)
        dh[dbase + (size_t)(ty + j * 8) * R + tx] = __float2half(s[tx][ty + j * 8]);
}

// ---------------- router: one warp per token ----------------
__global__ void router_kernel(const float* __restrict__ x,
                              const float* __restrict__ gw) {
    int t = blockIdx.x * (blockDim.x >> 5) + (threadIdx.x >> 5);
    int lane = threadIdx.x & 31;
    if (t >= NTOK) return;
    const float* xr = x + (size_t)t * HDIM;
    float acc[EEXP];
#pragma unroll
    for (int e = 0; e < EEXP; e++) acc[e] = 0.f;
    for (int h = lane; h < HDIM; h += 32) {
        float xv = xr[h];
        const float* g = gw + h * EEXP;
#pragma unroll
        for (int e = 0; e < EEXP; e++) acc[e] = fmaf(xv, g[e], acc[e]);
    }
#pragma unroll
    for (int off = 16; off > 0; off >>= 1) {
#pragma unroll
        for (int e = 0; e < EEXP; e++)
            acc[e] += __shfl_down_sync(0xffffffffu, acc[e], off);
    }
    if (lane == 0) {
        float mx = acc[0];
#pragma unroll
        for (int e = 1; e < EEXP; e++) mx = fmaxf(mx, acc[e]);
        float p[EEXP];
        float s = 0.f;
#pragma unroll
        for (int e = 0; e < EEXP; e++) { p[e] = expf(acc[e] - mx); s += p[e]; }
        float inv = 1.f / s;
#pragma unroll
        for (int e = 0; e < EEXP; e++) p[e] *= inv;
        int e0 = 0;
#pragma unroll
        for (int e = 1; e < EEXP; e++) if (p[e] > p[e0]) e0 = e;
        int e1 = (e0 == 0) ? 1 : 0;
#pragma unroll
        for (int e = 0; e < EEXP; e++) if (e != e0 && p[e] > p[e1]) e1 = e;
        float w0 = p[e0], w1 = p[e1];
        float rs = 1.f / (w0 + w1);
        g_toke[2 * t] = e0;      g_toke[2 * t + 1] = e1;
        g_selw[2 * t] = w0;      g_selw[2 * t + 1] = w1;
        g_tokw[2 * t] = w0 * rs; g_tokw[2 * t + 1] = w1 * rs;
        int p0 = atomicAdd(&g_cnt[e0], 1);
        g_pairs[e0 * NTOK + p0] = 2 * t;
        int p1 = atomicAdd(&g_cnt[e1], 1);
        g_pairs[e1 * NTOK + p1] = 2 * t + 1;
    }
}

// ---------------- aux loss ----------------
__global__ void aux_kernel(float* __restrict__ out_aux) {
    __shared__ float sload[256][EEXP];
    int tid = threadIdx.x;
    float l[EEXP];
#pragma unroll
    for (int e = 0; e < EEXP; e++) l[e] = 0.f;
    for (int a = tid; a < NTOK * 2; a += 256)
        l[g_toke[a]] += g_selw[a];
#pragma unroll
    for (int e = 0; e < EEXP; e++) sload[tid][e] = l[e];
    __syncthreads();
    for (int s = 128; s > 0; s >>= 1) {
        if (tid < s) {
#pragma unroll
            for (int e = 0; e < EEXP; e++) sload[tid][e] += sload[tid + s][e];
        }
        __syncthreads();
    }
    if (tid == 0) {
        float aux = 0.f;
#pragma unroll
        for (int e = 0; e < EEXP; e++) {
            float pe = sload[0][e] / (float)NTOK;
            float pt = (float)g_cnt[e] / (float)(NTOK * TOPK);
            aux += pe * pt;
        }
        aux *= (float)EEXP * 1e-3f;
        *out_aux = aux;
    }
}

// ---------------- gate+up GEMM (plain fp16, 1 MMA each; ldmatrix + cp.async) ----------------
__global__ __launch_bounds__(256) void gateup_kernel() {
    int e = blockIdx.z;
    int M = g_cnt[e];
    int m0 = blockIdx.y * TM;
    if (m0 >= M) return;
    int n0 = blockIdx.x * TN;

    __shared__ __half Ah[2][TM][AP];
    __shared__ __half Bg[2][TN][AP], Bu[2][TN][AP];
    __shared__ int prow[TM];
    __shared__ int toks[TM];

    int tid = threadIdx.x;
    if (tid < TM) {
        int r = m0 + tid;
        int pr = (r < M) ? g_pairs[e * NTOK + r] : g_pairs[e * NTOK];
        prow[tid] = pr;
        toks[tid] = pr >> 1;
    }
    __syncthreads();

    const __half* wg = g_wg + (size_t)e * IDIM * HDIM;
    const __half* wu = g_wu + (size_t)e * IDIM * HDIM;

    int wid = tid >> 5;
    int lane = tid & 31;
    int wm = wid >> 1;
    int wn = wid & 1;
    int g = lane >> 2;
    int q = lane & 3;

    int arow = tid >> 2;            // 0..63
    int achk = (tid & 3) * 8;

    unsigned offA0 = (unsigned)toks[arow] * HDIM + achk;
    unsigned offA1 = (unsigned)toks[arow + 64] * HDIM + achk;
    unsigned offB  = (unsigned)(n0 + arow) * HDIM + achk;

    unsigned aoff[2];
#pragma unroll
    for (int mf = 0; mf < 2; mf++)
        aoff[mf] = ((wm * 32 + mf * 16 + (lane & 15)) * AP + ((lane >> 4) << 3)) * 2;
    unsigned boff[2];
#pragma unroll
    for (int nfp = 0; nfp < 2; nfp++)
        boff[nfp] = ((wn * 32 + nfp * 16 + ((lane >> 4) << 3) + (lane & 7)) * AP
                     + (((lane >> 3) & 1) << 3)) * 2;

    unsigned sAh = (unsigned)__cvta_generic_to_shared(&Ah[0][0][0]);
    unsigned sBg = (unsigned)__cvta_generic_to_shared(&Bg[0][0][0]);
    unsigned sBu = (unsigned)__cvta_generic_to_shared(&Bu[0][0][0]);
    const unsigned strA = TM * AP * 2;
    const unsigned strB = TN * AP * 2;

    float accG[2][4][4], accU[2][4][4];
#pragma unroll
    for (int i = 0; i < 2; i++)
#pragma unroll
        for (int j = 0; j < 4; j++)
#pragma unroll
            for (int c = 0; c < 4; c++) { accG[i][j][c] = 0.f; accU[i][j][c] = 0.f; }

#define GU_LOAD(st, k0)                                            \
    do {                                                           \
        cpa16(&Ah[st][arow][achk],      g_xh + offA0 + (k0));      \
        cpa16(&Ah[st][arow + 64][achk], g_xh + offA1 + (k0));      \
        cpa16(&Bg[st][arow][achk],      wg + offB + (k0));         \
        cpa16(&Bu[st][arow][achk],      wu + offB + (k0));         \
        cpa_commit();                                              \
    } while (0)

    GU_LOAD(0, 0);

    const int NIT = HDIM / TK;
    for (int it = 0; it < NIT; it++) {
        cpa_wait0();
        __syncthreads();
        if (it + 1 < NIT) GU_LOAD((it + 1) & 1, (it + 1) * TK);
        unsigned stA = (it & 1) * strA;
        unsigned stB = (it & 1) * strB;

#pragma unroll
        for (int kk = 0; kk < TK; kk += 16) {
            unsigned aH[2][4];
#pragma unroll
            for (int mf = 0; mf < 2; mf++)
                ldsm4(aH[mf][0], aH[mf][1], aH[mf][2], aH[mf][3], sAh + stA + aoff[mf] + kk * 2);
#pragma unroll
            for (int nfp = 0; nfp < 2; nfp++) {
                unsigned bG[4];
                ldsm4(bG[0], bG[1], bG[2], bG[3], sBg + stB + boff[nfp] + kk * 2);
#pragma unroll
                for (int h2 = 0; h2 < 2; h2++) {
                    int nf = nfp * 2 + h2;
#pragma unroll
                    for (int mf = 0; mf < 2; mf++)
                        mma_f16(accG[mf][nf], aH[mf], &bG[h2 * 2]);
                }
            }
#pragma unroll
            for (int nfp = 0; nfp < 2; nfp++) {
                unsigned bU[4];
                ldsm4(bU[0], bU[1], bU[2], bU[3], sBu + stB + boff[nfp] + kk * 2);
#pragma unroll
                for (int h2 = 0; h2 < 2; h2++) {
                    int nf = nfp * 2 + h2;
#pragma unroll
                    for (int mf = 0; mf < 2; mf++)
                        mma_f16(accU[mf][nf], aH[mf], &bU[h2 * 2]);
                }
            }
        }
    }
#undef GU_LOAD

    // epilogue: h = silu(g) * u, single-rounded fp16
#pragma unroll
    for (int mf = 0; mf < 2; mf++) {
#pragma unroll
        for (int half = 0; half < 2; half++) {
            int lr = wm * 32 + mf * 16 + g + half * 8;
            int r = m0 + lr;
            if (r < M) {
                int p = prow[lr];
#pragma unroll
                for (int nf = 0; nf < 4; nf++) {
                    int col = n0 + wn * 32 + nf * 8 + 2 * q;
                    float gv0 = accG[mf][nf][half * 2 + 0];
                    float gv1 = accG[mf][nf][half * 2 + 1];
                    float uv0 = accU[mf][nf][half * 2 + 0];
                    float uv1 = accU[mf][nf][half * 2 + 1];
                    float hx = (gv0 / (1.f + expf(-gv0))) * uv0;
                    float hy = (gv1 / (1.f + expf(-gv1))) * uv1;
                    __half2 hv = __floats2half2_rn(hx, hy);
                    *(unsigned*)&g_hb[(size_t)p * IDIM + col] =
                        *reinterpret_cast<unsigned*>(&hv);
                }
            }
        }
    }
}

// ---------------- down GEMM (plain fp16, 1 MMA, ldmatrix + cp.async) ----------------
__global__ __launch_bounds__(256) void down_kernel() {
    int e = blockIdx.z;
    int M = g_cnt[e];
    int m0 = blockIdx.y * TM;
    if (m0 >= M) return;
    int n0 = blockIdx.x * TN;

    __shared__ __half Ah[2][TM][AP];
    __shared__ __half Bs[2][TN][AP];
    __shared__ int prow[TM];

    int tid = threadIdx.x;
    if (tid < TM) {
        int r = m0 + tid;
        prow[tid] = (r < M) ? g_pairs[e * NTOK + r] : g_pairs[e * NTOK];
    }
    __syncthreads();

    const __half* wd = g_wd + (size_t)e * HDIM * IDIM;

    int wid = tid >> 5;
    int lane = tid & 31;
    int wm = wid >> 1;
    int wn = wid & 1;
    int g = lane >> 2;
    int q = lane & 3;

    int arow = tid >> 2;
    int achk = (tid & 3) * 8;

    unsigned offA0 = (unsigned)prow[arow] * IDIM + achk;
    unsigned offA1 = (unsigned)prow[arow + 64] * IDIM + achk;
    unsigned offB  = (unsigned)(n0 + arow) * IDIM + achk;

    unsigned aoff[2];
#pragma unroll
    for (int mf = 0; mf < 2; mf++)
        aoff[mf] = ((wm * 32 + mf * 16 + (lane & 15)) * AP + ((lane >> 4) << 3)) * 2;
    unsigned boff[2];
#pragma unroll
    for (int nfp = 0; nfp < 2; nfp++)
        boff[nfp] = ((wn * 32 + nfp * 16 + ((lane >> 4) << 3) + (lane & 7)) * AP
                     + (((lane >> 3) & 1) << 3)) * 2;

    unsigned sAh = (unsigned)__cvta_generic_to_shared(&Ah[0][0][0]);
    unsigned sBs = (unsigned)__cvta_generic_to_shared(&Bs[0][0][0]);
    const unsigned strA = TM * AP * 2;
    const unsigned strB = TN * AP * 2;

    float acc[2][4][4];
#pragma unroll
    for (int i = 0; i < 2; i++)
#pragma unroll
        for (int j = 0; j < 4; j++)
#pragma unroll
            for (int c = 0; c < 4; c++) acc[i][j][c] = 0.f;

#define DN_LOAD(st, k0)                                            \
    do {                                                           \
        cpa16(&Ah[st][arow][achk],      g_hb + offA0 + (k0));      \
        cpa16(&Ah[st][arow + 64][achk], g_hb + offA1 + (k0));      \
        cpa16(&Bs[st][arow][achk],      wd + offB + (k0));         \
        cpa_commit();                                              \
    } while (0)

    DN_LOAD(0, 0);

    const int NIT = IDIM / TK;
    for (int it = 0; it < NIT; it++) {
        cpa_wait0();
        __syncthreads();
        if (it + 1 < NIT) DN_LOAD((it + 1) & 1, (it + 1) * TK);
        unsigned stA = (it & 1) * strA;
        unsigned stB = (it & 1) * strB;

#pragma unroll
        for (int kk = 0; kk < TK; kk += 16) {
            unsigned aH[2][4];
#pragma unroll
            for (int mf = 0; mf < 2; mf++)
                ldsm4(aH[mf][0], aH[mf][1], aH[mf][2], aH[mf][3], sAh + stA + aoff[mf] + kk * 2);
#pragma unroll
            for (int nfp = 0; nfp < 2; nfp++) {
                unsigned bB[4];
                ldsm4(bB[0], bB[1], bB[2], bB[3], sBs + stB + boff[nfp] + kk * 2);
#pragma unroll
                for (int h2 = 0; h2 < 2; h2++) {
                    int nf = nfp * 2 + h2;
#pragma unroll
                    for (int mf = 0; mf < 2; mf++)
                        mma_f16(acc[mf][nf], aH[mf], &bB[h2 * 2]);
                }
            }
        }
    }
#undef DN_LOAD

#pragma unroll
    for (int mf = 0; mf < 2; mf++) {
#pragma unroll
        for (int half = 0; half < 2; half++) {
            int lr = wm * 32 + mf * 16 + g + half * 8;
            int r = m0 + lr;
            if (r < M) {
                int p = prow[lr];
#pragma unroll
                for (int nf = 0; nf < 4; nf++) {
                    int col = n0 + wn * 32 + nf * 8 + 2 * q;
                    float2 o;
                    o.x = acc[mf][nf][half * 2 + 0];
                    o.y = acc[mf][nf][half * 2 + 1];
                    *(float2*)&g_ybuf[(size_t)p * HDIM + col] = o;
                }
            }
        }
    }
}

// ---------------- combine ----------------
__global__ void combine_kernel(float* __restrict__ y) {
    int idx = blockIdx.x * blockDim.x + threadIdx.x;
    int t = idx / (HDIM / 4);
    int h4 = (idx - t * (HDIM / 4)) * 4;
    float w0 = g_tokw[2 * t], w1 = g_tokw[2 * t + 1];
    float4 a = *(const float4*)&g_ybuf[(size_t)(2 * t) * HDIM + h4];
    float4 b = *(const float4*)&g_ybuf[(size_t)(2 * t + 1) * HDIM + h4];
    float4 r;
    r.x = w0 * a.x + w1 * b.x;
    r.y = w0 * a.y + w1 * b.y;
    r.z = w0 * a.z + w1 * b.z;
    r.w = w0 * a.w + w1 * b.w;
    *(float4*)&y[(size_t)t * HDIM + h4] = r;
}

// ---------------- launch ----------------
extern "C" void kernel_launch(void* const* d_in, const int* in_sizes, int n_in,
                              void* d_out, int out_size) {
    const float* x  = (const float*)d_in[0];
    const float* gw = (const float*)d_in[1];
    const float* wg = (const float*)d_in[2];
    const float* wu = (const float*)d_in[3];
    const float* wd = (const float*)d_in[4];
    float* y = (float*)d_out;

    reset_kernel<<<1, 32>>>();
    router_kernel<<<NTOK / 8, 256>>>(x, gw);
    aux_kernel<<<1, 256>>>(y + (out_size - 1));

    split_x_kernel<<<(NTOK * HDIM / 4) / 256, 256>>>(x);
    transpose_half_kernel<0><<<dim3(IDIM / 32, HDIM / 32, EEXP), 256>>>(wg, HDIM, IDIM);
    transpose_half_kernel<1><<<dim3(IDIM / 32, HDIM / 32, EEXP), 256>>>(wu, HDIM, IDIM);
    transpose_half_kernel<2><<<dim3(HDIM / 32, IDIM / 32, EEXP), 256>>>(wd, IDIM, HDIM);

    gateup_kernel<<<dim3(IDIM / TN, (NTOK * 2) / TM, EEXP), 256>>>();
    down_kernel<<<dim3(HDIM / TN, (NTOK * 2) / TM, EEXP), 256>>>();
    combine_kernel<<<(NTOK * HDIM / 4) / 256, 256>>>(y);
}

// round 12
// speedup vs baseline: 4.6506x; 1.0048x over previous
#include <cuda_runtime.h>
#include <cuda_fp16.h>
#include <math.h>

// Problem constants (fixed by setup_inputs)
#define NTOK 8192      // B*S
#define HDIM 1024
#define IDIM 2048
#define EEXP 8
#define TOPK 2

// GEMM tiling
#define TM 128
#define TN 128
#define TK 32
#define AP 40          // padded k-row length (fp16): 80B stride, conflict-free LDSM

#define GU_SMEM (1024 + 3 * 2 * TM * AP * 2)   // prow/toks + Ah,Bg,Bu double-buffered

// ---------------- device scratch ----------------
__device__ int   g_cnt[EEXP];
__device__ int   g_pairs[EEXP * NTOK];
__device__ float g_tokw[NTOK * 2];
__device__ int   g_toke[NTOK * 2];
__device__ float g_selw[NTOK * 2];

// all GEMM operands single-rounded fp16
__device__ __half g_xh[NTOK * HDIM];
__device__ __half g_wg[EEXP * IDIM * HDIM];   // gate, transposed [e][i][h]
__device__ __half g_wu[EEXP * IDIM * HDIM];   // up, transposed [e][i][h]
__device__ __half g_wd[EEXP * HDIM * IDIM];   // down, transposed [e][h][i]
__device__ __half g_hb[NTOK * 2 * IDIM];      // silu(g)*u (fp16)  [pair][I]
__device__ float g_ybuf[NTOK * 2 * HDIM];     // expert outputs [pair][H]

// ---------------- helpers ----------------
__device__ __forceinline__ void mma_f16(float *d, const unsigned *a, const unsigned *b) {
    asm volatile("mma.sync.aligned.m16n8k16.row.col.f32.f16.f16.f32 "
        "{%0,%1,%2,%3}, {%4,%5,%6,%7}, {%8,%9}, {%0,%1,%2,%3};\n"
        : "+f"(d[0]), "+f"(d[1]), "+f"(d[2]), "+f"(d[3])
        : "r"(a[0]), "r"(a[1]), "r"(a[2]), "r"(a[3]), "r"(b[0]), "r"(b[1]));
}

__device__ __forceinline__ void ldsm4(unsigned &r0, unsigned &r1, unsigned &r2, unsigned &r3,
                                      unsigned a) {
    asm volatile("ldmatrix.sync.aligned.m8n8.x4.shared.b16 {%0,%1,%2,%3}, [%4];\n"
        : "=r"(r0), "=r"(r1), "=r"(r2), "=r"(r3) : "r"(a));
}

__device__ __forceinline__ void cpa16(void* smem, const void* g) {
    unsigned s = (unsigned)__cvta_generic_to_shared(smem);
    asm volatile("cp.async.cg.shared.global [%0], [%1], 16;\n" :: "r"(s), "l"(g));
}
__device__ __forceinline__ void cpa_commit() {
    asm volatile("cp.async.commit_group;\n");
}
__device__ __forceinline__ void cpa_wait0() {
    asm volatile("cp.async.wait_group 0;\n");
}

// ---------------- reset ----------------
__global__ void reset_kernel() {
    if (threadIdx.x < EEXP) g_cnt[threadIdx.x] = 0;
}

// ---------------- convert x to fp16 ----------------
__global__ void split_x_kernel(const float* __restrict__ x) {
    int idx = blockIdx.x * blockDim.x + threadIdx.x;
    float4 v = ((const float4*)x)[idx];
    __half2 h0 = __floats2half2_rn(v.x, v.y);
    __half2 h1 = __floats2half2_rn(v.z, v.w);
    uint2 hh;
    hh.x = *reinterpret_cast<unsigned*>(&h0);
    hh.y = *reinterpret_cast<unsigned*>(&h1);
    ((uint2*)g_xh)[idx] = hh;
}

// ---------------- transpose weights to fp16: src [E][R][C] -> dst [E][C][R] ----------------
// W selects destinations IN DEVICE CODE (never pass __device__ globals from host:
// that passes the host shadow symbol; ATS silently dereferences host memory).
template<int W>
__global__ void transpose_half_kernel(const float* __restrict__ src, int R, int C) {
    __half* dh = (W == 0) ? g_wg : (W == 1) ? g_wu : g_wd;
    __shared__ float s[32][33];
    int e = blockIdx.z;
    int r0 = blockIdx.y * 32, c0 = blockIdx.x * 32;
    int tx = threadIdx.x & 31, ty = threadIdx.x >> 5;
    const float* sp = src + ((size_t)e * R + r0) * C + c0;
#pragma unroll
    for (int j = 0; j < 4; j++)
        s[ty + j * 8][tx] = sp[(size_t)(ty + j * 8) * C + tx];
    __syncthreads();
    size_t dbase = ((size_t)e * C + c0) * R + r0;
#pragma unroll
    for (int j = 0; j < 4; j++)
        dh[dbase + (size_t)(ty + j * 8) * R + tx] = __float2half(s[tx][ty + j * 8]);
}

// ---------------- router: one warp per token ----------------
__global__ void router_kernel(const float* __restrict__ x,
                              const float* __restrict__ gw) {
    int t = blockIdx.x * (blockDim.x >> 5) + (threadIdx.x >> 5);
    int lane = threadIdx.x & 31;
    if (t >= NTOK) return;
    const float* xr = x + (size_t)t * HDIM;
    float acc[EEXP];
#pragma unroll
    for (int e = 0; e < EEXP; e++) acc[e] = 0.f;
    for (int h = lane; h < HDIM; h += 32) {
        float xv = xr[h];
        const float* g = gw + h * EEXP;
#pragma unroll
        for (int e = 0; e < EEXP; e++) acc[e] = fmaf(xv, g[e], acc[e]);
    }
#pragma unroll
    for (int off = 16; off > 0; off >>= 1) {
#pragma unroll
        for (int e = 0; e < EEXP; e++)
            acc[e] += __shfl_down_sync(0xffffffffu, acc[e], off);
    }
    if (lane == 0) {
        float mx = acc[0];
#pragma unroll
        for (int e = 1; e < EEXP; e++) mx = fmaxf(mx, acc[e]);
        float p[EEXP];
        float s = 0.f;
#pragma unroll
        for (int e = 0; e < EEXP; e++) { p[e] = expf(acc[e] - mx); s += p[e]; }
        float inv = 1.f / s;
#pragma unroll
        for (int e = 0; e < EEXP; e++) p[e] *= inv;
        int e0 = 0;
#pragma unroll
        for (int e = 1; e < EEXP; e++) if (p[e] > p[e0]) e0 = e;
        int e1 = (e0 == 0) ? 1 : 0;
#pragma unroll
        for (int e = 0; e < EEXP; e++) if (e != e0 && p[e] > p[e1]) e1 = e;
        float w0 = p[e0], w1 = p[e1];
        float rs = 1.f / (w0 + w1);
        g_toke[2 * t] = e0;      g_toke[2 * t + 1] = e1;
        g_selw[2 * t] = w0;      g_selw[2 * t + 1] = w1;
        g_tokw[2 * t] = w0 * rs; g_tokw[2 * t + 1] = w1 * rs;
        int p0 = atomicAdd(&g_cnt[e0], 1);
        g_pairs[e0 * NTOK + p0] = 2 * t;
        int p1 = atomicAdd(&g_cnt[e1], 1);
        g_pairs[e1 * NTOK + p1] = 2 * t + 1;
    }
}

// ---------------- aux loss ----------------
__global__ void aux_kernel(float* __restrict__ out_aux) {
    __shared__ float sload[256][EEXP];
    int tid = threadIdx.x;
    float l[EEXP];
#pragma unroll
    for (int e = 0; e < EEXP; e++) l[e] = 0.f;
    for (int a = tid; a < NTOK * 2; a += 256)
        l[g_toke[a]] += g_selw[a];
#pragma unroll
    for (int e = 0; e < EEXP; e++) sload[tid][e] = l[e];
    __syncthreads();
    for (int s = 128; s > 0; s >>= 1) {
        if (tid < s) {
#pragma unroll
            for (int e = 0; e < EEXP; e++) sload[tid][e] += sload[tid + s][e];
        }
        __syncthreads();
    }
    if (tid == 0) {
        float aux = 0.f;
#pragma unroll
        for (int e = 0; e < EEXP; e++) {
            float pe = sload[0][e] / (float)NTOK;
            float pt = (float)g_cnt[e] / (float)(NTOK * TOPK);
            aux += pe * pt;
        }
        aux *= (float)EEXP * 1e-3f;
        *out_aux = aux;
    }
}

// ---------------- gate+up GEMM (fp16, 128x128 tile, ldmatrix + cp.async) ----------------
__global__ __launch_bounds__(256) void gateup_kernel() {
    extern __shared__ char sm[];
    int e = blockIdx.z;
    int M = g_cnt[e];
    int m0 = blockIdx.y * TM;
    if (m0 >= M) return;
    int n0 = blockIdx.x * TN;

    int* prow = (int*)sm;
    int* toks = (int*)(sm + 512);
    __half* Ah = (__half*)(sm + 1024);
    __half* Bg = Ah + 2 * TM * AP;
    __half* Bu = Bg + 2 * TM * AP;

    int tid = threadIdx.x;
    if (tid < TM) {
        int r = m0 + tid;
        int pr = (r < M) ? g_pairs[e * NTOK + r] : g_pairs[e * NTOK];
        prow[tid] = pr;
        toks[tid] = pr >> 1;
    }
    __syncthreads();

    const __half* wg = g_wg + (size_t)e * IDIM * HDIM;
    const __half* wu = g_wu + (size_t)e * IDIM * HDIM;

    int wid = tid >> 5;
    int lane = tid & 31;
    int wm = wid >> 1;          // 0..3: 32 rows each
    int wn = wid & 1;           // 0..1: 64 cols each
    int g = lane >> 2;
    int q = lane & 3;

    int arow = tid >> 2;        // 0..63
    int achk = (tid & 3) * 8;

    unsigned offA0 = (unsigned)toks[arow] * HDIM + achk;
    unsigned offA1 = (unsigned)toks[arow + 64] * HDIM + achk;
    unsigned offB0 = (unsigned)(n0 + arow) * HDIM + achk;
    unsigned offB1 = (unsigned)(n0 + arow + 64) * HDIM + achk;

    unsigned aoff[2];
#pragma unroll
    for (int mf = 0; mf < 2; mf++)
        aoff[mf] = ((wm * 32 + mf * 16 + (lane & 15)) * AP + ((lane >> 4) << 3)) * 2;
    unsigned boff[4];
#pragma unroll
    for (int nfp = 0; nfp < 4; nfp++)
        boff[nfp] = ((wn * 64 + nfp * 16 + ((lane >> 4) << 3) + (lane & 7)) * AP
                     + (((lane >> 3) & 1) << 3)) * 2;

    unsigned sAh = (unsigned)__cvta_generic_to_shared(Ah);
    unsigned sBg = (unsigned)__cvta_generic_to_shared(Bg);
    unsigned sBu = (unsigned)__cvta_generic_to_shared(Bu);
    const unsigned str = TM * AP * 2;

    float accG[2][8][4], accU[2][8][4];
#pragma unroll
    for (int i = 0; i < 2; i++)
#pragma unroll
        for (int j = 0; j < 8; j++)
#pragma unroll
            for (int c = 0; c < 4; c++) { accG[i][j][c] = 0.f; accU[i][j][c] = 0.f; }

#define GU_LOAD(st, k0)                                                    \
    do {                                                                   \
        __half* a = Ah + (st) * TM * AP;                                   \
        __half* bg = Bg + (st) * TM * AP;                                  \
        __half* bu = Bu + (st) * TM * AP;                                  \
        cpa16(a + arow * AP + achk,        g_xh + offA0 + (k0));           \
        cpa16(a + (arow + 64) * AP + achk, g_xh + offA1 + (k0));           \
        cpa16(bg + arow * AP + achk,        wg + offB0 + (k0));            \
        cpa16(bg + (arow + 64) * AP + achk, wg + offB1 + (k0));            \
        cpa16(bu + arow * AP + achk,        wu + offB0 + (k0));            \
        cpa16(bu + (arow + 64) * AP + achk, wu + offB1 + (k0));            \
        cpa_commit();                                                      \
    } while (0)

    GU_LOAD(0, 0);

    const int NIT = HDIM / TK;
    for (int it = 0; it < NIT; it++) {
        cpa_wait0();
        __syncthreads();
        if (it + 1 < NIT) GU_LOAD((it + 1) & 1, (it + 1) * TK);
        unsigned st = (it & 1) * str;

#pragma unroll
        for (int kk = 0; kk < TK; kk += 16) {
            unsigned aH[2][4];
#pragma unroll
            for (int mf = 0; mf < 2; mf++)
                ldsm4(aH[mf][0], aH[mf][1], aH[mf][2], aH[mf][3], sAh + st + aoff[mf] + kk * 2);
#pragma unroll
            for (int nfp = 0; nfp < 4; nfp++) {
                unsigned bG[4];
                ldsm4(bG[0], bG[1], bG[2], bG[3], sBg + st + boff[nfp] + kk * 2);
#pragma unroll
                for (int h2 = 0; h2 < 2; h2++) {
                    int nf = nfp * 2 + h2;
#pragma unroll
                    for (int mf = 0; mf < 2; mf++)
                        mma_f16(accG[mf][nf], aH[mf], &bG[h2 * 2]);
                }
            }
#pragma unroll
            for (int nfp = 0; nfp < 4; nfp++) {
                unsigned bU[4];
                ldsm4(bU[0], bU[1], bU[2], bU[3], sBu + st + boff[nfp] + kk * 2);
#pragma unroll
                for (int h2 = 0; h2 < 2; h2++) {
                    int nf = nfp * 2 + h2;
#pragma unroll
                    for (int mf = 0; mf < 2; mf++)
                        mma_f16(accU[mf][nf], aH[mf], &bU[h2 * 2]);
                }
            }
        }
    }
#undef GU_LOAD

    // epilogue: h = silu(g) * u, single-rounded fp16
#pragma unroll
    for (int mf = 0; mf < 2; mf++) {
#pragma unroll
        for (int half = 0; half < 2; half++) {
            int lr = wm * 32 + mf * 16 + g + half * 8;
            int r = m0 + lr;
            if (r < M) {
                int p = prow[lr];
#pragma unroll
                for (int nf = 0; nf < 8; nf++) {
                    int col = n0 + wn * 64 + nf * 8 + 2 * q;
                    float gv0 = accG[mf][nf][half * 2 + 0];
                    float gv1 = accG[mf][nf][half * 2 + 1];
                    float uv0 = accU[mf][nf][half * 2 + 0];
                    float uv1 = accU[mf][nf][half * 2 + 1];
                    float hx = (gv0 / (1.f + expf(-gv0))) * uv0;
                    float hy = (gv1 / (1.f + expf(-gv1))) * uv1;
                    __half2 hv = __floats2half2_rn(hx, hy);
                    *(unsigned*)&g_hb[(size_t)p * IDIM + col] =
                        *reinterpret_cast<unsigned*>(&hv);
                }
            }
        }
    }
}

// ---------------- down GEMM (fp16, 128x128 tile, ldmatrix + cp.async) ----------------
__global__ __launch_bounds__(256) void down_kernel() {
    int e = blockIdx.z;
    int M = g_cnt[e];
    int m0 = blockIdx.y * TM;
    if (m0 >= M) return;
    int n0 = blockIdx.x * TN;

    __shared__ __half Ah[2][TM][AP];
    __shared__ __half Bs[2][TN][AP];
    __shared__ int prow[TM];

    int tid = threadIdx.x;
    if (tid < TM) {
        int r = m0 + tid;
        prow[tid] = (r < M) ? g_pairs[e * NTOK + r] : g_pairs[e * NTOK];
    }
    __syncthreads();

    const __half* wd = g_wd + (size_t)e * HDIM * IDIM;

    int wid = tid >> 5;
    int lane = tid & 31;
    int wm = wid >> 1;
    int wn = wid & 1;
    int g = lane >> 2;
    int q = lane & 3;

    int arow = tid >> 2;
    int achk = (tid & 3) * 8;

    unsigned offA0 = (unsigned)prow[arow] * IDIM + achk;
    unsigned offA1 = (unsigned)prow[arow + 64] * IDIM + achk;
    unsigned offB0 = (unsigned)(n0 + arow) * IDIM + achk;
    unsigned offB1 = (unsigned)(n0 + arow + 64) * IDIM + achk;

    unsigned aoff[2];
#pragma unroll
    for (int mf = 0; mf < 2; mf++)
        aoff[mf] = ((wm * 32 + mf * 16 + (lane & 15)) * AP + ((lane >> 4) << 3)) * 2;
    unsigned boff[4];
#pragma unroll
    for (int nfp = 0; nfp < 4; nfp++)
        boff[nfp] = ((wn * 64 + nfp * 16 + ((lane >> 4) << 3) + (lane & 7)) * AP
                     + (((lane >> 3) & 1) << 3)) * 2;

    unsigned sAh = (unsigned)__cvta_generic_to_shared(&Ah[0][0][0]);
    unsigned sBs = (unsigned)__cvta_generic_to_shared(&Bs[0][0][0]);
    const unsigned str = TM * AP * 2;

    float acc[2][8][4];
#pragma unroll
    for (int i = 0; i < 2; i++)
#pragma unroll
        for (int j = 0; j < 8; j++)
#pragma unroll
            for (int c = 0; c < 4; c++) acc[i][j][c] = 0.f;

#define DN_LOAD(st, k0)                                                    \
    do {                                                                   \
        cpa16(&Ah[st][arow][achk],      g_hb + offA0 + (k0));              \
        cpa16(&Ah[st][arow + 64][achk], g_hb + offA1 + (k0));              \
        cpa16(&Bs[st][arow][achk],      wd + offB0 + (k0));                \
        cpa16(&Bs[st][arow + 64][achk], wd + offB1 + (k0));                \
        cpa_commit();                                                      \
    } while (0)

    DN_LOAD(0, 0);

    const int NIT = IDIM / TK;
    for (int it = 0; it < NIT; it++) {
        cpa_wait0();
        __syncthreads();
        if (it + 1 < NIT) DN_LOAD((it + 1) & 1, (it + 1) * TK);
        unsigned st = (it & 1) * str;

#pragma unroll
        for (int kk = 0; kk < TK; kk += 16) {
            unsigned aH[2][4];
#pragma unroll
            for (int mf = 0; mf < 2; mf++)
                ldsm4(aH[mf][0], aH[mf][1], aH[mf][2], aH[mf][3], sAh + st + aoff[mf] + kk * 2);
#pragma unroll
            for (int nfp = 0; nfp < 4; nfp++) {
                unsigned bB[4];
                ldsm4(bB[0], bB[1], bB[2], bB[3], sBs + st + boff[nfp] + kk * 2);
#pragma unroll
                for (int h2 = 0; h2 < 2; h2++) {
                    int nf = nfp * 2 + h2;
#pragma unroll
                    for (int mf = 0; mf < 2; mf++)
                        mma_f16(acc[mf][nf], aH[mf], &bB[h2 * 2]);
                }
            }
        }
    }
#undef DN_LOAD

#pragma unroll
    for (int mf = 0; mf < 2; mf++) {
#pragma unroll
        for (int half = 0; half < 2; half++) {
            int lr = wm * 32 + mf * 16 + g + half * 8;
            int r = m0 + lr;
            if (r < M) {
                int p = prow[lr];
#pragma unroll
                for (int nf = 0; nf < 8; nf++) {
                    int col = n0 + wn * 64 + nf * 8 + 2 * q;
                    float2 o;
                    o.x = acc[mf][nf][half * 2 + 0];
                    o.y = acc[mf][nf][half * 2 + 1];
                    *(float2*)&g_ybuf[(size_t)p * HDIM + col] = o;
                }
            }
        }
    }
}

// ---------------- combine ----------------
__global__ void combine_kernel(float* __restrict__ y) {
    int idx = blockIdx.x * blockDim.x + threadIdx.x;
    int t = idx / (HDIM / 4);
    int h4 = (idx - t * (HDIM / 4)) * 4;
    float w0 = g_tokw[2 * t], w1 = g_tokw[2 * t + 1];
    float4 a = *(const float4*)&g_ybuf[(size_t)(2 * t) * HDIM + h4];
    float4 b = *(const float4*)&g_ybuf[(size_t)(2 * t + 1) * HDIM + h4];
    float4 r;
    r.x = w0 * a.x + w1 * b.x;
    r.y = w0 * a.y + w1 * b.y;
    r.z = w0 * a.z + w1 * b.z;
    r.w = w0 * a.w + w1 * b.w;
    *(float4*)&y[(size_t)t * HDIM + h4] = r;
}

// ---------------- launch ----------------
extern "C" void kernel_launch(void* const* d_in, const int* in_sizes, int n_in,
                              void* d_out, int out_size) {
    const float* x  = (const float*)d_in[0];
    const float* gw = (const float*)d_in[1];
    const float* wg = (const float*)d_in[2];
    const float* wu = (const float*)d_in[3];
    const float* wd = (const float*)d_in[4];
    float* y = (float*)d_out;

    cudaFuncSetAttribute(gateup_kernel, cudaFuncAttributeMaxDynamicSharedMemorySize, GU_SMEM);

    reset_kernel<<<1, 32>>>();
    router_kernel<<<NTOK / 8, 256>>>(x, gw);
    aux_kernel<<<1, 256>>>(y + (out_size - 1));

    split_x_kernel<<<(NTOK * HDIM / 4) / 256, 256>>>(x);
    transpose_half_kernel<0><<<dim3(IDIM / 32, HDIM / 32, EEXP), 256>>>(wg, HDIM, IDIM);
    transpose_half_kernel<1><<<dim3(IDIM / 32, HDIM / 32, EEXP), 256>>>(wu, HDIM, IDIM);
    transpose_half_kernel<2><<<dim3(HDIM / 32, IDIM / 32, EEXP), 256>>>(wd, IDIM, HDIM);

    gateup_kernel<<<dim3(IDIM / TN, (NTOK * 2) / TM, EEXP), 256, GU_SMEM>>>();
    down_kernel<<<dim3(HDIM / TN, (NTOK * 2) / TM, EEXP), 256>>>();
    combine_kernel<<<(NTOK * HDIM / 4) / 256, 256>>>(y);
}

// round 13
// speedup vs baseline: 4.7374x; 1.0187x over previous
#include <cuda_runtime.h>
#include <cuda_fp16.h>
#include <math.h>

// Problem constants (fixed by setup_inputs)
#define NTOK 8192      // B*S
#define HDIM 1024
#define IDIM 2048
#define EEXP 8
#define TOPK 2

// GEMM tiling
#define TM 128
#define TN 128
#define TK 32
#define AP 40          // padded k-row length (fp16): 80B stride, conflict-free LDSM

#define GU_SMEM (1024 + 3 * 2 * TM * AP * 2)   // prow/toks + Ah,Bg,Bu double-buffered

// ---------------- device scratch ----------------
__device__ int   g_cnt[EEXP];
__device__ int   g_pairs[EEXP * NTOK];
__device__ float g_tokw[NTOK * 2];
__device__ int   g_toke[NTOK * 2];
__device__ float g_selw[NTOK * 2];

// all GEMM operands single-rounded fp16
__device__ __half g_xh[NTOK * HDIM];
__device__ __half g_wg[EEXP * IDIM * HDIM];   // gate, transposed [e][i][h]
__device__ __half g_wu[EEXP * IDIM * HDIM];   // up, transposed [e][i][h]
__device__ __half g_wd[EEXP * HDIM * IDIM];   // down, transposed [e][h][i]
__device__ __half g_hb[NTOK * 2 * IDIM];      // silu(g)*u (fp16)  [pair][I]
__device__ float g_ybuf[NTOK * 2 * HDIM];     // expert outputs [pair][H]

// ---------------- helpers ----------------
__device__ __forceinline__ void mma_f16(float *d, const unsigned *a, const unsigned *b) {
    asm volatile("mma.sync.aligned.m16n8k16.row.col.f32.f16.f16.f32 "
        "{%0,%1,%2,%3}, {%4,%5,%6,%7}, {%8,%9}, {%0,%1,%2,%3};\n"
        : "+f"(d[0]), "+f"(d[1]), "+f"(d[2]), "+f"(d[3])
        : "r"(a[0]), "r"(a[1]), "r"(a[2]), "r"(a[3]), "r"(b[0]), "r"(b[1]));
}

__device__ __forceinline__ void ldsm4(unsigned &r0, unsigned &r1, unsigned &r2, unsigned &r3,
                                      unsigned a) {
    asm volatile("ldmatrix.sync.aligned.m8n8.x4.shared.b16 {%0,%1,%2,%3}, [%4];\n"
        : "=r"(r0), "=r"(r1), "=r"(r2), "=r"(r3) : "r"(a));
}

__device__ __forceinline__ void cpa16(void* smem, const void* g) {
    unsigned s = (unsigned)__cvta_generic_to_shared(smem);
    asm volatile("cp.async.cg.shared.global [%0], [%1], 16;\n" :: "r"(s), "l"(g));
}
__device__ __forceinline__ void cpa_commit() {
    asm volatile("cp.async.commit_group;\n");
}
__device__ __forceinline__ void cpa_wait0() {
    asm volatile("cp.async.wait_group 0;\n");
}

// ---------------- reset ----------------
__global__ void reset_kernel() {
    if (threadIdx.x < EEXP) g_cnt[threadIdx.x] = 0;
}

// ---------------- transpose weights to fp16: src [E][R][C] -> dst [E][C][R] ----------------
// 64x64 tiles; float4 loads; uint4 (8-half) vectorized transposed stores.
// W selects destinations IN DEVICE CODE (never pass __device__ globals from host:
// that passes the host shadow symbol; ATS silently dereferences host memory).
template<int W>
__global__ void transpose_half_kernel(const float* __restrict__ src, int R, int C) {
    __half* dh = (W == 0) ? g_wg : (W == 1) ? g_wu : g_wd;
    __shared__ float s[64][65];
    int e = blockIdx.z;
    int r0 = blockIdx.y * 64, c0 = blockIdx.x * 64;
    int tid = threadIdx.x;
    const float* sp = src + ((size_t)e * R + r0) * C + c0;
#pragma unroll
    for (int k = 0; k < 4; k++) {
        int u = tid + k * 256;
        int row = u >> 4;
        int cq = (u & 15) * 4;
        float4 v = *(const float4*)(sp + (size_t)row * C + cq);
        s[row][cq + 0] = v.x; s[row][cq + 1] = v.y;
        s[row][cq + 2] = v.z; s[row][cq + 3] = v.w;
    }
    __syncthreads();
    size_t dbase = ((size_t)e * C + c0) * R + r0;
#pragma unroll
    for (int k = 0; k < 2; k++) {
        int u = tid + k * 256;
        int c = u >> 3;
        int rc = (u & 7) * 8;
        __half2 p0 = __floats2half2_rn(s[rc + 0][c], s[rc + 1][c]);
        __half2 p1 = __floats2half2_rn(s[rc + 2][c], s[rc + 3][c]);
        __half2 p2 = __floats2half2_rn(s[rc + 4][c], s[rc + 5][c]);
        __half2 p3 = __floats2half2_rn(s[rc + 6][c], s[rc + 7][c]);
        uint4 o;
        o.x = *reinterpret_cast<unsigned*>(&p0);
        o.y = *reinterpret_cast<unsigned*>(&p1);
        o.z = *reinterpret_cast<unsigned*>(&p2);
        o.w = *reinterpret_cast<unsigned*>(&p3);
        *(uint4*)(dh + dbase + (size_t)c * R + rc) = o;
    }
}

// ---------------- router: one warp per token (also emits x as fp16) ----------------
__global__ void router_kernel(const float* __restrict__ x,
                              const float* __restrict__ gw) {
    int t = blockIdx.x * (blockDim.x >> 5) + (threadIdx.x >> 5);
    int lane = threadIdx.x & 31;
    if (t >= NTOK) return;
    const float* xr = x + (size_t)t * HDIM;
    __half* xo = g_xh + (size_t)t * HDIM;
    float acc[EEXP];
#pragma unroll
    for (int e = 0; e < EEXP; e++) acc[e] = 0.f;
    for (int h = lane; h < HDIM; h += 32) {
        float xv = xr[h];
        xo[h] = __float2half(xv);
        const float* g = gw + h * EEXP;
#pragma unroll
        for (int e = 0; e < EEXP; e++) acc[e] = fmaf(xv, g[e], acc[e]);
    }
#pragma unroll
    for (int off = 16; off > 0; off >>= 1) {
#pragma unroll
        for (int e = 0; e < EEXP; e++)
            acc[e] += __shfl_down_sync(0xffffffffu, acc[e], off);
    }
    if (lane == 0) {
        float mx = acc[0];
#pragma unroll
        for (int e = 1; e < EEXP; e++) mx = fmaxf(mx, acc[e]);
        float p[EEXP];
        float s = 0.f;
#pragma unroll
        for (int e = 0; e < EEXP; e++) { p[e] = expf(acc[e] - mx); s += p[e]; }
        float inv = 1.f / s;
#pragma unroll
        for (int e = 0; e < EEXP; e++) p[e] *= inv;
        int e0 = 0;
#pragma unroll
        for (int e = 1; e < EEXP; e++) if (p[e] > p[e0]) e0 = e;
        int e1 = (e0 == 0) ? 1 : 0;
#pragma unroll
        for (int e = 0; e < EEXP; e++) if (e != e0 && p[e] > p[e1]) e1 = e;
        float w0 = p[e0], w1 = p[e1];
        float rs = 1.f / (w0 + w1);
        g_toke[2 * t] = e0;      g_toke[2 * t + 1] = e1;
        g_selw[2 * t] = w0;      g_selw[2 * t + 1] = w1;
        g_tokw[2 * t] = w0 * rs; g_tokw[2 * t + 1] = w1 * rs;
        int p0 = atomicAdd(&g_cnt[e0], 1);
        g_pairs[e0 * NTOK + p0] = 2 * t;
        int p1 = atomicAdd(&g_cnt[e1], 1);
        g_pairs[e1 * NTOK + p1] = 2 * t + 1;
    }
}

// ---------------- aux loss ----------------
__global__ void aux_kernel(float* __restrict__ out_aux) {
    __shared__ float sload[256][EEXP];
    int tid = threadIdx.x;
    float l[EEXP];
#pragma unroll
    for (int e = 0; e < EEXP; e++) l[e] = 0.f;
    for (int a = tid; a < NTOK * 2; a += 256)
        l[g_toke[a]] += g_selw[a];
#pragma unroll
    for (int e = 0; e < EEXP; e++) sload[tid][e] = l[e];
    __syncthreads();
    for (int s = 128; s > 0; s >>= 1) {
        if (tid < s) {
#pragma unroll
            for (int e = 0; e < EEXP; e++) sload[tid][e] += sload[tid + s][e];
        }
        __syncthreads();
    }
    if (tid == 0) {
        float aux = 0.f;
#pragma unroll
        for (int e = 0; e < EEXP; e++) {
            float pe = sload[0][e] / (float)NTOK;
            float pt = (float)g_cnt[e] / (float)(NTOK * TOPK);
            aux += pe * pt;
        }
        aux *= (float)EEXP * 1e-3f;
        *out_aux = aux;
    }
}

// ---------------- gate+up GEMM (fp16, 128x128 tile, ldmatrix + cp.async) ----------------
__global__ __launch_bounds__(256) void gateup_kernel() {
    extern __shared__ char sm[];
    int e = blockIdx.z;
    int M = g_cnt[e];
    int m0 = blockIdx.y * TM;
    if (m0 >= M) return;
    int n0 = blockIdx.x * TN;

    int* prow = (int*)sm;
    int* toks = (int*)(sm + 512);
    __half* Ah = (__half*)(sm + 1024);
    __half* Bg = Ah + 2 * TM * AP;
    __half* Bu = Bg + 2 * TM * AP;

    int tid = threadIdx.x;
    if (tid < TM) {
        int r = m0 + tid;
        int pr = (r < M) ? g_pairs[e * NTOK + r] : g_pairs[e * NTOK];
        prow[tid] = pr;
        toks[tid] = pr >> 1;
    }
    __syncthreads();

    const __half* wg = g_wg + (size_t)e * IDIM * HDIM;
    const __half* wu = g_wu + (size_t)e * IDIM * HDIM;

    int wid = tid >> 5;
    int lane = tid & 31;
    int wm = wid >> 1;          // 0..3: 32 rows each
    int wn = wid & 1;           // 0..1: 64 cols each
    int g = lane >> 2;
    int q = lane & 3;

    int arow = tid >> 2;        // 0..63
    int achk = (tid & 3) * 8;

    unsigned offA0 = (unsigned)toks[arow] * HDIM + achk;
    unsigned offA1 = (unsigned)toks[arow + 64] * HDIM + achk;
    unsigned offB0 = (unsigned)(n0 + arow) * HDIM + achk;
    unsigned offB1 = (unsigned)(n0 + arow + 64) * HDIM + achk;

    unsigned aoff[2];
#pragma unroll
    for (int mf = 0; mf < 2; mf++)
        aoff[mf] = ((wm * 32 + mf * 16 + (lane & 15)) * AP + ((lane >> 4) << 3)) * 2;
    unsigned boff[4];
#pragma unroll
    for (int nfp = 0; nfp < 4; nfp++)
        boff[nfp] = ((wn * 64 + nfp * 16 + ((lane >> 4) << 3) + (lane & 7)) * AP
                     + (((lane >> 3) & 1) << 3)) * 2;

    unsigned sAh = (unsigned)__cvta_generic_to_shared(Ah);
    unsigned sBg = (unsigned)__cvta_generic_to_shared(Bg);
    unsigned sBu = (unsigned)__cvta_generic_to_shared(Bu);
    const unsigned str = TM * AP * 2;

    float accG[2][8][4], accU[2][8][4];
#pragma unroll
    for (int i = 0; i < 2; i++)
#pragma unroll
        for (int j = 0; j < 8; j++)
#pragma unroll
            for (int c = 0; c < 4; c++) { accG[i][j][c] = 0.f; accU[i][j][c] = 0.f; }

#define GU_LOAD(st, k0)                                                    \
    do {                                                                   \
        __half* a = Ah + (st) * TM * AP;                                   \
        __half* bg = Bg + (st) * TM * AP;                                  \
        __half* bu = Bu + (st) * TM * AP;                                  \
        cpa16(a + arow * AP + achk,        g_xh + offA0 + (k0));           \
        cpa16(a + (arow + 64) * AP + achk, g_xh + offA1 + (k0));           \
        cpa16(bg + arow * AP + achk,        wg + offB0 + (k0));            \
        cpa16(bg + (arow + 64) * AP + achk, wg + offB1 + (k0));            \
        cpa16(bu + arow * AP + achk,        wu + offB0 + (k0));            \
        cpa16(bu + (arow + 64) * AP + achk, wu + offB1 + (k0));            \
        cpa_commit();                                                      \
    } while (0)

    GU_LOAD(0, 0);

    const int NIT = HDIM / TK;
    for (int it = 0; it < NIT; it++) {
        cpa_wait0();
        __syncthreads();
        if (it + 1 < NIT) GU_LOAD((it + 1) & 1, (it + 1) * TK);
        unsigned st = (it & 1) * str;

#pragma unroll
        for (int kk = 0; kk < TK; kk += 16) {
            unsigned aH[2][4];
#pragma unroll
            for (int mf = 0; mf < 2; mf++)
                ldsm4(aH[mf][0], aH[mf][1], aH[mf][2], aH[mf][3], sAh + st + aoff[mf] + kk * 2);
#pragma unroll
            for (int nfp = 0; nfp < 4; nfp++) {
                unsigned bG[4];
                ldsm4(bG[0], bG[1], bG[2], bG[3], sBg + st + boff[nfp] + kk * 2);
#pragma unroll
                for (int h2 = 0; h2 < 2; h2++) {
                    int nf = nfp * 2 + h2;
#pragma unroll
                    for (int mf = 0; mf < 2; mf++)
                        mma_f16(accG[mf][nf], aH[mf], &bG[h2 * 2]);
                }
            }
#pragma unroll
            for (int nfp = 0; nfp < 4; nfp++) {
                unsigned bU[4];
                ldsm4(bU[0], bU[1], bU[2], bU[3], sBu + st + boff[nfp] + kk * 2);
#pragma unroll
                for (int h2 = 0; h2 < 2; h2++) {
                    int nf = nfp * 2 + h2;
#pragma unroll
                    for (int mf = 0; mf < 2; mf++)
                        mma_f16(accU[mf][nf], aH[mf], &bU[h2 * 2]);
                }
            }
        }
    }
#undef GU_LOAD

    // epilogue: h = silu(g) * u, single-rounded fp16
#pragma unroll
    for (int mf = 0; mf < 2; mf++) {
#pragma unroll
        for (int half = 0; half < 2; half++) {
            int lr = wm * 32 + mf * 16 + g + half * 8;
            int r = m0 + lr;
            if (r < M) {
                int p = prow[lr];
#pragma unroll
                for (int nf = 0; nf < 8; nf++) {
                    int col = n0 + wn * 64 + nf * 8 + 2 * q;
                    float gv0 = accG[mf][nf][half * 2 + 0];
                    float gv1 = accG[mf][nf][half * 2 + 1];
                    float uv0 = accU[mf][nf][half * 2 + 0];
                    float uv1 = accU[mf][nf][half * 2 + 1];
                    float hx = (gv0 / (1.f + expf(-gv0))) * uv0;
                    float hy = (gv1 / (1.f + expf(-gv1))) * uv1;
                    __half2 hv = __floats2half2_rn(hx, hy);
                    *(unsigned*)&g_hb[(size_t)p * IDIM + col] =
                        *reinterpret_cast<unsigned*>(&hv);
                }
            }
        }
    }
}

// ---------------- down GEMM (fp16, 128x128 tile, ldmatrix + cp.async) ----------------
__global__ __launch_bounds__(256) void down_kernel() {
    int e = blockIdx.z;
    int M = g_cnt[e];
    int m0 = blockIdx.y * TM;
    if (m0 >= M) return;
    int n0 = blockIdx.x * TN;

    __shared__ __half Ah[2][TM][AP];
    __shared__ __half Bs[2][TN][AP];
    __shared__ int prow[TM];

    int tid = threadIdx.x;
    if (tid < TM) {
        int r = m0 + tid;
        prow[tid] = (r < M) ? g_pairs[e * NTOK + r] : g_pairs[e * NTOK];
    }
    __syncthreads();

    const __half* wd = g_wd + (size_t)e * HDIM * IDIM;

    int wid = tid >> 5;
    int lane = tid & 31;
    int wm = wid >> 1;
    int wn = wid & 1;
    int g = lane >> 2;
    int q = lane & 3;

    int arow = tid >> 2;
    int achk = (tid & 3) * 8;

    unsigned offA0 = (unsigned)prow[arow] * IDIM + achk;
    unsigned offA1 = (unsigned)prow[arow + 64] * IDIM + achk;
    unsigned offB0 = (unsigned)(n0 + arow) * IDIM + achk;
    unsigned offB1 = (unsigned)(n0 + arow + 64) * IDIM + achk;

    unsigned aoff[2];
#pragma unroll
    for (int mf = 0; mf < 2; mf++)
        aoff[mf] = ((wm * 32 + mf * 16 + (lane & 15)) * AP + ((lane >> 4) << 3)) * 2;
    unsigned boff[4];
#pragma unroll
    for (int nfp = 0; nfp < 4; nfp++)
        boff[nfp] = ((wn * 64 + nfp * 16 + ((lane >> 4) << 3) + (lane & 7)) * AP
                     + (((lane >> 3) & 1) << 3)) * 2;

    unsigned sAh = (unsigned)__cvta_generic_to_shared(&Ah[0][0][0]);
    unsigned sBs = (unsigned)__cvta_generic_to_shared(&Bs[0][0][0]);
    const unsigned str = TM * AP * 2;

    float acc[2][8][4];
#pragma unroll
    for (int i = 0; i < 2; i++)
#pragma unroll
        for (int j = 0; j < 8; j++)
#pragma unroll
            for (int c = 0; c < 4; c++) acc[i][j][c] = 0.f;

#define DN_LOAD(st, k0)                                                    \
    do {                                                                   \
        cpa16(&Ah[st][arow][achk],      g_hb + offA0 + (k0));              \
        cpa16(&Ah[st][arow + 64][achk], g_hb + offA1 + (k0));              \
        cpa16(&Bs[st][arow][achk],      wd + offB0 + (k0));                \
        cpa16(&Bs[st][arow + 64][achk], wd + offB1 + (k0));                \
        cpa_commit();                                                      \
    } while (0)

    DN_LOAD(0, 0);

    const int NIT = IDIM / TK;
    for (int it = 0; it < NIT; it++) {
        cpa_wait0();
        __syncthreads();
        if (it + 1 < NIT) DN_LOAD((it + 1) & 1, (it + 1) * TK);
        unsigned st = (it & 1) * str;

#pragma unroll
        for (int kk = 0; kk < TK; kk += 16) {
            unsigned aH[2][4];
#pragma unroll
            for (int mf = 0; mf < 2; mf++)
                ldsm4(aH[mf][0], aH[mf][1], aH[mf][2], aH[mf][3], sAh + st + aoff[mf] + kk * 2);
#pragma unroll
            for (int nfp = 0; nfp < 4; nfp++) {
                unsigned bB[4];
                ldsm4(bB[0], bB[1], bB[2], bB[3], sBs + st + boff[nfp] + kk * 2);
#pragma unroll
                for (int h2 = 0; h2 < 2; h2++) {
                    int nf = nfp * 2 + h2;
#pragma unroll
                    for (int mf = 0; mf < 2; mf++)
                        mma_f16(acc[mf][nf], aH[mf], &bB[h2 * 2]);
                }
            }
        }
    }
#undef DN_LOAD

#pragma unroll
    for (int mf = 0; mf < 2; mf++) {
#pragma unroll
        for (int half = 0; half < 2; half++) {
            int lr = wm * 32 + mf * 16 + g + half * 8;
            int r = m0 + lr;
            if (r < M) {
                int p = prow[lr];
#pragma unroll
                for (int nf = 0; nf < 8; nf++) {
                    int col = n0 + wn * 64 + nf * 8 + 2 * q;
                    float2 o;
                    o.x = acc[mf][nf][half * 2 + 0];
                    o.y = acc[mf][nf][half * 2 + 1];
                    *(float2*)&g_ybuf[(size_t)p * HDIM + col] = o;
                }
            }
        }
    }
}

// ---------------- combine ----------------
__global__ void combine_kernel(float* __restrict__ y) {
    int idx = blockIdx.x * blockDim.x + threadIdx.x;
    int t = idx / (HDIM / 4);
    int h4 = (idx - t * (HDIM / 4)) * 4;
    float w0 = g_tokw[2 * t], w1 = g_tokw[2 * t + 1];
    float4 a = *(const float4*)&g_ybuf[(size_t)(2 * t) * HDIM + h4];
    float4 b = *(const float4*)&g_ybuf[(size_t)(2 * t + 1) * HDIM + h4];
    float4 r;
    r.x = w0 * a.x + w1 * b.x;
    r.y = w0 * a.y + w1 * b.y;
    r.z = w0 * a.z + w1 * b.z;
    r.w = w0 * a.w + w1 * b.w;
    *(float4*)&y[(size_t)t * HDIM + h4] = r;
}

// ---------------- launch ----------------
extern "C" void kernel_launch(void* const* d_in, const int* in_sizes, int n_in,
                              void* d_out, int out_size) {
    const float* x  = (const float*)d_in[0];
    const float* gw = (const float*)d_in[1];
    const float* wg = (const float*)d_in[2];
    const float* wu = (const float*)d_in[3];
    const float* wd = (const float*)d_in[4];
    float* y = (float*)d_out;

    cudaFuncSetAttribute(gateup_kernel, cudaFuncAttributeMaxDynamicSharedMemorySize, GU_SMEM);

    reset_kernel<<<1, 32>>>();
    router_kernel<<<NTOK / 8, 256>>>(x, gw);
    aux_kernel<<<1, 256>>>(y + (out_size - 1));

    transpose_half_kernel<0><<<dim3(IDIM / 64, HDIM / 64, EEXP), 256>>>(wg, HDIM, IDIM);
    transpose_half_kernel<1><<<dim3(IDIM / 64, HDIM / 64, EEXP), 256>>>(wu, HDIM, IDIM);
    transpose_half_kernel<2><<<dim3(HDIM / 64, IDIM / 64, EEXP), 256>>>(wd, IDIM, HDIM);

    gateup_kernel<<<dim3(IDIM / TN, (NTOK * 2) / TM, EEXP), 256, GU_SMEM>>>();
    down_kernel<<<dim3(HDIM / TN, (NTOK * 2) / TM, EEXP), 256>>>();
    combine_kernel<<<(NTOK * HDIM / 4) / 256, 256>>>(y);
}

// round 14
// speedup vs baseline: 4.7437x; 1.0013x over previous
#include <cuda_runtime.h>
#include <cuda_fp16.h>
#include <math.h>

// Problem constants (fixed by setup_inputs)
#define NTOK 8192      // B*S
#define HDIM 1024
#define IDIM 2048
#define EEXP 8
#define TOPK 2

// GEMM tiling
#define TM 128
#define TN 128
#define TK 32
#define AP 40          // padded k-row length (fp16): 80B stride, conflict-free LDSM

#define GU_SMEM (1024 + 3 * 2 * TM * AP * 2)   // prow/toks + Ah,Bg,Bu double-buffered

// ---------------- device scratch ----------------
__device__ int   g_cnt[EEXP];
__device__ int   g_pairs[EEXP * NTOK];
__device__ float g_tokw[NTOK * 2];
__device__ int   g_toke[NTOK * 2];
__device__ float g_selw[NTOK * 2];

// all GEMM operands single-rounded fp16
__device__ __half g_xh[NTOK * HDIM];
__device__ __half g_wg[EEXP * IDIM * HDIM];   // gate, transposed [e][i][h]
__device__ __half g_wu[EEXP * IDIM * HDIM];   // up, transposed [e][i][h]
__device__ __half g_wd[EEXP * HDIM * IDIM];   // down, transposed [e][h][i]
__device__ __half g_hb[NTOK * 2 * IDIM];      // silu(g)*u (fp16)  [pair][I]

// ---------------- helpers ----------------
__device__ __forceinline__ void mma_f16(float *d, const unsigned *a, const unsigned *b) {
    asm volatile("mma.sync.aligned.m16n8k16.row.col.f32.f16.f16.f32 "
        "{%0,%1,%2,%3}, {%4,%5,%6,%7}, {%8,%9}, {%0,%1,%2,%3};\n"
        : "+f"(d[0]), "+f"(d[1]), "+f"(d[2]), "+f"(d[3])
        : "r"(a[0]), "r"(a[1]), "r"(a[2]), "r"(a[3]), "r"(b[0]), "r"(b[1]));
}

__device__ __forceinline__ void ldsm4(unsigned &r0, unsigned &r1, unsigned &r2, unsigned &r3,
                                      unsigned a) {
    asm volatile("ldmatrix.sync.aligned.m8n8.x4.shared.b16 {%0,%1,%2,%3}, [%4];\n"
        : "=r"(r0), "=r"(r1), "=r"(r2), "=r"(r3) : "r"(a));
}

__device__ __forceinline__ void cpa16(void* smem, const void* g) {
    unsigned s = (unsigned)__cvta_generic_to_shared(smem);
    asm volatile("cp.async.cg.shared.global [%0], [%1], 16;\n" :: "r"(s), "l"(g));
}
__device__ __forceinline__ void cpa_commit() {
    asm volatile("cp.async.commit_group;\n");
}
__device__ __forceinline__ void cpa_wait0() {
    asm volatile("cp.async.wait_group 0;\n");
}

// ---------------- reset ----------------
__global__ void reset_kernel() {
    if (threadIdx.x < EEXP) g_cnt[threadIdx.x] = 0;
}

// ---------------- zero output (d_out is poisoned; atomics need 0 base) ----------------
__global__ void zero_y_kernel(float* __restrict__ y) {
    int idx = blockIdx.x * blockDim.x + threadIdx.x;
    float4 z; z.x = 0.f; z.y = 0.f; z.z = 0.f; z.w = 0.f;
    ((float4*)y)[idx] = z;
}

// ---------------- transpose weights to fp16: src [E][R][C] -> dst [E][C][R] ----------------
// 64x64 tiles; float4 loads; uint4 (8-half) vectorized transposed stores.
// W selects destinations IN DEVICE CODE (never pass __device__ globals from host:
// that passes the host shadow symbol; ATS silently dereferences host memory).
template<int W>
__global__ void transpose_half_kernel(const float* __restrict__ src, int R, int C) {
    __half* dh = (W == 0) ? g_wg : (W == 1) ? g_wu : g_wd;
    __shared__ float s[64][65];
    int e = blockIdx.z;
    int r0 = blockIdx.y * 64, c0 = blockIdx.x * 64;
    int tid = threadIdx.x;
    const float* sp = src + ((size_t)e * R + r0) * C + c0;
#pragma unroll
    for (int k = 0; k < 4; k++) {
        int u = tid + k * 256;
        int row = u >> 4;
        int cq = (u & 15) * 4;
        float4 v = *(const float4*)(sp + (size_t)row * C + cq);
        s[row][cq + 0] = v.x; s[row][cq + 1] = v.y;
        s[row][cq + 2] = v.z; s[row][cq + 3] = v.w;
    }
    __syncthreads();
    size_t dbase = ((size_t)e * C + c0) * R + r0;
#pragma unroll
    for (int k = 0; k < 2; k++) {
        int u = tid + k * 256;
        int c = u >> 3;
        int rc = (u & 7) * 8;
        __half2 p0 = __floats2half2_rn(s[rc + 0][c], s[rc + 1][c]);
        __half2 p1 = __floats2half2_rn(s[rc + 2][c], s[rc + 3][c]);
        __half2 p2 = __floats2half2_rn(s[rc + 4][c], s[rc + 5][c]);
        __half2 p3 = __floats2half2_rn(s[rc + 6][c], s[rc + 7][c]);
        uint4 o;
        o.x = *reinterpret_cast<unsigned*>(&p0);
        o.y = *reinterpret_cast<unsigned*>(&p1);
        o.z = *reinterpret_cast<unsigned*>(&p2);
        o.w = *reinterpret_cast<unsigned*>(&p3);
        *(uint4*)(dh + dbase + (size_t)c * R + rc) = o;
    }
}

// ---------------- router: one warp per token (also emits x as fp16) ----------------
__global__ void router_kernel(const float* __restrict__ x,
                              const float* __restrict__ gw) {
    int t = blockIdx.x * (blockDim.x >> 5) + (threadIdx.x >> 5);
    int lane = threadIdx.x & 31;
    if (t >= NTOK) return;
    const float* xr = x + (size_t)t * HDIM;
    __half* xo = g_xh + (size_t)t * HDIM;
    float acc[EEXP];
#pragma unroll
    for (int e = 0; e < EEXP; e++) acc[e] = 0.f;
    for (int h = lane; h < HDIM; h += 32) {
        float xv = xr[h];
        xo[h] = __float2half(xv);
        const float* g = gw + h * EEXP;
#pragma unroll
        for (int e = 0; e < EEXP; e++) acc[e] = fmaf(xv, g[e], acc[e]);
    }
#pragma unroll
    for (int off = 16; off > 0; off >>= 1) {
#pragma unroll
        for (int e = 0; e < EEXP; e++)
            acc[e] += __shfl_down_sync(0xffffffffu, acc[e], off);
    }
    if (lane == 0) {
        float mx = acc[0];
#pragma unroll
        for (int e = 1; e < EEXP; e++) mx = fmaxf(mx, acc[e]);
        float p[EEXP];
        float s = 0.f;
#pragma unroll
        for (int e = 0; e < EEXP; e++) { p[e] = expf(acc[e] - mx); s += p[e]; }
        float inv = 1.f / s;
#pragma unroll
        for (int e = 0; e < EEXP; e++) p[e] *= inv;
        int e0 = 0;
#pragma unroll
        for (int e = 1; e < EEXP; e++) if (p[e] > p[e0]) e0 = e;
        int e1 = (e0 == 0) ? 1 : 0;
#pragma unroll
        for (int e = 0; e < EEXP; e++) if (e != e0 && p[e] > p[e1]) e1 = e;
        float w0 = p[e0], w1 = p[e1];
        float rs = 1.f / (w0 + w1);
        g_toke[2 * t] = e0;      g_toke[2 * t + 1] = e1;
        g_selw[2 * t] = w0;      g_selw[2 * t + 1] = w1;
        g_tokw[2 * t] = w0 * rs; g_tokw[2 * t + 1] = w1 * rs;
        int p0 = atomicAdd(&g_cnt[e0], 1);
        g_pairs[e0 * NTOK + p0] = 2 * t;
        int p1 = atomicAdd(&g_cnt[e1], 1);
        g_pairs[e1 * NTOK + p1] = 2 * t + 1;
    }
}

// ---------------- aux loss ----------------
__global__ void aux_kernel(float* __restrict__ out_aux) {
    __shared__ float sload[256][EEXP];
    int tid = threadIdx.x;
    float l[EEXP];
#pragma unroll
    for (int e = 0; e < EEXP; e++) l[e] = 0.f;
    for (int a = tid; a < NTOK * 2; a += 256)
        l[g_toke[a]] += g_selw[a];
#pragma unroll
    for (int e = 0; e < EEXP; e++) sload[tid][e] = l[e];
    __syncthreads();
    for (int s = 128; s > 0; s >>= 1) {
        if (tid < s) {
#pragma unroll
            for (int e = 0; e < EEXP; e++) sload[tid][e] += sload[tid + s][e];
        }
        __syncthreads();
    }
    if (tid == 0) {
        float aux = 0.f;
#pragma unroll
        for (int e = 0; e < EEXP; e++) {
            float pe = sload[0][e] / (float)NTOK;
            float pt = (float)g_cnt[e] / (float)(NTOK * TOPK);
            aux += pe * pt;
        }
        aux *= (float)EEXP * 1e-3f;
        *out_aux = aux;
    }
}

// ---------------- gate+up GEMM (fp16, 128x128 tile, ldmatrix + cp.async) ----------------
__global__ __launch_bounds__(256) void gateup_kernel() {
    extern __shared__ char sm[];
    int e = blockIdx.z;
    int M = g_cnt[e];
    int m0 = blockIdx.y * TM;
    if (m0 >= M) return;
    int n0 = blockIdx.x * TN;

    int* prow = (int*)sm;
    int* toks = (int*)(sm + 512);
    __half* Ah = (__half*)(sm + 1024);
    __half* Bg = Ah + 2 * TM * AP;
    __half* Bu = Bg + 2 * TM * AP;

    int tid = threadIdx.x;
    if (tid < TM) {
        int r = m0 + tid;
        int pr = (r < M) ? g_pairs[e * NTOK + r] : g_pairs[e * NTOK];
        prow[tid] = pr;
        toks[tid] = pr >> 1;
    }
    __syncthreads();

    const __half* wg = g_wg + (size_t)e * IDIM * HDIM;
    const __half* wu = g_wu + (size_t)e * IDIM * HDIM;

    int wid = tid >> 5;
    int lane = tid & 31;
    int wm = wid >> 1;          // 0..3: 32 rows each
    int wn = wid & 1;           // 0..1: 64 cols each
    int g = lane >> 2;
    int q = lane & 3;

    int arow = tid >> 2;        // 0..63
    int achk = (tid & 3) * 8;

    unsigned offA0 = (unsigned)toks[arow] * HDIM + achk;
    unsigned offA1 = (unsigned)toks[arow + 64] * HDIM + achk;
    unsigned offB0 = (unsigned)(n0 + arow) * HDIM + achk;
    unsigned offB1 = (unsigned)(n0 + arow + 64) * HDIM + achk;

    unsigned aoff[2];
#pragma unroll
    for (int mf = 0; mf < 2; mf++)
        aoff[mf] = ((wm * 32 + mf * 16 + (lane & 15)) * AP + ((lane >> 4) << 3)) * 2;
    unsigned boff[4];
#pragma unroll
    for (int nfp = 0; nfp < 4; nfp++)
        boff[nfp] = ((wn * 64 + nfp * 16 + ((lane >> 4) << 3) + (lane & 7)) * AP
                     + (((lane >> 3) & 1) << 3)) * 2;

    unsigned sAh = (unsigned)__cvta_generic_to_shared(Ah);
    unsigned sBg = (unsigned)__cvta_generic_to_shared(Bg);
    unsigned sBu = (unsigned)__cvta_generic_to_shared(Bu);
    const unsigned str = TM * AP * 2;

    float accG[2][8][4], accU[2][8][4];
#pragma unroll
    for (int i = 0; i < 2; i++)
#pragma unroll
        for (int j = 0; j < 8; j++)
#pragma unroll
            for (int c = 0; c < 4; c++) { accG[i][j][c] = 0.f; accU[i][j][c] = 0.f; }

#define GU_LOAD(st, k0)                                                    \
    do {                                                                   \
        __half* a = Ah + (st) * TM * AP;                                   \
        __half* bg = Bg + (st) * TM * AP;                                  \
        __half* bu = Bu + (st) * TM * AP;                                  \
        cpa16(a + arow * AP + achk,        g_xh + offA0 + (k0));           \
        cpa16(a + (arow + 64) * AP + achk, g_xh + offA1 + (k0));           \
        cpa16(bg + arow * AP + achk,        wg + offB0 + (k0));            \
        cpa16(bg + (arow + 64) * AP + achk, wg + offB1 + (k0));            \
        cpa16(bu + arow * AP + achk,        wu + offB0 + (k0));            \
        cpa16(bu + (arow + 64) * AP + achk, wu + offB1 + (k0));            \
        cpa_commit();                                                      \
    } while (0)

    GU_LOAD(0, 0);

    const int NIT = HDIM / TK;
    for (int it = 0; it < NIT; it++) {
        cpa_wait0();
        __syncthreads();
        if (it + 1 < NIT) GU_LOAD((it + 1) & 1, (it + 1) * TK);
        unsigned st = (it & 1) * str;

#pragma unroll
        for (int kk = 0; kk < TK; kk += 16) {
            unsigned aH[2][4];
#pragma unroll
            for (int mf = 0; mf < 2; mf++)
                ldsm4(aH[mf][0], aH[mf][1], aH[mf][2], aH[mf][3], sAh + st + aoff[mf] + kk * 2);
#pragma unroll
            for (int nfp = 0; nfp < 4; nfp++) {
                unsigned bG[4];
                ldsm4(bG[0], bG[1], bG[2], bG[3], sBg + st + boff[nfp] + kk * 2);
#pragma unroll
                for (int h2 = 0; h2 < 2; h2++) {
                    int nf = nfp * 2 + h2;
#pragma unroll
                    for (int mf = 0; mf < 2; mf++)
                        mma_f16(accG[mf][nf], aH[mf], &bG[h2 * 2]);
                }
            }
#pragma unroll
            for (int nfp = 0; nfp < 4; nfp++) {
                unsigned bU[4];
                ldsm4(bU[0], bU[1], bU[2], bU[3], sBu + st + boff[nfp] + kk * 2);
#pragma unroll
                for (int h2 = 0; h2 < 2; h2++) {
                    int nf = nfp * 2 + h2;
#pragma unroll
                    for (int mf = 0; mf < 2; mf++)
                        mma_f16(accU[mf][nf], aH[mf], &bU[h2 * 2]);
                }
            }
        }
    }
#undef GU_LOAD

    // epilogue: h = silu(g) * u, single-rounded fp16
#pragma unroll
    for (int mf = 0; mf < 2; mf++) {
#pragma unroll
        for (int half = 0; half < 2; half++) {
            int lr = wm * 32 + mf * 16 + g + half * 8;
            int r = m0 + lr;
            if (r < M) {
                int p = prow[lr];
#pragma unroll
                for (int nf = 0; nf < 8; nf++) {
                    int col = n0 + wn * 64 + nf * 8 + 2 * q;
                    float gv0 = accG[mf][nf][half * 2 + 0];
                    float gv1 = accG[mf][nf][half * 2 + 1];
                    float uv0 = accU[mf][nf][half * 2 + 0];
                    float uv1 = accU[mf][nf][half * 2 + 1];
                    float hx = (gv0 / (1.f + expf(-gv0))) * uv0;
                    float hy = (gv1 / (1.f + expf(-gv1))) * uv1;
                    __half2 hv = __floats2half2_rn(hx, hy);
                    *(unsigned*)&g_hb[(size_t)p * IDIM + col] =
                        *reinterpret_cast<unsigned*>(&hv);
                }
            }
        }
    }
}

// ---------------- down GEMM (fp16, 128x128 tile; fused weighted atomic combine) ----------------
__global__ __launch_bounds__(256) void down_kernel(float* __restrict__ y) {
    int e = blockIdx.z;
    int M = g_cnt[e];
    int m0 = blockIdx.y * TM;
    if (m0 >= M) return;
    int n0 = blockIdx.x * TN;

    __shared__ __half Ah[2][TM][AP];
    __shared__ __half Bs[2][TN][AP];
    __shared__ int prow[TM];

    int tid = threadIdx.x;
    if (tid < TM) {
        int r = m0 + tid;
        prow[tid] = (r < M) ? g_pairs[e * NTOK + r] : g_pairs[e * NTOK];
    }
    __syncthreads();

    const __half* wd = g_wd + (size_t)e * HDIM * IDIM;

    int wid = tid >> 5;
    int lane = tid & 31;
    int wm = wid >> 1;
    int wn = wid & 1;
    int g = lane >> 2;
    int q = lane & 3;

    int arow = tid >> 2;
    int achk = (tid & 3) * 8;

    unsigned offA0 = (unsigned)prow[arow] * IDIM + achk;
    unsigned offA1 = (unsigned)prow[arow + 64] * IDIM + achk;
    unsigned offB0 = (unsigned)(n0 + arow) * IDIM + achk;
    unsigned offB1 = (unsigned)(n0 + arow + 64) * IDIM + achk;

    unsigned aoff[2];
#pragma unroll
    for (int mf = 0; mf < 2; mf++)
        aoff[mf] = ((wm * 32 + mf * 16 + (lane & 15)) * AP + ((lane >> 4) << 3)) * 2;
    unsigned boff[4];
#pragma unroll
    for (int nfp = 0; nfp < 4; nfp++)
        boff[nfp] = ((wn * 64 + nfp * 16 + ((lane >> 4) << 3) + (lane & 7)) * AP
                     + (((lane >> 3) & 1) << 3)) * 2;

    unsigned sAh = (unsigned)__cvta_generic_to_shared(&Ah[0][0][0]);
    unsigned sBs = (unsigned)__cvta_generic_to_shared(&Bs[0][0][0]);
    const unsigned str = TM * AP * 2;

    float acc[2][8][4];
#pragma unroll
    for (int i = 0; i < 2; i++)
#pragma unroll
        for (int j = 0; j < 8; j++)
#pragma unroll
            for (int c = 0; c < 4; c++) acc[i][j][c] = 0.f;

#define DN_LOAD(st, k0)                                                    \
    do {                                                                   \
        cpa16(&Ah[st][arow][achk],      g_hb + offA0 + (k0));              \
        cpa16(&Ah[st][arow + 64][achk], g_hb + offA1 + (k0));              \
        cpa16(&Bs[st][arow][achk],      wd + offB0 + (k0));                \
        cpa16(&Bs[st][arow + 64][achk], wd + offB1 + (k0));                \
        cpa_commit();                                                      \
    } while (0)

    DN_LOAD(0, 0);

    const int NIT = IDIM / TK;
    for (int it = 0; it < NIT; it++) {
        cpa_wait0();
        __syncthreads();
        if (it + 1 < NIT) DN_LOAD((it + 1) & 1, (it + 1) * TK);
        unsigned st = (it & 1) * str;

#pragma unroll
        for (int kk = 0; kk < TK; kk += 16) {
            unsigned aH[2][4];
#pragma unroll
            for (int mf = 0; mf < 2; mf++)
                ldsm4(aH[mf][0], aH[mf][1], aH[mf][2], aH[mf][3], sAh + st + aoff[mf] + kk * 2);
#pragma unroll
            for (int nfp = 0; nfp < 4; nfp++) {
                unsigned bB[4];
                ldsm4(bB[0], bB[1], bB[2], bB[3], sBs + st + boff[nfp] + kk * 2);
#pragma unroll
                for (int h2 = 0; h2 < 2; h2++) {
                    int nf = nfp * 2 + h2;
#pragma unroll
                    for (int mf = 0; mf < 2; mf++)
                        mma_f16(acc[mf][nf], aH[mf], &bB[h2 * 2]);
                }
            }
        }
    }
#undef DN_LOAD

    // epilogue: weighted atomic scatter into y.
    // Each y element receives exactly TWO atomic adds (one per selected expert);
    // fp32 addition is commutative, so two-contribution accumulation from a
    // zeroed base is order-independent -> deterministic output bits.
#pragma unroll
    for (int mf = 0; mf < 2; mf++) {
#pragma unroll
        for (int half = 0; half < 2; half++) {
            int lr = wm * 32 + mf * 16 + g + half * 8;
            int r = m0 + lr;
            if (r < M) {
                int p = prow[lr];
                float w = g_tokw[p];
                float* yr = y + (size_t)(p >> 1) * HDIM;
#pragma unroll
                for (int nf = 0; nf < 8; nf++) {
                    int col = n0 + wn * 64 + nf * 8 + 2 * q;
                    atomicAdd(&yr[col],     w * acc[mf][nf][half * 2 + 0]);
                    atomicAdd(&yr[col + 1], w * acc[mf][nf][half * 2 + 1]);
                }
            }
        }
    }
}

// ---------------- launch ----------------
extern "C" void kernel_launch(void* const* d_in, const int* in_sizes, int n_in,
                              void* d_out, int out_size) {
    const float* x  = (const float*)d_in[0];
    const float* gw = (const float*)d_in[1];
    const float* wg = (const float*)d_in[2];
    const float* wu = (const float*)d_in[3];
    const float* wd = (const float*)d_in[4];
    float* y = (float*)d_out;

    cudaFuncSetAttribute(gateup_kernel, cudaFuncAttributeMaxDynamicSharedMemorySize, GU_SMEM);

    reset_kernel<<<1, 32>>>();
    zero_y_kernel<<<(NTOK * HDIM / 4) / 256, 256>>>(y);
    router_kernel<<<NTOK / 8, 256>>>(x, gw);
    aux_kernel<<<1, 256>>>(y + (out_size - 1));

    transpose_half_kernel<0><<<dim3(IDIM / 64, HDIM / 64, EEXP), 256>>>(wg, HDIM, IDIM);
    transpose_half_kernel<1><<<dim3(IDIM / 64, HDIM / 64, EEXP), 256>>>(wu, HDIM, IDIM);
    transpose_half_kernel<2><<<dim3(HDIM / 64, IDIM / 64, EEXP), 256>>>(wd, IDIM, HDIM);

    gateup_kernel<<<dim3(IDIM / TN, (NTOK * 2) / TM, EEXP), 256, GU_SMEM>>>();
    down_kernel<<<dim3(HDIM / TN, (NTOK * 2) / TM, EEXP), 256>>>(y);
}